// round 1
// baseline (speedup 1.0000x reference)
#include <cuda_runtime.h>
#include <math.h>

// ---------------- problem constants ----------------
#define BB 2
#define SS 2048
#define EE 1024
#define HH 16
#define HD 64
#define ROWS (BB*SS)           // 4096
#define NHROWS (BB*HH*SS)      // 65536
#define PROJ_ELEMS (ROWS*EE)   // 4194304
#define ATTN_ELEMS (BB*HH*SS*SS) // 134217728

// ---------------- scratch (static device globals; no allocation) ----------------
__device__ float g_proj[3][PROJ_ELEMS];   // projected q,k,v (B*S, E) row-major
__device__ float g_heads[3][PROJ_ELEMS];  // qn, kn, vh in (b2,h,s2,d) row-major
__device__ float g_zc[PROJ_ELEMS];        // combined attention output (B*S, E)
__device__ float g_m[NHROWS];             // softmax row max
__device__ float g_l[NHROWS];             // softmax row denom

// =============================================================================
// 128x128x8 fp32 tiled GEMM with bias:  C[M,N] = A[M,K] @ B[K,N] + bias[N]
// 256 threads, 8x8 microtile per thread.
// =============================================================================
__global__ __launch_bounds__(256) void gemm128(const float* __restrict__ A,
                                               const float* __restrict__ B,
                                               const float* __restrict__ bias,
                                               float* __restrict__ C,
                                               int M, int N, int K)
{
    __shared__ float As[8][132];
    __shared__ float Bs[8][132];
    int tid = threadIdx.x;
    int tx = tid & 15, ty = tid >> 4;
    int m0 = blockIdx.y * 128, n0 = blockIdx.x * 128;

    float acc[8][8];
#pragma unroll
    for (int i = 0; i < 8; i++)
#pragma unroll
        for (int j = 0; j < 8; j++) acc[i][j] = 0.f;

    const float* Ab = A + (size_t)m0 * K;
    const float* Bb = B + n0;

    for (int k0 = 0; k0 < K; k0 += 8) {
#pragma unroll
        for (int l = 0; l < 4; l++) {
            int idx = l * 256 + tid;
            As[idx & 7][idx >> 3]  = Ab[(size_t)(idx >> 3) * K + k0 + (idx & 7)];
            Bs[idx >> 7][idx & 127] = Bb[(size_t)(k0 + (idx >> 7)) * N + (idx & 127)];
        }
        __syncthreads();
#pragma unroll
        for (int kk = 0; kk < 8; kk++) {
            float a[8], b[8];
#pragma unroll
            for (int i = 0; i < 8; i++) a[i] = As[kk][ty * 8 + i];
#pragma unroll
            for (int j = 0; j < 8; j++) b[j] = Bs[kk][tx * 8 + j];
#pragma unroll
            for (int i = 0; i < 8; i++)
#pragma unroll
                for (int j = 0; j < 8; j++)
                    acc[i][j] += a[i] * b[j];
        }
        __syncthreads();
    }

#pragma unroll
    for (int i = 0; i < 8; i++) {
        int m = m0 + ty * 8 + i;
#pragma unroll
        for (int j = 0; j < 8; j++) {
            int n = n0 + tx * 8 + j;
            C[(size_t)m * N + n] = acc[i][j] + bias[n];
        }
    }
}

// =============================================================================
// Gather scrambled heads + (optional) L2-normalize over HD.
// heads[(b2,h,s2,d)] = proj[b = d&1, s = 32*(s2&63)+(d>>1), e = b2*512+h*32+(s2>>6)]
// One warp per head-row; lane handles d=2*lane (b=0) and d=2*lane+1 (b=1).
// =============================================================================
__global__ __launch_bounds__(256) void gather_norm(const float* __restrict__ proj,
                                                   float* __restrict__ outp,
                                                   int do_norm)
{
    int w = blockIdx.x * 8 + (threadIdx.x >> 5);   // head-row id in [0, 65536)
    int lane = threadIdx.x & 31;
    int b2 = w >> 15;
    int h  = (w >> 11) & 15;
    int s2 = w & 2047;
    int e = b2 * 512 + h * 32 + (s2 >> 6);
    int s = ((s2 & 63) << 5) + lane;
    float v0 = proj[(size_t)s * EE + e];            // b = 0, d = 2*lane
    float v1 = proj[(size_t)(SS + s) * EE + e];     // b = 1, d = 2*lane+1
    float rn = 1.0f;
    if (do_norm) {
        float ssq = v0 * v0 + v1 * v1;
#pragma unroll
        for (int o = 16; o; o >>= 1) ssq += __shfl_xor_sync(0xffffffffu, ssq, o);
        rn = rsqrtf(ssq);
    }
    float2 val;
    val.x = v0 * rn;
    val.y = v1 * rn;
    ((float2*)outp)[(size_t)w * 32 + lane] = val;
}

// =============================================================================
// Flash-style causal attention, fp32. Block = (qb, h, b2); BQ = BK = 64.
// 256 threads, 4x4 microtile. Writes combined output directly into zc layout,
// and per-row (m, l) for the optional attn-materialization pass.
// =============================================================================
__global__ __launch_bounds__(256) void attn_kernel(const float* __restrict__ qn,
                                                   const float* __restrict__ kn,
                                                   const float* __restrict__ vh,
                                                   float* __restrict__ zc,
                                                   float* __restrict__ gm,
                                                   float* __restrict__ gl)
{
    extern __shared__ float sm[];
    float (*Qs)[68] = (float(*)[68])sm;
    float (*Ks)[68] = (float(*)[68])(sm + 64 * 68);
    float (*Vs)[68] = (float(*)[68])(sm + 2 * 64 * 68);
    float (*Ps)[68] = (float(*)[68])(sm + 3 * 64 * 68);
    __shared__ float m_s[64], l_s[64], scale_s[64], mnew_s[64];
    __shared__ float red[4][64];

    int tid = threadIdx.x;
    int tx = tid & 15, ty = tid >> 4;
    int qb = blockIdx.x, h = blockIdx.y, b2 = blockIdx.z;
    int base = (b2 * HH + h) * SS;   // head-row base
    int q0 = qb * 64;

#pragma unroll
    for (int l = 0; l < 16; l++) {
        int idx = l * 256 + tid;
        Qs[idx >> 6][idx & 63] = qn[(size_t)(base + q0 + (idx >> 6)) * HD + (idx & 63)];
    }
    if (tid < 64) { m_s[tid] = -1e30f; l_s[tid] = 0.f; }
    float acc[4][4];
#pragma unroll
    for (int i = 0; i < 4; i++)
#pragma unroll
        for (int j = 0; j < 4; j++) acc[i][j] = 0.f;
    __syncthreads();

    for (int kb = 0; kb <= qb; kb++) {
        int k0 = kb * 64;
#pragma unroll
        for (int l = 0; l < 16; l++) {
            int idx = l * 256 + tid;
            Ks[idx >> 6][idx & 63] = kn[(size_t)(base + k0 + (idx >> 6)) * HD + (idx & 63)];
            Vs[idx >> 6][idx & 63] = vh[(size_t)(base + k0 + (idx >> 6)) * HD + (idx & 63)];
        }
        __syncthreads();

        // ---- S = (Q @ K^T) * 1000, causal mask on the diagonal tile ----
        float s[4][4];
#pragma unroll
        for (int i = 0; i < 4; i++)
#pragma unroll
            for (int j = 0; j < 4; j++) s[i][j] = 0.f;
#pragma unroll 16
        for (int k = 0; k < HD; k++) {
            float a[4], b[4];
#pragma unroll
            for (int i = 0; i < 4; i++) a[i] = Qs[ty * 4 + i][k];
#pragma unroll
            for (int j = 0; j < 4; j++) b[j] = Ks[tx * 4 + j][k];
#pragma unroll
            for (int i = 0; i < 4; i++)
#pragma unroll
                for (int j = 0; j < 4; j++)
                    s[i][j] += a[i] * b[j];
        }
#pragma unroll
        for (int i = 0; i < 4; i++) {
            int ig = q0 + ty * 4 + i;
#pragma unroll
            for (int j = 0; j < 4; j++) {
                float v = s[i][j] * 1000.f;
                if (kb == qb && (k0 + tx * 4 + j) > ig) v = -1e30f;
                Ps[ty * 4 + i][tx * 4 + j] = v;
            }
        }
        __syncthreads();

        // ---- online softmax: row max (4 partials per row) ----
        {
            int r = tid & 63, part = tid >> 6;
            float mx = -1e30f;
#pragma unroll
            for (int c = 0; c < 16; c++) mx = fmaxf(mx, Ps[r][part * 16 + c]);
            red[part][r] = mx;
        }
        __syncthreads();
        if (tid < 64) {
            int r = tid;
            float mx = fmaxf(fmaxf(red[0][r], red[1][r]), fmaxf(red[2][r], red[3][r]));
            float mnew = fmaxf(m_s[r], mx);
            mnew_s[r] = mnew;
            scale_s[r] = expf(m_s[r] - mnew);
            m_s[r] = mnew;
        }
        __syncthreads();

        // ---- exp + row sums ----
        {
            int r = tid & 63, part = tid >> 6;
            float mn = mnew_s[r];
            float ssum = 0.f;
#pragma unroll
            for (int c = 0; c < 16; c++) {
                float p = expf(Ps[r][part * 16 + c] - mn);
                Ps[r][part * 16 + c] = p;
                ssum += p;
            }
            red[part][r] = ssum;
        }
        __syncthreads();
        if (tid < 64) {
            int r = tid;
            l_s[r] = l_s[r] * scale_s[r] + red[0][r] + red[1][r] + red[2][r] + red[3][r];
        }

        // ---- rescale accumulator, then O += P @ V ----
#pragma unroll
        for (int i = 0; i < 4; i++) {
            float f = scale_s[ty * 4 + i];
#pragma unroll
            for (int j = 0; j < 4; j++) acc[i][j] *= f;
        }
#pragma unroll 8
        for (int c = 0; c < 64; c++) {
            float p[4], v[4];
#pragma unroll
            for (int i = 0; i < 4; i++) p[i] = Ps[ty * 4 + i][c];
#pragma unroll
            for (int j = 0; j < 4; j++) v[j] = Vs[c][tx * 4 + j];
#pragma unroll
            for (int i = 0; i < 4; i++)
#pragma unroll
                for (int j = 0; j < 4; j++)
                    acc[i][j] += p[i] * v[j];
        }
        __syncthreads();
    }

    // ---- epilogue: normalize, write into combined (B*S, E) layout ----
#pragma unroll
    for (int i = 0; i < 4; i++) {
        int r = ty * 4 + i;
        float invl = 1.f / l_s[r];
#pragma unroll
        for (int j = 0; j < 4; j++) {
            zc[(size_t)(b2 * SS + q0 + r) * EE + h * HD + tx * 4 + j] = acc[i][j] * invl;
        }
    }
    if (tid < 64) {
        int w = base + q0 + tid;
        gm[w] = m_s[tid];
        gl[w] = l_s[tid];
    }
}

// =============================================================================
// Optional second pass: materialize attn (B,H,S,S) using stored (m, l).
// Above-diagonal tiles are written as zeros.
// =============================================================================
__global__ __launch_bounds__(256) void attn_out_kernel(const float* __restrict__ qn,
                                                       const float* __restrict__ kn,
                                                       const float* __restrict__ gm,
                                                       const float* __restrict__ gl,
                                                       float* __restrict__ out)
{
    __shared__ float Qs[64][68];
    __shared__ float Ks[64][68];
    __shared__ float ms[64], li[64];

    int tid = threadIdx.x;
    int tx = tid & 15, ty = tid >> 4;
    int bx = blockIdx.x;
    int qb = bx >> 5, kb = bx & 31;
    int h = blockIdx.y, b2 = blockIdx.z;
    size_t obase = (size_t)(b2 * HH + h) * SS * SS;
    int q0 = qb * 64, k0 = kb * 64;

    if (kb > qb) {
#pragma unroll
        for (int l = 0; l < 16; l++) {
            int idx = l * 256 + tid;
            out[obase + (size_t)(q0 + (idx >> 6)) * SS + k0 + (idx & 63)] = 0.f;
        }
        return;
    }

    int base = (b2 * HH + h) * SS;
#pragma unroll
    for (int l = 0; l < 16; l++) {
        int idx = l * 256 + tid;
        Qs[idx >> 6][idx & 63] = qn[(size_t)(base + q0 + (idx >> 6)) * HD + (idx & 63)];
        Ks[idx >> 6][idx & 63] = kn[(size_t)(base + k0 + (idx >> 6)) * HD + (idx & 63)];
    }
    if (tid < 64) {
        ms[tid] = gm[base + q0 + tid];
        li[tid] = 1.f / gl[base + q0 + tid];
    }
    __syncthreads();

    float s[4][4];
#pragma unroll
    for (int i = 0; i < 4; i++)
#pragma unroll
        for (int j = 0; j < 4; j++) s[i][j] = 0.f;
#pragma unroll 16
    for (int k = 0; k < HD; k++) {
        float a[4], b[4];
#pragma unroll
        for (int i = 0; i < 4; i++) a[i] = Qs[ty * 4 + i][k];
#pragma unroll
        for (int j = 0; j < 4; j++) b[j] = Ks[tx * 4 + j][k];
#pragma unroll
        for (int i = 0; i < 4; i++)
#pragma unroll
            for (int j = 0; j < 4; j++)
                s[i][j] += a[i] * b[j];
    }
#pragma unroll
    for (int i = 0; i < 4; i++) {
        int r = ty * 4 + i;
        int ig = q0 + r;
        float mm = ms[r], lv = li[r];
#pragma unroll
        for (int j = 0; j < 4; j++) {
            int jg = k0 + tx * 4 + j;
            float p = (jg > ig) ? 0.f : expf(s[i][j] * 1000.f - mm) * lv;
            out[obase + (size_t)ig * SS + jg] = p;
        }
    }
}

// =============================================================================
// Host launcher
// =============================================================================
extern "C" void kernel_launch(void* const* d_in, const int* in_sizes, int n_in,
                              void* d_out, int out_size)
{
    const float* q  = (const float*)d_in[0];
    const float* k  = (const float*)d_in[1];
    const float* v  = (const float*)d_in[2];
    // d_in[3] = mask (causal triu) — applied analytically
    const float* Wq = (const float*)d_in[4];
    const float* bq = (const float*)d_in[5];
    const float* Wk = (const float*)d_in[6];
    const float* bk = (const float*)d_in[7];
    const float* Wv = (const float*)d_in[8];
    const float* bv = (const float*)d_in[9];
    const float* Wz = (const float*)d_in[10];
    const float* bz = (const float*)d_in[11];
    float* out = (float*)d_out;

    float *proj, *heads, *zc, *gm, *gl;
    cudaGetSymbolAddress((void**)&proj,  g_proj);
    cudaGetSymbolAddress((void**)&heads, g_heads);
    cudaGetSymbolAddress((void**)&zc,    g_zc);
    cudaGetSymbolAddress((void**)&gm,    g_m);
    cudaGetSymbolAddress((void**)&gl,    g_l);

    dim3 gb(EE / 128, ROWS / 128);

    // 1) projections
    gemm128<<<gb, 256>>>(q, Wq, bq, proj + 0 * (size_t)PROJ_ELEMS, ROWS, EE, EE);
    gemm128<<<gb, 256>>>(k, Wk, bk, proj + 1 * (size_t)PROJ_ELEMS, ROWS, EE, EE);
    gemm128<<<gb, 256>>>(v, Wv, bv, proj + 2 * (size_t)PROJ_ELEMS, ROWS, EE, EE);

    // 2) scrambled head split + normalize
    gather_norm<<<NHROWS / 8, 256>>>(proj + 0 * (size_t)PROJ_ELEMS, heads + 0 * (size_t)PROJ_ELEMS, 1);
    gather_norm<<<NHROWS / 8, 256>>>(proj + 1 * (size_t)PROJ_ELEMS, heads + 1 * (size_t)PROJ_ELEMS, 1);
    gather_norm<<<NHROWS / 8, 256>>>(proj + 2 * (size_t)PROJ_ELEMS, heads + 2 * (size_t)PROJ_ELEMS, 0);

    // 3) flash attention
    size_t smem = 4 * 64 * 68 * sizeof(float);
    cudaFuncSetAttribute(attn_kernel, cudaFuncAttributeMaxDynamicSharedMemorySize, (int)smem);
    attn_kernel<<<dim3(SS / 64, HH, BB), 256, smem>>>(
        heads + 0 * (size_t)PROJ_ELEMS, heads + 1 * (size_t)PROJ_ELEMS,
        heads + 2 * (size_t)PROJ_ELEMS, zc, gm, gl);

    // 4) output projection
    gemm128<<<gb, 256>>>(zc, Wz, bz, out, ROWS, EE, EE);

    // 5) optional: materialize the attn tensor if the harness expects the tuple
    if ((long long)out_size >= (long long)PROJ_ELEMS + (long long)ATTN_ELEMS) {
        attn_out_kernel<<<dim3(32 * 32, HH, BB), 256>>>(
            heads + 0 * (size_t)PROJ_ELEMS, heads + 1 * (size_t)PROJ_ELEMS,
            gm, gl, out + PROJ_ELEMS);
    }
}

// round 2
// speedup vs baseline: 1.0485x; 1.0485x over previous
#include <cuda_runtime.h>
#include <math.h>
#include <stdint.h>

// ---------------- problem constants ----------------
#define BB 2
#define SS 2048
#define EE 1024
#define HH 16
#define HD 64
#define ROWS (BB*SS)           // 4096
#define NHROWS (BB*HH*SS)      // 65536
#define PROJ_ELEMS (ROWS*EE)   // 4194304
#define ATTN_ELEMS (BB*HH*SS*SS) // 134217728

// ---------------- scratch ----------------
__device__ float g_proj[3][PROJ_ELEMS];
__device__ float g_heads[3][PROJ_ELEMS];
__device__ float g_zc[PROJ_ELEMS];
__device__ float g_m[NHROWS];
__device__ float g_l[NHROWS];

// ---------------- tf32 helpers ----------------
__device__ __forceinline__ float2 tf32split(float x) {
    uint32_t hi;
    asm("cvt.rna.tf32.f32 %0, %1;" : "=r"(hi) : "f"(x));
    float h = __uint_as_float(hi);
    uint32_t lo;
    asm("cvt.rna.tf32.f32 %0, %1;" : "=r"(lo) : "f"(x - h));
    return make_float2(h, __uint_as_float(lo));
}

__device__ __forceinline__ void mma8(float c[4],
                                     uint32_t a0, uint32_t a1, uint32_t a2, uint32_t a3,
                                     uint32_t b0, uint32_t b1) {
    asm volatile(
        "mma.sync.aligned.m16n8k8.row.col.f32.tf32.tf32.f32 "
        "{%0,%1,%2,%3}, {%4,%5,%6,%7}, {%8,%9}, {%0,%1,%2,%3};\n"
        : "+f"(c[0]), "+f"(c[1]), "+f"(c[2]), "+f"(c[3])
        : "r"(a0), "r"(a1), "r"(a2), "r"(a3), "r"(b0), "r"(b1));
}

#define F2U(x) __float_as_uint(x)

// 3xTF32: acc += (ahi+alo)*(bhi+blo) - (alo*blo)
__device__ __forceinline__ void mma3x(float c[4],
                                      const float2 a0, const float2 a1,
                                      const float2 a2, const float2 a3,
                                      const float2 b0, const float2 b1) {
    mma8(c, F2U(a0.x), F2U(a1.x), F2U(a2.x), F2U(a3.x), F2U(b0.x), F2U(b1.x));
    mma8(c, F2U(a0.x), F2U(a1.x), F2U(a2.x), F2U(a3.x), F2U(b0.y), F2U(b1.y));
    mma8(c, F2U(a0.y), F2U(a1.y), F2U(a2.y), F2U(a3.y), F2U(b0.x), F2U(b1.x));
}

// =============================================================================
// 128x128x16 tf32x3 GEMM with bias.  256 threads, 8 warps (2m x 4n), each warp
// 64x32 (4 m16-tiles x 4 n8-tiles). hi/lo packed float2 in smem.
// =============================================================================
__global__ __launch_bounds__(256) void gemm_tf32(const float* __restrict__ A,
                                                 const float* __restrict__ B,
                                                 const float* __restrict__ bias,
                                                 float* __restrict__ C,
                                                 int M, int N, int K)
{
    __shared__ float2 A2[16][136];   // [k][m]
    __shared__ float2 B2[16][136];   // [k][n]

    int tid = threadIdx.x;
    int wid = tid >> 5, lane = tid & 31;
    int g = lane >> 2, t = lane & 3;
    int wm = wid >> 2, wn = wid & 3;
    int m0 = blockIdx.y * 128, n0 = blockIdx.x * 128;

    int ma = tid & 127, kqa = tid >> 7;        // A: m row, k quad (0/1, +2)
    int nqb = tid & 31, kbr = tid >> 5;        // B: n quad, k row (0..7, +8)

    float acc[4][4][4];
#pragma unroll
    for (int mt = 0; mt < 4; mt++)
#pragma unroll
        for (int nt = 0; nt < 4; nt++)
#pragma unroll
            for (int c = 0; c < 4; c++) acc[mt][nt][c] = 0.f;

    const int NC = K / 16;
    float4 pa0, pa1, pb0, pb1;
    // prefetch chunk 0
    pa0 = *(const float4*)(A + (size_t)(m0 + ma) * K + kqa * 4);
    pa1 = *(const float4*)(A + (size_t)(m0 + ma) * K + (kqa + 2) * 4);
    pb0 = *(const float4*)(B + (size_t)kbr * N + n0 + nqb * 4);
    pb1 = *(const float4*)(B + (size_t)(kbr + 8) * N + n0 + nqb * 4);

    for (int c = 0; c < NC; c++) {
        // stage regs -> smem (split into tf32 hi/lo)
        {
            float* f;
            f = (float*)&pa0;
#pragma unroll
            for (int j = 0; j < 4; j++) A2[kqa * 4 + j][ma] = tf32split(f[j]);
            f = (float*)&pa1;
#pragma unroll
            for (int j = 0; j < 4; j++) A2[(kqa + 2) * 4 + j][ma] = tf32split(f[j]);
            f = (float*)&pb0;
#pragma unroll
            for (int j = 0; j < 4; j++) B2[kbr][nqb * 4 + j] = tf32split(f[j]);
            f = (float*)&pb1;
#pragma unroll
            for (int j = 0; j < 4; j++) B2[kbr + 8][nqb * 4 + j] = tf32split(f[j]);
        }
        __syncthreads();
        if (c + 1 < NC) {
            int k0 = (c + 1) * 16;
            pa0 = *(const float4*)(A + (size_t)(m0 + ma) * K + k0 + kqa * 4);
            pa1 = *(const float4*)(A + (size_t)(m0 + ma) * K + k0 + (kqa + 2) * 4);
            pb0 = *(const float4*)(B + (size_t)(k0 + kbr) * N + n0 + nqb * 4);
            pb1 = *(const float4*)(B + (size_t)(k0 + kbr + 8) * N + n0 + nqb * 4);
        }
#pragma unroll
        for (int s = 0; s < 2; s++) {
            int kof = s * 8;
            float2 af[4][4];
#pragma unroll
            for (int mt = 0; mt < 4; mt++) {
                int rb = wm * 64 + mt * 16;
                af[mt][0] = A2[kof + t][rb + g];
                af[mt][1] = A2[kof + t][rb + g + 8];
                af[mt][2] = A2[kof + t + 4][rb + g];
                af[mt][3] = A2[kof + t + 4][rb + g + 8];
            }
#pragma unroll
            for (int nt = 0; nt < 4; nt++) {
                int cb = wn * 32 + nt * 8 + g;
                float2 b0 = B2[kof + t][cb];
                float2 b1 = B2[kof + t + 4][cb];
#pragma unroll
                for (int mt = 0; mt < 4; mt++)
                    mma3x(acc[mt][nt], af[mt][0], af[mt][1], af[mt][2], af[mt][3], b0, b1);
            }
        }
        __syncthreads();
    }

    // epilogue
#pragma unroll
    for (int mt = 0; mt < 4; mt++) {
        int r = m0 + wm * 64 + mt * 16 + g;
#pragma unroll
        for (int nt = 0; nt < 4; nt++) {
            int cc = n0 + wn * 32 + nt * 8 + 2 * t;
            float bb0 = bias[cc], bb1 = bias[cc + 1];
            float2 v0 = make_float2(acc[mt][nt][0] + bb0, acc[mt][nt][1] + bb1);
            float2 v1 = make_float2(acc[mt][nt][2] + bb0, acc[mt][nt][3] + bb1);
            *(float2*)&C[(size_t)r * N + cc] = v0;
            *(float2*)&C[(size_t)(r + 8) * N + cc] = v1;
        }
    }
}

// =============================================================================
// Gather scrambled heads + optional L2-normalize (unchanged from R0).
// =============================================================================
__global__ __launch_bounds__(256) void gather_norm(const float* __restrict__ proj,
                                                   float* __restrict__ outp,
                                                   int do_norm)
{
    int w = blockIdx.x * 8 + (threadIdx.x >> 5);
    int lane = threadIdx.x & 31;
    int b2 = w >> 15;
    int h  = (w >> 11) & 15;
    int s2 = w & 2047;
    int e = b2 * 512 + h * 32 + (s2 >> 6);
    int s = ((s2 & 63) << 5) + lane;
    float v0 = proj[(size_t)s * EE + e];
    float v1 = proj[(size_t)(SS + s) * EE + e];
    float rn = 1.0f;
    if (do_norm) {
        float ssq = v0 * v0 + v1 * v1;
#pragma unroll
        for (int o = 16; o; o >>= 1) ssq += __shfl_xor_sync(0xffffffffu, ssq, o);
        rn = rsqrtf(ssq);
    }
    float2 val;
    val.x = v0 * rn;
    val.y = v1 * rn;
    ((float2*)outp)[(size_t)w * 32 + lane] = val;
}

// =============================================================================
// mma-based causal flash attention, tf32x3. BQ=64, BK=32, 128 threads (4 warps,
// warp w owns q-rows 16w..16w+15). Online softmax fully in registers.
// =============================================================================
__global__ __launch_bounds__(128) void attn_mma(const float* __restrict__ qn,
                                                const float* __restrict__ kn,
                                                const float* __restrict__ vh,
                                                float* __restrict__ zc,
                                                float* __restrict__ gm,
                                                float* __restrict__ gl)
{
    extern __shared__ float2 smem2[];
    float2 (*Q2)[72] = (float2(*)[72])smem2;                               // [k][m] 64x72
    float2 (*K2)[40] = (float2(*)[40])(smem2 + 64 * 72);                   // [k][n] 64x40
    float2 (*V2)[72] = (float2(*)[72])(smem2 + 64 * 72 + 64 * 40);         // [kk][d] 32x72
    float2 (*P2)[72] = (float2(*)[72])(smem2 + 64 * 72 + 64 * 40 + 32 * 72); // [kk][m] 32x72

    int tid = threadIdx.x;
    int w = tid >> 5, lane = tid & 31;
    int g = lane >> 2, t = lane & 3;
    int qb = blockIdx.x, h = blockIdx.y, b2 = blockIdx.z;
    int base = (b2 * HH + h) * SS;
    int q0 = qb * 64;
    int r0 = w * 16;

    // ---- load Q (split hi/lo) ----
    {
        int m = tid >> 1, kh = (tid & 1) * 32;
        const float4* src = (const float4*)(qn + (size_t)(base + q0 + m) * HD + kh);
#pragma unroll
        for (int j = 0; j < 8; j++) {
            float4 v = src[j];
            Q2[kh + 4 * j + 0][m] = tf32split(v.x);
            Q2[kh + 4 * j + 1][m] = tf32split(v.y);
            Q2[kh + 4 * j + 2][m] = tf32split(v.z);
            Q2[kh + 4 * j + 3][m] = tf32split(v.w);
        }
    }

    float oacc[8][4];
#pragma unroll
    for (int nt = 0; nt < 8; nt++)
#pragma unroll
        for (int c = 0; c < 4; c++) oacc[nt][c] = 0.f;
    float m0 = -1e30f, m1 = -1e30f, l0 = 0.f, l1 = 0.f;

    int row0 = q0 + r0 + g, row1 = row0 + 8;
    int nkb = 2 * (qb + 1);

    for (int kb = 0; kb < nkb; kb++) {
        int k0 = kb * 32;
        __syncthreads();   // previous iter's K2/V2/P2 reads done
        // ---- load K, V tiles ----
        {
            int n = tid >> 2, kh = (tid & 3) * 16;
            const float4* ks = (const float4*)(kn + (size_t)(base + k0 + n) * HD + kh);
            const float4* vs = (const float4*)(vh + (size_t)(base + k0 + n) * HD + kh);
#pragma unroll
            for (int j = 0; j < 4; j++) {
                float4 kv = ks[j];
                K2[kh + 4 * j + 0][n] = tf32split(kv.x);
                K2[kh + 4 * j + 1][n] = tf32split(kv.y);
                K2[kh + 4 * j + 2][n] = tf32split(kv.z);
                K2[kh + 4 * j + 3][n] = tf32split(kv.w);
                float4 vv = vs[j];
                V2[n][kh + 4 * j + 0] = tf32split(vv.x);
                V2[n][kh + 4 * j + 1] = tf32split(vv.y);
                V2[n][kh + 4 * j + 2] = tf32split(vv.z);
                V2[n][kh + 4 * j + 3] = tf32split(vv.w);
            }
        }
        __syncthreads();

        // per-warp skip of fully-masked tiles
        if (k0 > q0 + r0 + 15) continue;

        // ---- S = Q @ K^T (tf32x3) ----
        float sacc[4][4];
#pragma unroll
        for (int nt = 0; nt < 4; nt++)
#pragma unroll
            for (int c = 0; c < 4; c++) sacc[nt][c] = 0.f;
#pragma unroll
        for (int ks = 0; ks < 8; ks++) {
            int kof = ks * 8;
            float2 a0 = Q2[kof + t][r0 + g];
            float2 a1 = Q2[kof + t][r0 + g + 8];
            float2 a2 = Q2[kof + t + 4][r0 + g];
            float2 a3 = Q2[kof + t + 4][r0 + g + 8];
#pragma unroll
            for (int nt = 0; nt < 4; nt++) {
                float2 b0 = K2[kof + t][nt * 8 + g];
                float2 b1 = K2[kof + t + 4][nt * 8 + g];
                mma3x(sacc[nt], a0, a1, a2, a3, b0, b1);
            }
        }

        // ---- scale + mask + online softmax (register, shfl over 4-lane group) ----
        bool nm = (k0 + 31 > q0 + r0);
        float sv[4][4];
        float mx0 = -1e30f, mx1 = -1e30f;
#pragma unroll
        for (int nt = 0; nt < 4; nt++) {
            int cb = k0 + nt * 8 + 2 * t;
            float s0 = sacc[nt][0] * 1000.f;
            float s1 = sacc[nt][1] * 1000.f;
            float s2 = sacc[nt][2] * 1000.f;
            float s3 = sacc[nt][3] * 1000.f;
            if (nm) {
                if (cb > row0) s0 = -1e30f;
                if (cb + 1 > row0) s1 = -1e30f;
                if (cb > row1) s2 = -1e30f;
                if (cb + 1 > row1) s3 = -1e30f;
            }
            sv[nt][0] = s0; sv[nt][1] = s1; sv[nt][2] = s2; sv[nt][3] = s3;
            mx0 = fmaxf(mx0, fmaxf(s0, s1));
            mx1 = fmaxf(mx1, fmaxf(s2, s3));
        }
        mx0 = fmaxf(mx0, __shfl_xor_sync(0xffffffffu, mx0, 1));
        mx0 = fmaxf(mx0, __shfl_xor_sync(0xffffffffu, mx0, 2));
        mx1 = fmaxf(mx1, __shfl_xor_sync(0xffffffffu, mx1, 1));
        mx1 = fmaxf(mx1, __shfl_xor_sync(0xffffffffu, mx1, 2));
        float mn0 = fmaxf(m0, mx0), mn1 = fmaxf(m1, mx1);
        float sc0 = __expf(m0 - mn0), sc1 = __expf(m1 - mn1);
        m0 = mn0; m1 = mn1;
        float rs0 = 0.f, rs1 = 0.f;
#pragma unroll
        for (int nt = 0; nt < 4; nt++) {
            float p0 = __expf(sv[nt][0] - mn0);
            float p1 = __expf(sv[nt][1] - mn0);
            float p2 = __expf(sv[nt][2] - mn1);
            float p3 = __expf(sv[nt][3] - mn1);
            rs0 += p0 + p1;
            rs1 += p2 + p3;
            int kk = nt * 8 + 2 * t;
            P2[kk][r0 + g] = tf32split(p0);
            P2[kk + 1][r0 + g] = tf32split(p1);
            P2[kk][r0 + g + 8] = tf32split(p2);
            P2[kk + 1][r0 + g + 8] = tf32split(p3);
        }
        rs0 += __shfl_xor_sync(0xffffffffu, rs0, 1);
        rs0 += __shfl_xor_sync(0xffffffffu, rs0, 2);
        rs1 += __shfl_xor_sync(0xffffffffu, rs1, 1);
        rs1 += __shfl_xor_sync(0xffffffffu, rs1, 2);
        l0 = l0 * sc0 + rs0;
        l1 = l1 * sc1 + rs1;
#pragma unroll
        for (int nt = 0; nt < 8; nt++) {
            oacc[nt][0] *= sc0; oacc[nt][1] *= sc0;
            oacc[nt][2] *= sc1; oacc[nt][3] *= sc1;
        }
        __syncwarp();

        // ---- O += P @ V (tf32x3) ----
#pragma unroll
        for (int ks = 0; ks < 4; ks++) {
            int kof = ks * 8;
            float2 a0 = P2[kof + t][r0 + g];
            float2 a1 = P2[kof + t][r0 + g + 8];
            float2 a2 = P2[kof + t + 4][r0 + g];
            float2 a3 = P2[kof + t + 4][r0 + g + 8];
#pragma unroll
            for (int nt = 0; nt < 8; nt++) {
                float2 b0 = V2[kof + t][nt * 8 + g];
                float2 b1 = V2[kof + t + 4][nt * 8 + g];
                mma3x(oacc[nt], a0, a1, a2, a3, b0, b1);
            }
        }
    }

    // ---- epilogue ----
    float inv0 = 1.f / l0, inv1 = 1.f / l1;
    int rg = b2 * SS + q0 + r0 + g;
#pragma unroll
    for (int nt = 0; nt < 8; nt++) {
        int col = h * HD + nt * 8 + 2 * t;
        *(float2*)&zc[(size_t)rg * EE + col] =
            make_float2(oacc[nt][0] * inv0, oacc[nt][1] * inv0);
        *(float2*)&zc[(size_t)(rg + 8) * EE + col] =
            make_float2(oacc[nt][2] * inv1, oacc[nt][3] * inv1);
    }
    if (t == 0) {
        gm[base + q0 + r0 + g] = m0;
        gl[base + q0 + r0 + g] = l0;
        gm[base + q0 + r0 + g + 8] = m1;
        gl[base + q0 + r0 + g + 8] = l1;
    }
}

// =============================================================================
// Optional second pass: materialize attn (B,H,S,S) using stored (m, l).
// =============================================================================
__global__ __launch_bounds__(256) void attn_out_kernel(const float* __restrict__ qn,
                                                       const float* __restrict__ kn,
                                                       const float* __restrict__ gm,
                                                       const float* __restrict__ gl,
                                                       float* __restrict__ out)
{
    __shared__ float Qs[64][68];
    __shared__ float Ks[64][68];
    __shared__ float ms[64], li[64];

    int tid = threadIdx.x;
    int tx = tid & 15, ty = tid >> 4;
    int bx = blockIdx.x;
    int qb = bx >> 5, kb = bx & 31;
    int h = blockIdx.y, b2 = blockIdx.z;
    size_t obase = (size_t)(b2 * HH + h) * SS * SS;
    int q0 = qb * 64, k0 = kb * 64;

    if (kb > qb) {
#pragma unroll
        for (int l = 0; l < 16; l++) {
            int idx = l * 256 + tid;
            out[obase + (size_t)(q0 + (idx >> 6)) * SS + k0 + (idx & 63)] = 0.f;
        }
        return;
    }

    int base = (b2 * HH + h) * SS;
#pragma unroll
    for (int l = 0; l < 16; l++) {
        int idx = l * 256 + tid;
        Qs[idx >> 6][idx & 63] = qn[(size_t)(base + q0 + (idx >> 6)) * HD + (idx & 63)];
        Ks[idx >> 6][idx & 63] = kn[(size_t)(base + k0 + (idx >> 6)) * HD + (idx & 63)];
    }
    if (tid < 64) {
        ms[tid] = gm[base + q0 + tid];
        li[tid] = 1.f / gl[base + q0 + tid];
    }
    __syncthreads();

    float s[4][4];
#pragma unroll
    for (int i = 0; i < 4; i++)
#pragma unroll
        for (int j = 0; j < 4; j++) s[i][j] = 0.f;
#pragma unroll 16
    for (int k = 0; k < HD; k++) {
        float a[4], b[4];
#pragma unroll
        for (int i = 0; i < 4; i++) a[i] = Qs[ty * 4 + i][k];
#pragma unroll
        for (int j = 0; j < 4; j++) b[j] = Ks[tx * 4 + j][k];
#pragma unroll
        for (int i = 0; i < 4; i++)
#pragma unroll
            for (int j = 0; j < 4; j++)
                s[i][j] += a[i] * b[j];
    }
#pragma unroll
    for (int i = 0; i < 4; i++) {
        int r = ty * 4 + i;
        int ig = q0 + r;
        float mm = ms[r], lv = li[r];
#pragma unroll
        for (int j = 0; j < 4; j++) {
            int jg = k0 + tx * 4 + j;
            float p = (jg > ig) ? 0.f : __expf(s[i][j] * 1000.f - mm) * lv;
            out[obase + (size_t)ig * SS + jg] = p;
        }
    }
}

// =============================================================================
// Host launcher
// =============================================================================
extern "C" void kernel_launch(void* const* d_in, const int* in_sizes, int n_in,
                              void* d_out, int out_size)
{
    const float* q  = (const float*)d_in[0];
    const float* k  = (const float*)d_in[1];
    const float* v  = (const float*)d_in[2];
    const float* Wq = (const float*)d_in[4];
    const float* bq = (const float*)d_in[5];
    const float* Wk = (const float*)d_in[6];
    const float* bk = (const float*)d_in[7];
    const float* Wv = (const float*)d_in[8];
    const float* bv = (const float*)d_in[9];
    const float* Wz = (const float*)d_in[10];
    const float* bz = (const float*)d_in[11];
    float* out = (float*)d_out;

    float *proj, *heads, *zc, *gm, *gl;
    cudaGetSymbolAddress((void**)&proj,  g_proj);
    cudaGetSymbolAddress((void**)&heads, g_heads);
    cudaGetSymbolAddress((void**)&zc,    g_zc);
    cudaGetSymbolAddress((void**)&gm,    g_m);
    cudaGetSymbolAddress((void**)&gl,    g_l);

    dim3 gb(EE / 128, ROWS / 128);

    // 1) projections (tf32x3 tensor-core GEMM)
    gemm_tf32<<<gb, 256>>>(q, Wq, bq, proj + 0 * (size_t)PROJ_ELEMS, ROWS, EE, EE);
    gemm_tf32<<<gb, 256>>>(k, Wk, bk, proj + 1 * (size_t)PROJ_ELEMS, ROWS, EE, EE);
    gemm_tf32<<<gb, 256>>>(v, Wv, bv, proj + 2 * (size_t)PROJ_ELEMS, ROWS, EE, EE);

    // 2) scrambled head split + normalize
    gather_norm<<<NHROWS / 8, 256>>>(proj + 0 * (size_t)PROJ_ELEMS, heads + 0 * (size_t)PROJ_ELEMS, 1);
    gather_norm<<<NHROWS / 8, 256>>>(proj + 1 * (size_t)PROJ_ELEMS, heads + 1 * (size_t)PROJ_ELEMS, 1);
    gather_norm<<<NHROWS / 8, 256>>>(proj + 2 * (size_t)PROJ_ELEMS, heads + 2 * (size_t)PROJ_ELEMS, 0);

    // 3) mma flash attention
    size_t smem = (size_t)(64 * 72 + 64 * 40 + 32 * 72 + 32 * 72) * sizeof(float2); // 94208
    cudaFuncSetAttribute(attn_mma, cudaFuncAttributeMaxDynamicSharedMemorySize, (int)smem);
    attn_mma<<<dim3(SS / 64, HH, BB), 128, smem>>>(
        heads + 0 * (size_t)PROJ_ELEMS, heads + 1 * (size_t)PROJ_ELEMS,
        heads + 2 * (size_t)PROJ_ELEMS, zc, gm, gl);

    // 4) output projection
    gemm_tf32<<<gb, 256>>>(zc, Wz, bz, out, ROWS, EE, EE);

    // 5) optional: materialize attn tensor
    if ((long long)out_size >= (long long)PROJ_ELEMS + (long long)ATTN_ELEMS) {
        attn_out_kernel<<<dim3(32 * 32, HH, BB), 256>>>(
            heads + 0 * (size_t)PROJ_ELEMS, heads + 1 * (size_t)PROJ_ELEMS,
            gm, gl, out + PROJ_ELEMS);
    }
}

// round 3
// speedup vs baseline: 1.2734x; 1.2145x over previous
#include <cuda_runtime.h>
#include <math.h>
#include <stdint.h>

// ---------------- problem constants ----------------
#define BB 2
#define SS 2048
#define EE 1024
#define HH 16
#define HD 64
#define ROWS (BB*SS)           // 4096
#define NHROWS (BB*HH*SS)      // 65536
#define PROJ_ELEMS (ROWS*EE)   // 4194304
#define ATTN_ELEMS (BB*HH*SS*SS) // 134217728

// ---------------- scratch ----------------
__device__ float g_proj[3][PROJ_ELEMS];
__device__ float g_heads[3][PROJ_ELEMS];
__device__ float g_zc[PROJ_ELEMS];
__device__ float g_m[NHROWS];
__device__ float g_l[NHROWS];

// ---------------- tf32 helpers ----------------
__device__ __forceinline__ float2 tf32split(float x) {
    uint32_t hi;
    asm("cvt.rna.tf32.f32 %0, %1;" : "=r"(hi) : "f"(x));
    float h = __uint_as_float(hi);
    uint32_t lo;
    asm("cvt.rna.tf32.f32 %0, %1;" : "=r"(lo) : "f"(x - h));
    return make_float2(h, __uint_as_float(lo));
}

__device__ __forceinline__ void mma8(float c[4],
                                     uint32_t a0, uint32_t a1, uint32_t a2, uint32_t a3,
                                     uint32_t b0, uint32_t b1) {
    asm volatile(
        "mma.sync.aligned.m16n8k8.row.col.f32.tf32.tf32.f32 "
        "{%0,%1,%2,%3}, {%4,%5,%6,%7}, {%8,%9}, {%0,%1,%2,%3};\n"
        : "+f"(c[0]), "+f"(c[1]), "+f"(c[2]), "+f"(c[3])
        : "r"(a0), "r"(a1), "r"(a2), "r"(a3), "r"(b0), "r"(b1));
}

#define F2U(x) __float_as_uint(x)

// 3xTF32: hi*hi + hi*lo + lo*hi, fp32 accumulate.
// a0..a3 / b0..b1 are (hi,lo) pairs packed from float4 fragments.
__device__ __forceinline__ void mma3x4(float c[4],
                                       const float4 f0, const float4 f1,
                                       const float4 bf) {
    // a0=(f0.x,f0.y) k=t ; a1=(f1.x,f1.y) ; a2=(f0.z,f0.w) k=t+4 ; a3=(f1.z,f1.w)
    // b0=(bf.x,bf.y) k=t ; b1=(bf.z,bf.w) k=t+4
    mma8(c, F2U(f0.x), F2U(f1.x), F2U(f0.z), F2U(f1.z), F2U(bf.x), F2U(bf.z));
    mma8(c, F2U(f0.x), F2U(f1.x), F2U(f0.z), F2U(f1.z), F2U(bf.y), F2U(bf.w));
    mma8(c, F2U(f0.y), F2U(f1.y), F2U(f0.w), F2U(f1.w), F2U(bf.x), F2U(bf.z));
}

__device__ __forceinline__ float4 packsplit(float v0, float v1) {
    float2 h0 = tf32split(v0);
    float2 h1 = tf32split(v1);
    return make_float4(h0.x, h0.y, h1.x, h1.y);
}

// =============================================================================
// Batched 128x128x16 tf32x3 GEMM with bias. grid.z selects the batch entry.
// Smem packed as float4 {hi(k),lo(k),hi(k+4),lo(k+4)}; pitch 130 float4
// (2080B mod 128 = 32B) -> conflict-free LDS.128 fragment loads.
// =============================================================================
struct GemmBatch {
    const float* A[3];
    const float* B[3];
    const float* bias[3];
    float* C[3];
};

__global__ __launch_bounds__(256) void gemm_tf32_pk(GemmBatch args, int M, int N, int K)
{
    __shared__ float4 Apk[2][4][130];
    __shared__ float4 Bpk[2][4][130];

    const float* A    = args.A[blockIdx.z];
    const float* B    = args.B[blockIdx.z];
    const float* bias = args.bias[blockIdx.z];
    float*       C    = args.C[blockIdx.z];

    int tid = threadIdx.x;
    int wid = tid >> 5, lane = tid & 31;
    int g = lane >> 2, t = lane & 3;
    int wm = wid >> 2, wn = wid & 3;
    int m0 = blockIdx.y * 128, n0 = blockIdx.x * 128;

    int ma = tid & 127, ha = tid >> 7;    // A: row, k-half (0/1)
    int nq = tid & 31,  kr = tid >> 5;    // B: n-quad, k row id
    int bs = kr >> 2,   bt = kr & 3;

    float acc[4][4][4];
#pragma unroll
    for (int mt = 0; mt < 4; mt++)
#pragma unroll
        for (int nt = 0; nt < 4; nt++)
#pragma unroll
            for (int c = 0; c < 4; c++) acc[mt][nt][c] = 0.f;

    const int NC = K / 16;
    float4 pa0, pa1, pb0, pb1;
    {
        const float* pA = A + (size_t)(m0 + ma) * K + ha * 8;
        pa0 = *(const float4*)pA;
        pa1 = *(const float4*)(pA + 4);
        const float* pB = B + (size_t)(bs * 8 + bt) * N + n0 + nq * 4;
        pb0 = *(const float4*)pB;
        pb1 = *(const float4*)(pB + 4 * (size_t)N);
    }

    for (int c = 0; c < NC; c++) {
        // stage (split + pack)
        {
            float va[8] = {pa0.x, pa0.y, pa0.z, pa0.w, pa1.x, pa1.y, pa1.z, pa1.w};
#pragma unroll
            for (int tt = 0; tt < 4; tt++)
                Apk[ha][tt][ma] = packsplit(va[tt], va[tt + 4]);
            float vb0[4] = {pb0.x, pb0.y, pb0.z, pb0.w};
            float vb1[4] = {pb1.x, pb1.y, pb1.z, pb1.w};
#pragma unroll
            for (int j = 0; j < 4; j++)
                Bpk[bs][bt][nq * 4 + j] = packsplit(vb0[j], vb1[j]);
        }
        __syncthreads();
        if (c + 1 < NC) {
            int k0 = (c + 1) * 16;
            const float* pA = A + (size_t)(m0 + ma) * K + k0 + ha * 8;
            pa0 = *(const float4*)pA;
            pa1 = *(const float4*)(pA + 4);
            const float* pB = B + (size_t)(k0 + bs * 8 + bt) * N + n0 + nq * 4;
            pb0 = *(const float4*)pB;
            pb1 = *(const float4*)(pB + 4 * (size_t)N);
        }
#pragma unroll
        for (int s = 0; s < 2; s++) {
            float4 af0[4], af1[4];
#pragma unroll
            for (int mt = 0; mt < 4; mt++) {
                int rb = wm * 64 + mt * 16;
                af0[mt] = Apk[s][t][rb + g];
                af1[mt] = Apk[s][t][rb + g + 8];
            }
#pragma unroll
            for (int nt = 0; nt < 4; nt++) {
                float4 bf = Bpk[s][t][wn * 32 + nt * 8 + g];
#pragma unroll
                for (int mt = 0; mt < 4; mt++)
                    mma3x4(acc[mt][nt], af0[mt], af1[mt], bf);
            }
        }
        __syncthreads();
    }

#pragma unroll
    for (int mt = 0; mt < 4; mt++) {
        int r = m0 + wm * 64 + mt * 16 + g;
#pragma unroll
        for (int nt = 0; nt < 4; nt++) {
            int cc = n0 + wn * 32 + nt * 8 + 2 * t;
            float bb0 = bias[cc], bb1 = bias[cc + 1];
            *(float2*)&C[(size_t)r * N + cc] =
                make_float2(acc[mt][nt][0] + bb0, acc[mt][nt][1] + bb1);
            *(float2*)&C[(size_t)(r + 8) * N + cc] =
                make_float2(acc[mt][nt][2] + bb0, acc[mt][nt][3] + bb1);
        }
    }
}

// =============================================================================
// Fused gather (q,k,v in one launch) + optional L2-normalize.
// =============================================================================
__global__ __launch_bounds__(256) void gather_norm3(const float* __restrict__ proj_base,
                                                    float* __restrict__ heads_base)
{
    int which = blockIdx.y;
    const float* proj = proj_base + (size_t)which * PROJ_ELEMS;
    float* outp = heads_base + (size_t)which * PROJ_ELEMS;
    int do_norm = (which < 2);

    int w = blockIdx.x * 8 + (threadIdx.x >> 5);
    int lane = threadIdx.x & 31;
    int b2 = w >> 15;
    int h  = (w >> 11) & 15;
    int s2 = w & 2047;
    int e = b2 * 512 + h * 32 + (s2 >> 6);
    int s = ((s2 & 63) << 5) + lane;
    float v0 = proj[(size_t)s * EE + e];
    float v1 = proj[(size_t)(SS + s) * EE + e];
    float rn = 1.0f;
    if (do_norm) {
        float ssq = v0 * v0 + v1 * v1;
#pragma unroll
        for (int o = 16; o; o >>= 1) ssq += __shfl_xor_sync(0xffffffffu, ssq, o);
        rn = rsqrtf(ssq);
    }
    ((float2*)outp)[(size_t)w * 32 + lane] = make_float2(v0 * rn, v1 * rn);
}

// =============================================================================
// mma flash attention, tf32x3, packed-float4 smem (conflict-free LDS.128).
// BQ=64, BK=32, 128 threads (4 warps x 16 q-rows).
// =============================================================================
__global__ __launch_bounds__(128) void attn_mma(const float* __restrict__ qn,
                                                const float* __restrict__ kn,
                                                const float* __restrict__ vh,
                                                float* __restrict__ zc,
                                                float* __restrict__ gm,
                                                float* __restrict__ gl)
{
    extern __shared__ float4 sm4[];
    float4 (*Qpk)[4][66] = (float4(*)[4][66])sm4;                          // [8][4][66]
    float4 (*Kpk)[4][34] = (float4(*)[4][34])(sm4 + 8 * 4 * 66);           // [8][4][34]
    float4 (*Vpk)[4][66] = (float4(*)[4][66])(sm4 + 8 * 4 * 66 + 8 * 4 * 34); // [4][4][66]
    float4 (*Ppk)[4][66] = (float4(*)[4][66])(sm4 + 8 * 4 * 66 + 8 * 4 * 34 + 4 * 4 * 66);

    int tid = threadIdx.x;
    int w = tid >> 5, lane = tid & 31;
    int g = lane >> 2, t = lane & 3;
    int qb = blockIdx.x, h = blockIdx.y, b2 = blockIdx.z;
    int base = (b2 * HH + h) * SS;
    int q0 = qb * 64;
    int r0 = w * 16;

    // ---- stage Q (packed split) ----
    {
        int m = tid >> 1, hs = tid & 1;
        const float4* src = (const float4*)(qn + (size_t)(base + q0 + m) * HD + hs * 32);
        float4 v[8];
#pragma unroll
        for (int j = 0; j < 8; j++) v[j] = src[j];
        const float* vf = (const float*)v;
#pragma unroll
        for (int sp = 0; sp < 4; sp++)
#pragma unroll
            for (int tt = 0; tt < 4; tt++)
                Qpk[hs * 4 + sp][tt][m] = packsplit(vf[8 * sp + tt], vf[8 * sp + tt + 4]);
    }

    float oacc[8][4];
#pragma unroll
    for (int nt = 0; nt < 8; nt++)
#pragma unroll
        for (int c = 0; c < 4; c++) oacc[nt][c] = 0.f;
    float m0 = -1e30f, m1 = -1e30f, l0 = 0.f, l1 = 0.f;

    int row0 = q0 + r0 + g, row1 = row0 + 8;
    int nkb = 2 * (qb + 1);

    for (int kb = 0; kb < nkb; kb++) {
        int k0 = kb * 32;
        __syncthreads();
        // ---- stage K tile ----
        {
            int n = tid >> 2, qk = tid & 3;
            const float4* src = (const float4*)(kn + (size_t)(base + k0 + n) * HD + qk * 16);
            float4 v[4];
#pragma unroll
            for (int j = 0; j < 4; j++) v[j] = src[j];
            const float* vf = (const float*)v;
#pragma unroll
            for (int sp = 0; sp < 2; sp++)
#pragma unroll
                for (int tt = 0; tt < 4; tt++)
                    Kpk[qk * 2 + sp][tt][n] = packsplit(vf[8 * sp + tt], vf[8 * sp + tt + 4]);
        }
        // ---- stage V tile ([k'][n] fragment layout) ----
        {
            int n4 = tid & 15;
            int comb = tid >> 4;
            int s = comb >> 1, tb = (comb & 1) * 2;
#pragma unroll
            for (int dt = 0; dt < 2; dt++) {
                int tt = tb + dt;
                const float* p = vh + (size_t)(base + k0 + 8 * s + tt) * HD + n4 * 4;
                float4 x0 = *(const float4*)p;
                float4 x1 = *(const float4*)(p + 4 * HD);
                const float* f0 = (const float*)&x0;
                const float* f1 = (const float*)&x1;
#pragma unroll
                for (int j = 0; j < 4; j++)
                    Vpk[s][tt][n4 * 4 + j] = packsplit(f0[j], f1[j]);
            }
        }
        __syncthreads();

        if (k0 > q0 + r0 + 15) continue;   // fully-masked for this warp

        // ---- S = Q @ K^T ----
        float sacc[4][4];
#pragma unroll
        for (int nt = 0; nt < 4; nt++)
#pragma unroll
            for (int c = 0; c < 4; c++) sacc[nt][c] = 0.f;
#pragma unroll
        for (int ks = 0; ks < 8; ks++) {
            float4 f0 = Qpk[ks][t][r0 + g];
            float4 f1 = Qpk[ks][t][r0 + g + 8];
#pragma unroll
            for (int nt = 0; nt < 4; nt++) {
                float4 bf = Kpk[ks][t][nt * 8 + g];
                mma3x4(sacc[nt], f0, f1, bf);
            }
        }

        // ---- scale + mask + online softmax ----
        bool nm = (k0 + 31 > q0 + r0);
        float sv[4][4];
        float mx0 = -1e30f, mx1 = -1e30f;
#pragma unroll
        for (int nt = 0; nt < 4; nt++) {
            int cb = k0 + nt * 8 + 2 * t;
            float s0 = sacc[nt][0] * 1000.f;
            float s1 = sacc[nt][1] * 1000.f;
            float s2 = sacc[nt][2] * 1000.f;
            float s3 = sacc[nt][3] * 1000.f;
            if (nm) {
                if (cb > row0) s0 = -1e30f;
                if (cb + 1 > row0) s1 = -1e30f;
                if (cb > row1) s2 = -1e30f;
                if (cb + 1 > row1) s3 = -1e30f;
            }
            sv[nt][0] = s0; sv[nt][1] = s1; sv[nt][2] = s2; sv[nt][3] = s3;
            mx0 = fmaxf(mx0, fmaxf(s0, s1));
            mx1 = fmaxf(mx1, fmaxf(s2, s3));
        }
        mx0 = fmaxf(mx0, __shfl_xor_sync(0xffffffffu, mx0, 1));
        mx0 = fmaxf(mx0, __shfl_xor_sync(0xffffffffu, mx0, 2));
        mx1 = fmaxf(mx1, __shfl_xor_sync(0xffffffffu, mx1, 1));
        mx1 = fmaxf(mx1, __shfl_xor_sync(0xffffffffu, mx1, 2));
        float mn0 = fmaxf(m0, mx0), mn1 = fmaxf(m1, mx1);
        float sc0 = __expf(m0 - mn0), sc1 = __expf(m1 - mn1);
        m0 = mn0; m1 = mn1;
        float rs0 = 0.f, rs1 = 0.f;
        int tpA = (2 * t) & 3, tpB = (2 * t + 1) & 3;
        int slot = (t >= 2);
#pragma unroll
        for (int nt = 0; nt < 4; nt++) {
            float p0 = __expf(sv[nt][0] - mn0);
            float p1 = __expf(sv[nt][1] - mn0);
            float p2 = __expf(sv[nt][2] - mn1);
            float p3 = __expf(sv[nt][3] - mn1);
            rs0 += p0 + p1;
            rs1 += p2 + p3;
            ((float2*)&Ppk[nt][tpA][r0 + g])[slot]     = tf32split(p0);
            ((float2*)&Ppk[nt][tpB][r0 + g])[slot]     = tf32split(p1);
            ((float2*)&Ppk[nt][tpA][r0 + g + 8])[slot] = tf32split(p2);
            ((float2*)&Ppk[nt][tpB][r0 + g + 8])[slot] = tf32split(p3);
        }
        rs0 += __shfl_xor_sync(0xffffffffu, rs0, 1);
        rs0 += __shfl_xor_sync(0xffffffffu, rs0, 2);
        rs1 += __shfl_xor_sync(0xffffffffu, rs1, 1);
        rs1 += __shfl_xor_sync(0xffffffffu, rs1, 2);
        l0 = l0 * sc0 + rs0;
        l1 = l1 * sc1 + rs1;
#pragma unroll
        for (int nt = 0; nt < 8; nt++) {
            oacc[nt][0] *= sc0; oacc[nt][1] *= sc0;
            oacc[nt][2] *= sc1; oacc[nt][3] *= sc1;
        }
        __syncwarp();

        // ---- O += P @ V ----
#pragma unroll
        for (int s = 0; s < 4; s++) {
            float4 f0 = Ppk[s][t][r0 + g];
            float4 f1 = Ppk[s][t][r0 + g + 8];
#pragma unroll
            for (int nt = 0; nt < 8; nt++) {
                float4 bf = Vpk[s][t][nt * 8 + g];
                mma3x4(oacc[nt], f0, f1, bf);
            }
        }
    }

    // ---- epilogue ----
    float inv0 = 1.f / l0, inv1 = 1.f / l1;
    int rg = b2 * SS + q0 + r0 + g;
#pragma unroll
    for (int nt = 0; nt < 8; nt++) {
        int col = h * HD + nt * 8 + 2 * t;
        *(float2*)&zc[(size_t)rg * EE + col] =
            make_float2(oacc[nt][0] * inv0, oacc[nt][1] * inv0);
        *(float2*)&zc[(size_t)(rg + 8) * EE + col] =
            make_float2(oacc[nt][2] * inv1, oacc[nt][3] * inv1);
    }
    if (t == 0) {
        gm[base + q0 + r0 + g] = m0;
        gl[base + q0 + r0 + g] = l0;
        gm[base + q0 + r0 + g + 8] = m1;
        gl[base + q0 + r0 + g + 8] = l1;
    }
}

// =============================================================================
// attn materialization: zero-fill of strictly-upper tiles (memory-only).
// =============================================================================
__global__ __launch_bounds__(256) void attn_zero(float* __restrict__ out)
{
    int qb = blockIdx.x >> 5, kb = blockIdx.x & 31;
    if (kb <= qb) return;
    int h = blockIdx.y, b2 = blockIdx.z;
    size_t obase = (size_t)(b2 * HH + h) * SS * SS;
    int q0 = qb * 64, k0 = kb * 64;
    float4 z = make_float4(0.f, 0.f, 0.f, 0.f);
    int tid = threadIdx.x;
#pragma unroll
    for (int l = 0; l < 4; l++) {
        int idx = l * 256 + tid;            // 1024 float4s = 64 rows x 16
        int row = idx >> 4, c4 = idx & 15;
        *(float4*)&out[obase + (size_t)(q0 + row) * SS + k0 + c4 * 4] = z;
    }
}

// =============================================================================
// attn materialization: lower-triangle tiles via tf32x3 mma recompute.
// grid.x indexes the 528 lower tiles triangularly.
// =============================================================================
__global__ __launch_bounds__(128) void attn_out_mma(const float* __restrict__ qn,
                                                    const float* __restrict__ kn,
                                                    const float* __restrict__ gm,
                                                    const float* __restrict__ gl,
                                                    float* __restrict__ out)
{
    extern __shared__ float4 sm4[];
    float4 (*Qpk)[4][66] = (float4(*)[4][66])sm4;              // [8][4][66]
    float4 (*Kpk)[4][66] = (float4(*)[4][66])(sm4 + 8 * 4 * 66);

    int bx = blockIdx.x;
    int qb = (int)floorf((sqrtf(8.f * bx + 1.f) - 1.f) * 0.5f);
    while ((qb + 1) * (qb + 2) / 2 <= bx) qb++;
    while (qb * (qb + 1) / 2 > bx) qb--;
    int kb = bx - qb * (qb + 1) / 2;

    int h = blockIdx.y, b2 = blockIdx.z;
    int base = (b2 * HH + h) * SS;
    size_t obase = (size_t)(b2 * HH + h) * SS * SS;
    int q0 = qb * 64, k0 = kb * 64;

    int tid = threadIdx.x;
    int w = tid >> 5, lane = tid & 31;
    int g = lane >> 2, t = lane & 3;
    int r0 = w * 16;

    // stage Q and K (64x64 each, packed split)
    {
        int m = tid >> 1, hs = tid & 1;
        const float4* qs = (const float4*)(qn + (size_t)(base + q0 + m) * HD + hs * 32);
        const float4* ks = (const float4*)(kn + (size_t)(base + k0 + m) * HD + hs * 32);
        float4 vq[8], vk[8];
#pragma unroll
        for (int j = 0; j < 8; j++) { vq[j] = qs[j]; vk[j] = ks[j]; }
        const float* qf = (const float*)vq;
        const float* kf = (const float*)vk;
#pragma unroll
        for (int sp = 0; sp < 4; sp++)
#pragma unroll
            for (int tt = 0; tt < 4; tt++) {
                Qpk[hs * 4 + sp][tt][m] = packsplit(qf[8 * sp + tt], qf[8 * sp + tt + 4]);
                Kpk[hs * 4 + sp][tt][m] = packsplit(kf[8 * sp + tt], kf[8 * sp + tt + 4]);
            }
    }
    __syncthreads();

    float sacc[8][4];
#pragma unroll
    for (int nt = 0; nt < 8; nt++)
#pragma unroll
        for (int c = 0; c < 4; c++) sacc[nt][c] = 0.f;

#pragma unroll
    for (int ks = 0; ks < 8; ks++) {
        float4 f0 = Qpk[ks][t][r0 + g];
        float4 f1 = Qpk[ks][t][r0 + g + 8];
#pragma unroll
        for (int nt = 0; nt < 8; nt++) {
            float4 bf = Kpk[ks][t][nt * 8 + g];
            mma3x4(sacc[nt], f0, f1, bf);
        }
    }

    int row0 = q0 + r0 + g, row1 = row0 + 8;
    float mm0 = gm[base + row0], il0 = 1.f / gl[base + row0];
    float mm1 = gm[base + row1], il1 = 1.f / gl[base + row1];

#pragma unroll
    for (int nt = 0; nt < 8; nt++) {
        int jg = k0 + nt * 8 + 2 * t;
        float p0 = (jg     > row0) ? 0.f : __expf(sacc[nt][0] * 1000.f - mm0) * il0;
        float p1 = (jg + 1 > row0) ? 0.f : __expf(sacc[nt][1] * 1000.f - mm0) * il0;
        float p2 = (jg     > row1) ? 0.f : __expf(sacc[nt][2] * 1000.f - mm1) * il1;
        float p3 = (jg + 1 > row1) ? 0.f : __expf(sacc[nt][3] * 1000.f - mm1) * il1;
        *(float2*)&out[obase + (size_t)row0 * SS + jg] = make_float2(p0, p1);
        *(float2*)&out[obase + (size_t)row1 * SS + jg] = make_float2(p2, p3);
    }
}

// =============================================================================
// Host launcher
// =============================================================================
extern "C" void kernel_launch(void* const* d_in, const int* in_sizes, int n_in,
                              void* d_out, int out_size)
{
    const float* q  = (const float*)d_in[0];
    const float* k  = (const float*)d_in[1];
    const float* v  = (const float*)d_in[2];
    const float* Wq = (const float*)d_in[4];
    const float* bq = (const float*)d_in[5];
    const float* Wk = (const float*)d_in[6];
    const float* bk = (const float*)d_in[7];
    const float* Wv = (const float*)d_in[8];
    const float* bv = (const float*)d_in[9];
    const float* Wz = (const float*)d_in[10];
    const float* bz = (const float*)d_in[11];
    float* out = (float*)d_out;

    float *proj, *heads, *zc, *gm, *gl;
    cudaGetSymbolAddress((void**)&proj,  g_proj);
    cudaGetSymbolAddress((void**)&heads, g_heads);
    cudaGetSymbolAddress((void**)&zc,    g_zc);
    cudaGetSymbolAddress((void**)&gm,    g_m);
    cudaGetSymbolAddress((void**)&gl,    g_l);

    // 1) three projection GEMMs, one batched launch (768 blocks)
    GemmBatch pb;
    pb.A[0] = q;  pb.A[1] = k;  pb.A[2] = v;
    pb.B[0] = Wq; pb.B[1] = Wk; pb.B[2] = Wv;
    pb.bias[0] = bq; pb.bias[1] = bk; pb.bias[2] = bv;
    pb.C[0] = proj;
    pb.C[1] = proj + (size_t)PROJ_ELEMS;
    pb.C[2] = proj + 2 * (size_t)PROJ_ELEMS;
    gemm_tf32_pk<<<dim3(EE / 128, ROWS / 128, 3), 256>>>(pb, ROWS, EE, EE);

    // 2) fused gather + normalize
    gather_norm3<<<dim3(NHROWS / 8, 3), 256>>>(proj, heads);

    // 3) mma flash attention
    size_t smA = (size_t)(8 * 4 * 66 + 8 * 4 * 34 + 4 * 4 * 66 + 4 * 4 * 66) * sizeof(float4);
    cudaFuncSetAttribute(attn_mma, cudaFuncAttributeMaxDynamicSharedMemorySize, (int)smA);
    attn_mma<<<dim3(SS / 64, HH, BB), 128, smA>>>(
        heads, heads + (size_t)PROJ_ELEMS, heads + 2 * (size_t)PROJ_ELEMS, zc, gm, gl);

    int need_attn = ((long long)out_size >= (long long)PROJ_ELEMS + (long long)ATTN_ELEMS);

    // 4) attn upper-triangle zero-fill
    if (need_attn)
        attn_zero<<<dim3(32 * 32, HH, BB), 256>>>(out + PROJ_ELEMS);

    // 5) attn lower-triangle mma recompute
    if (need_attn) {
        size_t smO = (size_t)(2 * 8 * 4 * 66) * sizeof(float4);
        cudaFuncSetAttribute(attn_out_mma, cudaFuncAttributeMaxDynamicSharedMemorySize, (int)smO);
        attn_out_mma<<<dim3(528, HH, BB), 128, smO>>>(
            heads, heads + (size_t)PROJ_ELEMS, gm, gl, out + PROJ_ELEMS);
    }

    // 6) final output projection (slot 5 for ncu)
    GemmBatch fb;
    fb.A[0] = zc; fb.B[0] = Wz; fb.bias[0] = bz; fb.C[0] = out;
    fb.A[1] = fb.A[2] = zc; fb.B[1] = fb.B[2] = Wz;
    fb.bias[1] = fb.bias[2] = bz; fb.C[1] = fb.C[2] = out;
    gemm_tf32_pk<<<dim3(EE / 128, ROWS / 128, 1), 256>>>(fb, ROWS, EE, EE);
}

// round 4
// speedup vs baseline: 1.3525x; 1.0621x over previous
#include <cuda_runtime.h>
#include <math.h>
#include <stdint.h>

// ---------------- problem constants ----------------
#define BB 2
#define SS 2048
#define EE 1024
#define HH 16
#define HD 64
#define ROWS (BB*SS)           // 4096
#define NHROWS (BB*HH*SS)      // 65536
#define PROJ_ELEMS (ROWS*EE)   // 4194304
#define ATTN_ELEMS (BB*HH*SS*SS) // 134217728

// ---------------- scratch ----------------
__device__ float g_proj[3][PROJ_ELEMS];
__device__ float g_heads[3][PROJ_ELEMS];
__device__ float g_zc[PROJ_ELEMS];
__device__ float g_m[NHROWS];
__device__ float g_l[NHROWS];

// ---------------- tf32 helpers ----------------
__device__ __forceinline__ float2 tf32split(float x) {
    uint32_t hi;
    asm("cvt.rna.tf32.f32 %0, %1;" : "=r"(hi) : "f"(x));
    float h = __uint_as_float(hi);
    uint32_t lo;
    asm("cvt.rna.tf32.f32 %0, %1;" : "=r"(lo) : "f"(x - h));
    return make_float2(h, __uint_as_float(lo));
}

__device__ __forceinline__ float tf32hi(float x) {
    uint32_t hi;
    asm("cvt.rna.tf32.f32 %0, %1;" : "=r"(hi) : "f"(x));
    return __uint_as_float(hi);
}

__device__ __forceinline__ void mma8(float c[4],
                                     uint32_t a0, uint32_t a1, uint32_t a2, uint32_t a3,
                                     uint32_t b0, uint32_t b1) {
    asm volatile(
        "mma.sync.aligned.m16n8k8.row.col.f32.tf32.tf32.f32 "
        "{%0,%1,%2,%3}, {%4,%5,%6,%7}, {%8,%9}, {%0,%1,%2,%3};\n"
        : "+f"(c[0]), "+f"(c[1]), "+f"(c[2]), "+f"(c[3])
        : "r"(a0), "r"(a1), "r"(a2), "r"(a3), "r"(b0), "r"(b1));
}

#define F2U(x) __float_as_uint(x)

// 3xTF32 (hi*hi + hi*lo + lo*hi), fp32 accumulate. f = {hi_a, lo_a, hi_b, lo_b}
__device__ __forceinline__ void mma3x4(float c[4],
                                       const float4 f0, const float4 f1,
                                       const float4 bf) {
    mma8(c, F2U(f0.x), F2U(f1.x), F2U(f0.z), F2U(f1.z), F2U(bf.x), F2U(bf.z));
    mma8(c, F2U(f0.x), F2U(f1.x), F2U(f0.z), F2U(f1.z), F2U(bf.y), F2U(bf.w));
    mma8(c, F2U(f0.y), F2U(f1.y), F2U(f0.w), F2U(f1.w), F2U(bf.x), F2U(bf.z));
}

// 1xTF32 — hi*hi only (for precision-insensitive GEMMs)
__device__ __forceinline__ void mma1x4(float c[4],
                                       const float4 f0, const float4 f1,
                                       const float4 bf) {
    mma8(c, F2U(f0.x), F2U(f1.x), F2U(f0.z), F2U(f1.z), F2U(bf.x), F2U(bf.z));
}

__device__ __forceinline__ float4 packsplit(float v0, float v1) {
    float2 h0 = tf32split(v0);
    float2 h1 = tf32split(v1);
    return make_float4(h0.x, h0.y, h1.x, h1.y);
}

__device__ __forceinline__ float4 packhi(float v0, float v1) {
    return make_float4(tf32hi(v0), 0.f, tf32hi(v1), 0.f);
}

// =============================================================================
// Batched 128x128x16 tf32 GEMM with bias; per-batch precision flag
// (prec=1 -> 3xTF32, prec=0 -> 1xTF32).
// =============================================================================
struct GemmBatch {
    const float* A[3];
    const float* B[3];
    const float* bias[3];
    float* C[3];
    int prec[3];
};

__global__ __launch_bounds__(256) void gemm_tf32_pk(GemmBatch args, int M, int N, int K)
{
    __shared__ float4 Apk[2][4][130];
    __shared__ float4 Bpk[2][4][130];

    const float* A    = args.A[blockIdx.z];
    const float* B    = args.B[blockIdx.z];
    const float* bias = args.bias[blockIdx.z];
    float*       C    = args.C[blockIdx.z];
    const int precise = args.prec[blockIdx.z];

    int tid = threadIdx.x;
    int wid = tid >> 5, lane = tid & 31;
    int g = lane >> 2, t = lane & 3;
    int wm = wid >> 2, wn = wid & 3;
    int m0 = blockIdx.y * 128, n0 = blockIdx.x * 128;

    int ma = tid & 127, ha = tid >> 7;    // A: row, k-half (0/1)
    int nq = tid & 31,  kr = tid >> 5;    // B: n-quad, k row id
    int bs = kr >> 2,   bt = kr & 3;

    float acc[4][4][4];
#pragma unroll
    for (int mt = 0; mt < 4; mt++)
#pragma unroll
        for (int nt = 0; nt < 4; nt++)
#pragma unroll
            for (int c = 0; c < 4; c++) acc[mt][nt][c] = 0.f;

    const int NC = K / 16;
    float4 pa0, pa1, pb0, pb1;
    {
        const float* pA = A + (size_t)(m0 + ma) * K + ha * 8;
        pa0 = *(const float4*)pA;
        pa1 = *(const float4*)(pA + 4);
        const float* pB = B + (size_t)(bs * 8 + bt) * N + n0 + nq * 4;
        pb0 = *(const float4*)pB;
        pb1 = *(const float4*)(pB + 4 * (size_t)N);
    }

    for (int c = 0; c < NC; c++) {
        {
            float va[8] = {pa0.x, pa0.y, pa0.z, pa0.w, pa1.x, pa1.y, pa1.z, pa1.w};
#pragma unroll
            for (int tt = 0; tt < 4; tt++)
                Apk[ha][tt][ma] = packsplit(va[tt], va[tt + 4]);
            float vb0[4] = {pb0.x, pb0.y, pb0.z, pb0.w};
            float vb1[4] = {pb1.x, pb1.y, pb1.z, pb1.w};
#pragma unroll
            for (int j = 0; j < 4; j++)
                Bpk[bs][bt][nq * 4 + j] = packsplit(vb0[j], vb1[j]);
        }
        __syncthreads();
        if (c + 1 < NC) {
            int k0 = (c + 1) * 16;
            const float* pA = A + (size_t)(m0 + ma) * K + k0 + ha * 8;
            pa0 = *(const float4*)pA;
            pa1 = *(const float4*)(pA + 4);
            const float* pB = B + (size_t)(k0 + bs * 8 + bt) * N + n0 + nq * 4;
            pb0 = *(const float4*)pB;
            pb1 = *(const float4*)(pB + 4 * (size_t)N);
        }
#pragma unroll
        for (int s = 0; s < 2; s++) {
            float4 af0[4], af1[4];
#pragma unroll
            for (int mt = 0; mt < 4; mt++) {
                int rb = wm * 64 + mt * 16;
                af0[mt] = Apk[s][t][rb + g];
                af1[mt] = Apk[s][t][rb + g + 8];
            }
            if (precise) {
#pragma unroll
                for (int nt = 0; nt < 4; nt++) {
                    float4 bf = Bpk[s][t][wn * 32 + nt * 8 + g];
#pragma unroll
                    for (int mt = 0; mt < 4; mt++)
                        mma3x4(acc[mt][nt], af0[mt], af1[mt], bf);
                }
            } else {
#pragma unroll
                for (int nt = 0; nt < 4; nt++) {
                    float4 bf = Bpk[s][t][wn * 32 + nt * 8 + g];
#pragma unroll
                    for (int mt = 0; mt < 4; mt++)
                        mma1x4(acc[mt][nt], af0[mt], af1[mt], bf);
                }
            }
        }
        __syncthreads();
    }

#pragma unroll
    for (int mt = 0; mt < 4; mt++) {
        int r = m0 + wm * 64 + mt * 16 + g;
#pragma unroll
        for (int nt = 0; nt < 4; nt++) {
            int cc = n0 + wn * 32 + nt * 8 + 2 * t;
            float bb0 = bias[cc], bb1 = bias[cc + 1];
            *(float2*)&C[(size_t)r * N + cc] =
                make_float2(acc[mt][nt][0] + bb0, acc[mt][nt][1] + bb1);
            *(float2*)&C[(size_t)(r + 8) * N + cc] =
                make_float2(acc[mt][nt][2] + bb0, acc[mt][nt][3] + bb1);
        }
    }
}

// =============================================================================
// Fused gather (q,k,v) + optional L2-normalize.
// =============================================================================
__global__ __launch_bounds__(256) void gather_norm3(const float* __restrict__ proj_base,
                                                    float* __restrict__ heads_base)
{
    int which = blockIdx.y;
    const float* proj = proj_base + (size_t)which * PROJ_ELEMS;
    float* outp = heads_base + (size_t)which * PROJ_ELEMS;
    int do_norm = (which < 2);

    int w = blockIdx.x * 8 + (threadIdx.x >> 5);
    int lane = threadIdx.x & 31;
    int b2 = w >> 15;
    int h  = (w >> 11) & 15;
    int s2 = w & 2047;
    int e = b2 * 512 + h * 32 + (s2 >> 6);
    int s = ((s2 & 63) << 5) + lane;
    float v0 = proj[(size_t)s * EE + e];
    float v1 = proj[(size_t)(SS + s) * EE + e];
    float rn = 1.0f;
    if (do_norm) {
        float ssq = v0 * v0 + v1 * v1;
#pragma unroll
        for (int o = 16; o; o >>= 1) ssq += __shfl_xor_sync(0xffffffffu, ssq, o);
        rn = rsqrtf(ssq);
    }
    ((float2*)outp)[(size_t)w * 32 + lane] = make_float2(v0 * rn, v1 * rn);
}

// =============================================================================
// mma flash attention: QK^T at 3xTF32, P@V at 1xTF32.
// =============================================================================
__global__ __launch_bounds__(128) void attn_mma(const float* __restrict__ qn,
                                                const float* __restrict__ kn,
                                                const float* __restrict__ vh,
                                                float* __restrict__ zc,
                                                float* __restrict__ gm,
                                                float* __restrict__ gl)
{
    extern __shared__ float4 sm4[];
    float4 (*Qpk)[4][66] = (float4(*)[4][66])sm4;                          // [8][4][66]
    float4 (*Kpk)[4][34] = (float4(*)[4][34])(sm4 + 8 * 4 * 66);           // [8][4][34]
    float4 (*Vpk)[4][66] = (float4(*)[4][66])(sm4 + 8 * 4 * 66 + 8 * 4 * 34); // [4][4][66]
    float4 (*Ppk)[4][66] = (float4(*)[4][66])(sm4 + 8 * 4 * 66 + 8 * 4 * 34 + 4 * 4 * 66);

    int tid = threadIdx.x;
    int w = tid >> 5, lane = tid & 31;
    int g = lane >> 2, t = lane & 3;
    int qb = blockIdx.x, h = blockIdx.y, b2 = blockIdx.z;
    int base = (b2 * HH + h) * SS;
    int q0 = qb * 64;
    int r0 = w * 16;

    // ---- stage Q (packed split) ----
    {
        int m = tid >> 1, hs = tid & 1;
        const float4* src = (const float4*)(qn + (size_t)(base + q0 + m) * HD + hs * 32);
        float4 v[8];
#pragma unroll
        for (int j = 0; j < 8; j++) v[j] = src[j];
        const float* vf = (const float*)v;
#pragma unroll
        for (int sp = 0; sp < 4; sp++)
#pragma unroll
            for (int tt = 0; tt < 4; tt++)
                Qpk[hs * 4 + sp][tt][m] = packsplit(vf[8 * sp + tt], vf[8 * sp + tt + 4]);
    }

    float oacc[8][4];
#pragma unroll
    for (int nt = 0; nt < 8; nt++)
#pragma unroll
        for (int c = 0; c < 4; c++) oacc[nt][c] = 0.f;
    float m0 = -1e30f, m1 = -1e30f, l0 = 0.f, l1 = 0.f;

    int row0 = q0 + r0 + g, row1 = row0 + 8;
    int nkb = 2 * (qb + 1);

    for (int kb = 0; kb < nkb; kb++) {
        int k0 = kb * 32;
        __syncthreads();
        // ---- stage K tile (3x needs hi+lo) ----
        {
            int n = tid >> 2, qk = tid & 3;
            const float4* src = (const float4*)(kn + (size_t)(base + k0 + n) * HD + qk * 16);
            float4 v[4];
#pragma unroll
            for (int j = 0; j < 4; j++) v[j] = src[j];
            const float* vf = (const float*)v;
#pragma unroll
            for (int sp = 0; sp < 2; sp++)
#pragma unroll
                for (int tt = 0; tt < 4; tt++)
                    Kpk[qk * 2 + sp][tt][n] = packsplit(vf[8 * sp + tt], vf[8 * sp + tt + 4]);
        }
        // ---- stage V tile (1x: hi only) ----
        {
            int n4 = tid & 15;
            int comb = tid >> 4;
            int s = comb >> 1, tb = (comb & 1) * 2;
#pragma unroll
            for (int dt = 0; dt < 2; dt++) {
                int tt = tb + dt;
                const float* p = vh + (size_t)(base + k0 + 8 * s + tt) * HD + n4 * 4;
                float4 x0 = *(const float4*)p;
                float4 x1 = *(const float4*)(p + 4 * HD);
                const float* f0 = (const float*)&x0;
                const float* f1 = (const float*)&x1;
#pragma unroll
                for (int j = 0; j < 4; j++)
                    Vpk[s][tt][n4 * 4 + j] = packhi(f0[j], f1[j]);
            }
        }
        __syncthreads();

        if (k0 > q0 + r0 + 15) continue;

        // ---- S = Q @ K^T (3xTF32) ----
        float sacc[4][4];
#pragma unroll
        for (int nt = 0; nt < 4; nt++)
#pragma unroll
            for (int c = 0; c < 4; c++) sacc[nt][c] = 0.f;
#pragma unroll
        for (int ks = 0; ks < 8; ks++) {
            float4 f0 = Qpk[ks][t][r0 + g];
            float4 f1 = Qpk[ks][t][r0 + g + 8];
#pragma unroll
            for (int nt = 0; nt < 4; nt++) {
                float4 bf = Kpk[ks][t][nt * 8 + g];
                mma3x4(sacc[nt], f0, f1, bf);
            }
        }

        // ---- scale + mask + online softmax ----
        bool nm = (k0 + 31 > q0 + r0);
        float sv[4][4];
        float mx0 = -1e30f, mx1 = -1e30f;
#pragma unroll
        for (int nt = 0; nt < 4; nt++) {
            int cb = k0 + nt * 8 + 2 * t;
            float s0 = sacc[nt][0] * 1000.f;
            float s1 = sacc[nt][1] * 1000.f;
            float s2 = sacc[nt][2] * 1000.f;
            float s3 = sacc[nt][3] * 1000.f;
            if (nm) {
                if (cb > row0) s0 = -1e30f;
                if (cb + 1 > row0) s1 = -1e30f;
                if (cb > row1) s2 = -1e30f;
                if (cb + 1 > row1) s3 = -1e30f;
            }
            sv[nt][0] = s0; sv[nt][1] = s1; sv[nt][2] = s2; sv[nt][3] = s3;
            mx0 = fmaxf(mx0, fmaxf(s0, s1));
            mx1 = fmaxf(mx1, fmaxf(s2, s3));
        }
        mx0 = fmaxf(mx0, __shfl_xor_sync(0xffffffffu, mx0, 1));
        mx0 = fmaxf(mx0, __shfl_xor_sync(0xffffffffu, mx0, 2));
        mx1 = fmaxf(mx1, __shfl_xor_sync(0xffffffffu, mx1, 1));
        mx1 = fmaxf(mx1, __shfl_xor_sync(0xffffffffu, mx1, 2));
        float mn0 = fmaxf(m0, mx0), mn1 = fmaxf(m1, mx1);
        float sc0 = __expf(m0 - mn0), sc1 = __expf(m1 - mn1);
        m0 = mn0; m1 = mn1;
        float rs0 = 0.f, rs1 = 0.f;
        int tpA = (2 * t) & 3, tpB = (2 * t + 1) & 3;
        int slot = (t >= 2);
#pragma unroll
        for (int nt = 0; nt < 4; nt++) {
            float p0 = __expf(sv[nt][0] - mn0);
            float p1 = __expf(sv[nt][1] - mn0);
            float p2 = __expf(sv[nt][2] - mn1);
            float p3 = __expf(sv[nt][3] - mn1);
            rs0 += p0 + p1;
            rs1 += p2 + p3;
            ((float2*)&Ppk[nt][tpA][r0 + g])[slot]     = make_float2(tf32hi(p0), 0.f);
            ((float2*)&Ppk[nt][tpB][r0 + g])[slot]     = make_float2(tf32hi(p1), 0.f);
            ((float2*)&Ppk[nt][tpA][r0 + g + 8])[slot] = make_float2(tf32hi(p2), 0.f);
            ((float2*)&Ppk[nt][tpB][r0 + g + 8])[slot] = make_float2(tf32hi(p3), 0.f);
        }
        rs0 += __shfl_xor_sync(0xffffffffu, rs0, 1);
        rs0 += __shfl_xor_sync(0xffffffffu, rs0, 2);
        rs1 += __shfl_xor_sync(0xffffffffu, rs1, 1);
        rs1 += __shfl_xor_sync(0xffffffffu, rs1, 2);
        l0 = l0 * sc0 + rs0;
        l1 = l1 * sc1 + rs1;
#pragma unroll
        for (int nt = 0; nt < 8; nt++) {
            oacc[nt][0] *= sc0; oacc[nt][1] *= sc0;
            oacc[nt][2] *= sc1; oacc[nt][3] *= sc1;
        }
        __syncwarp();

        // ---- O += P @ V (1xTF32) ----
#pragma unroll
        for (int s = 0; s < 4; s++) {
            float4 f0 = Ppk[s][t][r0 + g];
            float4 f1 = Ppk[s][t][r0 + g + 8];
#pragma unroll
            for (int nt = 0; nt < 8; nt++) {
                float4 bf = Vpk[s][t][nt * 8 + g];
                mma1x4(oacc[nt], f0, f1, bf);
            }
        }
    }

    // ---- epilogue ----
    float inv0 = 1.f / l0, inv1 = 1.f / l1;
    int rg = b2 * SS + q0 + r0 + g;
#pragma unroll
    for (int nt = 0; nt < 8; nt++) {
        int col = h * HD + nt * 8 + 2 * t;
        *(float2*)&zc[(size_t)rg * EE + col] =
            make_float2(oacc[nt][0] * inv0, oacc[nt][1] * inv0);
        *(float2*)&zc[(size_t)(rg + 8) * EE + col] =
            make_float2(oacc[nt][2] * inv1, oacc[nt][3] * inv1);
    }
    if (t == 0) {
        gm[base + q0 + r0 + g] = m0;
        gl[base + q0 + r0 + g] = l0;
        gm[base + q0 + r0 + g + 8] = m1;
        gl[base + q0 + r0 + g + 8] = l1;
    }
}

// =============================================================================
// attn materialization: one kernel for all 32x32 tiles.
// Upper tiles -> vectorized zero store; lower tiles -> tf32x3 mma recompute.
// =============================================================================
__global__ __launch_bounds__(128) void attn_out_full(const float* __restrict__ qn,
                                                     const float* __restrict__ kn,
                                                     const float* __restrict__ gm,
                                                     const float* __restrict__ gl,
                                                     float* __restrict__ out)
{
    extern __shared__ float4 sm4[];
    float4 (*Qpk)[4][66] = (float4(*)[4][66])sm4;
    float4 (*Kpk)[4][66] = (float4(*)[4][66])(sm4 + 8 * 4 * 66);

    int qb = blockIdx.x >> 5, kb = blockIdx.x & 31;
    int h = blockIdx.y, b2 = blockIdx.z;
    size_t obase = (size_t)(b2 * HH + h) * SS * SS;
    int q0 = qb * 64, k0 = kb * 64;
    int tid = threadIdx.x;

    if (kb > qb) {
        float4 z = make_float4(0.f, 0.f, 0.f, 0.f);
#pragma unroll
        for (int l = 0; l < 8; l++) {
            int idx = l * 128 + tid;          // 1024 float4 = 64 rows x 16
            int row = idx >> 4, c4 = idx & 15;
            *(float4*)&out[obase + (size_t)(q0 + row) * SS + k0 + c4 * 4] = z;
        }
        return;
    }

    int base = (b2 * HH + h) * SS;
    int w = tid >> 5, lane = tid & 31;
    int g = lane >> 2, t = lane & 3;
    int r0 = w * 16;

    {
        int m = tid >> 1, hs = tid & 1;
        const float4* qs = (const float4*)(qn + (size_t)(base + q0 + m) * HD + hs * 32);
        const float4* ks = (const float4*)(kn + (size_t)(base + k0 + m) * HD + hs * 32);
        float4 vq[8], vk[8];
#pragma unroll
        for (int j = 0; j < 8; j++) { vq[j] = qs[j]; vk[j] = ks[j]; }
        const float* qf = (const float*)vq;
        const float* kf = (const float*)vk;
#pragma unroll
        for (int sp = 0; sp < 4; sp++)
#pragma unroll
            for (int tt = 0; tt < 4; tt++) {
                Qpk[hs * 4 + sp][tt][m] = packsplit(qf[8 * sp + tt], qf[8 * sp + tt + 4]);
                Kpk[hs * 4 + sp][tt][m] = packsplit(kf[8 * sp + tt], kf[8 * sp + tt + 4]);
            }
    }
    __syncthreads();

    float sacc[8][4];
#pragma unroll
    for (int nt = 0; nt < 8; nt++)
#pragma unroll
        for (int c = 0; c < 4; c++) sacc[nt][c] = 0.f;

#pragma unroll
    for (int ks = 0; ks < 8; ks++) {
        float4 f0 = Qpk[ks][t][r0 + g];
        float4 f1 = Qpk[ks][t][r0 + g + 8];
#pragma unroll
        for (int nt = 0; nt < 8; nt++) {
            float4 bf = Kpk[ks][t][nt * 8 + g];
            mma3x4(sacc[nt], f0, f1, bf);
        }
    }

    int row0 = q0 + r0 + g, row1 = row0 + 8;
    float mm0 = gm[base + row0], il0 = 1.f / gl[base + row0];
    float mm1 = gm[base + row1], il1 = 1.f / gl[base + row1];

#pragma unroll
    for (int nt = 0; nt < 8; nt++) {
        int jg = k0 + nt * 8 + 2 * t;
        float p0 = (jg     > row0) ? 0.f : __expf(sacc[nt][0] * 1000.f - mm0) * il0;
        float p1 = (jg + 1 > row0) ? 0.f : __expf(sacc[nt][1] * 1000.f - mm0) * il0;
        float p2 = (jg     > row1) ? 0.f : __expf(sacc[nt][2] * 1000.f - mm1) * il1;
        float p3 = (jg + 1 > row1) ? 0.f : __expf(sacc[nt][3] * 1000.f - mm1) * il1;
        *(float2*)&out[obase + (size_t)row0 * SS + jg] = make_float2(p0, p1);
        *(float2*)&out[obase + (size_t)row1 * SS + jg] = make_float2(p2, p3);
    }
}

// =============================================================================
// Host launcher
// =============================================================================
extern "C" void kernel_launch(void* const* d_in, const int* in_sizes, int n_in,
                              void* d_out, int out_size)
{
    const float* q  = (const float*)d_in[0];
    const float* k  = (const float*)d_in[1];
    const float* v  = (const float*)d_in[2];
    const float* Wq = (const float*)d_in[4];
    const float* bq = (const float*)d_in[5];
    const float* Wk = (const float*)d_in[6];
    const float* bk = (const float*)d_in[7];
    const float* Wv = (const float*)d_in[8];
    const float* bv = (const float*)d_in[9];
    const float* Wz = (const float*)d_in[10];
    const float* bz = (const float*)d_in[11];
    float* out = (float*)d_out;

    float *proj, *heads, *zc, *gm, *gl;
    cudaGetSymbolAddress((void**)&proj,  g_proj);
    cudaGetSymbolAddress((void**)&heads, g_heads);
    cudaGetSymbolAddress((void**)&zc,    g_zc);
    cudaGetSymbolAddress((void**)&gm,    g_m);
    cudaGetSymbolAddress((void**)&gl,    g_l);

    // 1) three projection GEMMs (q,k precise; v fast)
    GemmBatch pb;
    pb.A[0] = q;  pb.A[1] = k;  pb.A[2] = v;
    pb.B[0] = Wq; pb.B[1] = Wk; pb.B[2] = Wv;
    pb.bias[0] = bq; pb.bias[1] = bk; pb.bias[2] = bv;
    pb.C[0] = proj;
    pb.C[1] = proj + (size_t)PROJ_ELEMS;
    pb.C[2] = proj + 2 * (size_t)PROJ_ELEMS;
    pb.prec[0] = 1; pb.prec[1] = 1; pb.prec[2] = 0;
    gemm_tf32_pk<<<dim3(EE / 128, ROWS / 128, 3), 256>>>(pb, ROWS, EE, EE);

    // 2) fused gather + normalize
    gather_norm3<<<dim3(NHROWS / 8, 3), 256>>>(proj, heads);

    // 3) mma flash attention
    size_t smA = (size_t)(8 * 4 * 66 + 8 * 4 * 34 + 4 * 4 * 66 + 4 * 4 * 66) * sizeof(float4);
    cudaFuncSetAttribute(attn_mma, cudaFuncAttributeMaxDynamicSharedMemorySize, (int)smA);
    attn_mma<<<dim3(SS / 64, HH, BB), 128, smA>>>(
        heads, heads + (size_t)PROJ_ELEMS, heads + 2 * (size_t)PROJ_ELEMS, zc, gm, gl);

    // 4) final output projection (fast path)
    GemmBatch fb;
    fb.A[0] = zc; fb.B[0] = Wz; fb.bias[0] = bz; fb.C[0] = out; fb.prec[0] = 0;
    fb.A[1] = fb.A[2] = zc; fb.B[1] = fb.B[2] = Wz;
    fb.bias[1] = fb.bias[2] = bz; fb.C[1] = fb.C[2] = out;
    fb.prec[1] = fb.prec[2] = 0;
    gemm_tf32_pk<<<dim3(EE / 128, ROWS / 128, 1), 256>>>(fb, ROWS, EE, EE);

    // 5) attn materialization (zero + recompute in one kernel)
    if ((long long)out_size >= (long long)PROJ_ELEMS + (long long)ATTN_ELEMS) {
        size_t smO = (size_t)(2 * 8 * 4 * 66) * sizeof(float4);
        cudaFuncSetAttribute(attn_out_full, cudaFuncAttributeMaxDynamicSharedMemorySize, (int)smO);
        attn_out_full<<<dim3(32 * 32, HH, BB), 128, smO>>>(
            heads, heads + (size_t)PROJ_ELEMS, gm, gl, out + PROJ_ELEMS);
    }
}

// round 5
// speedup vs baseline: 1.4760x; 1.0913x over previous
#include <cuda_runtime.h>
#include <math.h>
#include <stdint.h>

// ---------------- problem constants ----------------
#define BB 2
#define SS 2048
#define EE 1024
#define HH 16
#define HD 64
#define ROWS (BB*SS)           // 4096
#define NHROWS (BB*HH*SS)      // 65536
#define PROJ_ELEMS (ROWS*EE)   // 4194304
#define ATTN_ELEMS (BB*HH*SS*SS) // 134217728

// ---------------- scratch ----------------
__device__ float g_proj[3][PROJ_ELEMS];
__device__ float g_heads[3][PROJ_ELEMS];
__device__ float g_zc[PROJ_ELEMS];
__device__ float g_m[NHROWS];
__device__ float g_l[NHROWS];

// ---------------- tf32 helpers ----------------
__device__ __forceinline__ float2 tf32split(float x) {
    uint32_t hi;
    asm("cvt.rna.tf32.f32 %0, %1;" : "=r"(hi) : "f"(x));
    float h = __uint_as_float(hi);
    uint32_t lo;
    asm("cvt.rna.tf32.f32 %0, %1;" : "=r"(lo) : "f"(x - h));
    return make_float2(h, __uint_as_float(lo));
}

__device__ __forceinline__ float tf32hi(float x) {
    uint32_t hi;
    asm("cvt.rna.tf32.f32 %0, %1;" : "=r"(hi) : "f"(x));
    return __uint_as_float(hi);
}

__device__ __forceinline__ void mma8(float c[4],
                                     uint32_t a0, uint32_t a1, uint32_t a2, uint32_t a3,
                                     uint32_t b0, uint32_t b1) {
    asm volatile(
        "mma.sync.aligned.m16n8k8.row.col.f32.tf32.tf32.f32 "
        "{%0,%1,%2,%3}, {%4,%5,%6,%7}, {%8,%9}, {%0,%1,%2,%3};\n"
        : "+f"(c[0]), "+f"(c[1]), "+f"(c[2]), "+f"(c[3])
        : "r"(a0), "r"(a1), "r"(a2), "r"(a3), "r"(b0), "r"(b1));
}

#define F2U(x) __float_as_uint(x)

// 3xTF32 (hi*hi + hi*lo + lo*hi), fp32 accumulate. f = {hi_a, lo_a, hi_b, lo_b}
__device__ __forceinline__ void mma3x4(float c[4],
                                       const float4 f0, const float4 f1,
                                       const float4 bf) {
    mma8(c, F2U(f0.x), F2U(f1.x), F2U(f0.z), F2U(f1.z), F2U(bf.x), F2U(bf.z));
    mma8(c, F2U(f0.x), F2U(f1.x), F2U(f0.z), F2U(f1.z), F2U(bf.y), F2U(bf.w));
    mma8(c, F2U(f0.y), F2U(f1.y), F2U(f0.w), F2U(f1.w), F2U(bf.x), F2U(bf.z));
}

// 1xTF32 — hi*hi only
__device__ __forceinline__ void mma1x4(float c[4],
                                       const float4 f0, const float4 f1,
                                       const float4 bf) {
    mma8(c, F2U(f0.x), F2U(f1.x), F2U(f0.z), F2U(f1.z), F2U(bf.x), F2U(bf.z));
}

__device__ __forceinline__ float4 packsplit(float v0, float v1) {
    float2 h0 = tf32split(v0);
    float2 h1 = tf32split(v1);
    return make_float4(h0.x, h0.y, h1.x, h1.y);
}

__device__ __forceinline__ float4 packhi(float v0, float v1) {
    return make_float4(tf32hi(v0), 0.f, tf32hi(v1), 0.f);
}

// =============================================================================
// Batched 128x128x16 tf32 GEMM, double-buffered smem pipeline (1 sync/chunk).
// prec=1 -> 3xTF32, prec=0 -> 1xTF32 (hi-only staging).
// =============================================================================
struct GemmBatch {
    const float* A[3];
    const float* B[3];
    const float* bias[3];
    float* C[3];
    int prec[3];
};

#define APITCH (4*130)
#define BUFSZ  (2*4*130)   // one buffer: [2 khalf][4 t][130]

__global__ __launch_bounds__(256) void gemm_tf32_pk(GemmBatch args, int M, int N, int K)
{
    extern __shared__ float4 smemg[];
    // layout: A buf0, A buf1, B buf0, B buf1
    float4 (*Apk)[2][4][130] = (float4(*)[2][4][130])smemg;
    float4 (*Bpk)[2][4][130] = (float4(*)[2][4][130])(smemg + 2 * BUFSZ);

    const float* A    = args.A[blockIdx.z];
    const float* B    = args.B[blockIdx.z];
    const float* bias = args.bias[blockIdx.z];
    float*       C    = args.C[blockIdx.z];
    const int precise = args.prec[blockIdx.z];

    int tid = threadIdx.x;
    int wid = tid >> 5, lane = tid & 31;
    int g = lane >> 2, t = lane & 3;
    int wm = wid >> 2, wn = wid & 3;
    int m0 = blockIdx.y * 128, n0 = blockIdx.x * 128;

    int ma = tid & 127, ha = tid >> 7;    // A: row, k-half (0/1)
    int nq = tid & 31,  kr = tid >> 5;    // B: n-quad, k row id
    int bs = kr >> 2,   bt = kr & 3;

    float acc[4][4][4];
#pragma unroll
    for (int mt = 0; mt < 4; mt++)
#pragma unroll
        for (int nt = 0; nt < 4; nt++)
#pragma unroll
            for (int c = 0; c < 4; c++) acc[mt][nt][c] = 0.f;

    const int NC = K / 16;
    float4 pa0, pa1, pb0, pb1;
    {
        const float* pA = A + (size_t)(m0 + ma) * K + ha * 8;
        pa0 = *(const float4*)pA;
        pa1 = *(const float4*)(pA + 4);
        const float* pB = B + (size_t)(bs * 8 + bt) * N + n0 + nq * 4;
        pb0 = *(const float4*)pB;
        pb1 = *(const float4*)(pB + 4 * (size_t)N);
    }

    for (int c = 0; c < NC; c++) {
        int buf = c & 1;
        // ---- stage chunk c into buf ----
        {
            float va[8] = {pa0.x, pa0.y, pa0.z, pa0.w, pa1.x, pa1.y, pa1.z, pa1.w};
            float vb0[4] = {pb0.x, pb0.y, pb0.z, pb0.w};
            float vb1[4] = {pb1.x, pb1.y, pb1.z, pb1.w};
            if (precise) {
#pragma unroll
                for (int tt = 0; tt < 4; tt++)
                    Apk[buf][ha][tt][ma] = packsplit(va[tt], va[tt + 4]);
#pragma unroll
                for (int j = 0; j < 4; j++)
                    Bpk[buf][bs][bt][nq * 4 + j] = packsplit(vb0[j], vb1[j]);
            } else {
#pragma unroll
                for (int tt = 0; tt < 4; tt++)
                    Apk[buf][ha][tt][ma] = packhi(va[tt], va[tt + 4]);
#pragma unroll
                for (int j = 0; j < 4; j++)
                    Bpk[buf][bs][bt][nq * 4 + j] = packhi(vb0[j], vb1[j]);
            }
        }
        // ---- prefetch chunk c+1 (overlaps with compute below) ----
        if (c + 1 < NC) {
            int k0 = (c + 1) * 16;
            const float* pA = A + (size_t)(m0 + ma) * K + k0 + ha * 8;
            pa0 = *(const float4*)pA;
            pa1 = *(const float4*)(pA + 4);
            const float* pB = B + (size_t)(k0 + bs * 8 + bt) * N + n0 + nq * 4;
            pb0 = *(const float4*)pB;
            pb1 = *(const float4*)(pB + 4 * (size_t)N);
        }
        __syncthreads();
        // ---- compute chunk c from buf ----
#pragma unroll
        for (int s = 0; s < 2; s++) {
            float4 af0[4], af1[4];
#pragma unroll
            for (int mt = 0; mt < 4; mt++) {
                int rb = wm * 64 + mt * 16;
                af0[mt] = Apk[buf][s][t][rb + g];
                af1[mt] = Apk[buf][s][t][rb + g + 8];
            }
            if (precise) {
#pragma unroll
                for (int nt = 0; nt < 4; nt++) {
                    float4 bf = Bpk[buf][s][t][wn * 32 + nt * 8 + g];
#pragma unroll
                    for (int mt = 0; mt < 4; mt++)
                        mma3x4(acc[mt][nt], af0[mt], af1[mt], bf);
                }
            } else {
#pragma unroll
                for (int nt = 0; nt < 4; nt++) {
                    float4 bf = Bpk[buf][s][t][wn * 32 + nt * 8 + g];
#pragma unroll
                    for (int mt = 0; mt < 4; mt++)
                        mma1x4(acc[mt][nt], af0[mt], af1[mt], bf);
                }
            }
        }
    }

#pragma unroll
    for (int mt = 0; mt < 4; mt++) {
        int r = m0 + wm * 64 + mt * 16 + g;
#pragma unroll
        for (int nt = 0; nt < 4; nt++) {
            int cc = n0 + wn * 32 + nt * 8 + 2 * t;
            float bb0 = bias[cc], bb1 = bias[cc + 1];
            *(float2*)&C[(size_t)r * N + cc] =
                make_float2(acc[mt][nt][0] + bb0, acc[mt][nt][1] + bb1);
            *(float2*)&C[(size_t)(r + 8) * N + cc] =
                make_float2(acc[mt][nt][2] + bb0, acc[mt][nt][3] + bb1);
        }
    }
}

// =============================================================================
// Fused gather (q,k,v) + optional L2-normalize.
// =============================================================================
__global__ __launch_bounds__(256) void gather_norm3(const float* __restrict__ proj_base,
                                                    float* __restrict__ heads_base)
{
    int which = blockIdx.y;
    const float* proj = proj_base + (size_t)which * PROJ_ELEMS;
    float* outp = heads_base + (size_t)which * PROJ_ELEMS;
    int do_norm = (which < 2);

    int w = blockIdx.x * 8 + (threadIdx.x >> 5);
    int lane = threadIdx.x & 31;
    int b2 = w >> 15;
    int h  = (w >> 11) & 15;
    int s2 = w & 2047;
    int e = b2 * 512 + h * 32 + (s2 >> 6);
    int s = ((s2 & 63) << 5) + lane;
    float v0 = proj[(size_t)s * EE + e];
    float v1 = proj[(size_t)(SS + s) * EE + e];
    float rn = 1.0f;
    if (do_norm) {
        float ssq = v0 * v0 + v1 * v1;
#pragma unroll
        for (int o = 16; o; o >>= 1) ssq += __shfl_xor_sync(0xffffffffu, ssq, o);
        rn = rsqrtf(ssq);
    }
    ((float2*)outp)[(size_t)w * 32 + lane] = make_float2(v0 * rn, v1 * rn);
}

// =============================================================================
// mma flash attention: QK^T at 3xTF32, P@V at 1xTF32.
// =============================================================================
__global__ __launch_bounds__(128) void attn_mma(const float* __restrict__ qn,
                                                const float* __restrict__ kn,
                                                const float* __restrict__ vh,
                                                float* __restrict__ zc,
                                                float* __restrict__ gm,
                                                float* __restrict__ gl)
{
    extern __shared__ float4 sm4[];
    float4 (*Qpk)[4][66] = (float4(*)[4][66])sm4;                          // [8][4][66]
    float4 (*Kpk)[4][34] = (float4(*)[4][34])(sm4 + 8 * 4 * 66);           // [8][4][34]
    float4 (*Vpk)[4][66] = (float4(*)[4][66])(sm4 + 8 * 4 * 66 + 8 * 4 * 34); // [4][4][66]
    float4 (*Ppk)[4][66] = (float4(*)[4][66])(sm4 + 8 * 4 * 66 + 8 * 4 * 34 + 4 * 4 * 66);

    int tid = threadIdx.x;
    int w = tid >> 5, lane = tid & 31;
    int g = lane >> 2, t = lane & 3;
    int qb = blockIdx.x, h = blockIdx.y, b2 = blockIdx.z;
    int base = (b2 * HH + h) * SS;
    int q0 = qb * 64;
    int r0 = w * 16;

    // ---- stage Q (packed split) ----
    {
        int m = tid >> 1, hs = tid & 1;
        const float4* src = (const float4*)(qn + (size_t)(base + q0 + m) * HD + hs * 32);
        float4 v[8];
#pragma unroll
        for (int j = 0; j < 8; j++) v[j] = src[j];
        const float* vf = (const float*)v;
#pragma unroll
        for (int sp = 0; sp < 4; sp++)
#pragma unroll
            for (int tt = 0; tt < 4; tt++)
                Qpk[hs * 4 + sp][tt][m] = packsplit(vf[8 * sp + tt], vf[8 * sp + tt + 4]);
    }

    float oacc[8][4];
#pragma unroll
    for (int nt = 0; nt < 8; nt++)
#pragma unroll
        for (int c = 0; c < 4; c++) oacc[nt][c] = 0.f;
    float m0 = -1e30f, m1 = -1e30f, l0 = 0.f, l1 = 0.f;

    int row0 = q0 + r0 + g, row1 = row0 + 8;
    int nkb = 2 * (qb + 1);

    for (int kb = 0; kb < nkb; kb++) {
        int k0 = kb * 32;
        __syncthreads();
        // ---- stage K tile (3x needs hi+lo) ----
        {
            int n = tid >> 2, qk = tid & 3;
            const float4* src = (const float4*)(kn + (size_t)(base + k0 + n) * HD + qk * 16);
            float4 v[4];
#pragma unroll
            for (int j = 0; j < 4; j++) v[j] = src[j];
            const float* vf = (const float*)v;
#pragma unroll
            for (int sp = 0; sp < 2; sp++)
#pragma unroll
                for (int tt = 0; tt < 4; tt++)
                    Kpk[qk * 2 + sp][tt][n] = packsplit(vf[8 * sp + tt], vf[8 * sp + tt + 4]);
        }
        // ---- stage V tile (1x: hi only) ----
        {
            int n4 = tid & 15;
            int comb = tid >> 4;
            int s = comb >> 1, tb = (comb & 1) * 2;
#pragma unroll
            for (int dt = 0; dt < 2; dt++) {
                int tt = tb + dt;
                const float* p = vh + (size_t)(base + k0 + 8 * s + tt) * HD + n4 * 4;
                float4 x0 = *(const float4*)p;
                float4 x1 = *(const float4*)(p + 4 * HD);
                const float* f0 = (const float*)&x0;
                const float* f1 = (const float*)&x1;
#pragma unroll
                for (int j = 0; j < 4; j++)
                    Vpk[s][tt][n4 * 4 + j] = packhi(f0[j], f1[j]);
            }
        }
        __syncthreads();

        if (k0 > q0 + r0 + 15) continue;

        // ---- S = Q @ K^T (3xTF32) ----
        float sacc[4][4];
#pragma unroll
        for (int nt = 0; nt < 4; nt++)
#pragma unroll
            for (int c = 0; c < 4; c++) sacc[nt][c] = 0.f;
#pragma unroll
        for (int ks = 0; ks < 8; ks++) {
            float4 f0 = Qpk[ks][t][r0 + g];
            float4 f1 = Qpk[ks][t][r0 + g + 8];
#pragma unroll
            for (int nt = 0; nt < 4; nt++) {
                float4 bf = Kpk[ks][t][nt * 8 + g];
                mma3x4(sacc[nt], f0, f1, bf);
            }
        }

        // ---- scale + mask + online softmax ----
        bool nm = (k0 + 31 > q0 + r0);
        float sv[4][4];
        float mx0 = -1e30f, mx1 = -1e30f;
#pragma unroll
        for (int nt = 0; nt < 4; nt++) {
            int cb = k0 + nt * 8 + 2 * t;
            float s0 = sacc[nt][0] * 1000.f;
            float s1 = sacc[nt][1] * 1000.f;
            float s2 = sacc[nt][2] * 1000.f;
            float s3 = sacc[nt][3] * 1000.f;
            if (nm) {
                if (cb > row0) s0 = -1e30f;
                if (cb + 1 > row0) s1 = -1e30f;
                if (cb > row1) s2 = -1e30f;
                if (cb + 1 > row1) s3 = -1e30f;
            }
            sv[nt][0] = s0; sv[nt][1] = s1; sv[nt][2] = s2; sv[nt][3] = s3;
            mx0 = fmaxf(mx0, fmaxf(s0, s1));
            mx1 = fmaxf(mx1, fmaxf(s2, s3));
        }
        mx0 = fmaxf(mx0, __shfl_xor_sync(0xffffffffu, mx0, 1));
        mx0 = fmaxf(mx0, __shfl_xor_sync(0xffffffffu, mx0, 2));
        mx1 = fmaxf(mx1, __shfl_xor_sync(0xffffffffu, mx1, 1));
        mx1 = fmaxf(mx1, __shfl_xor_sync(0xffffffffu, mx1, 2));
        float mn0 = fmaxf(m0, mx0), mn1 = fmaxf(m1, mx1);
        float sc0 = __expf(m0 - mn0), sc1 = __expf(m1 - mn1);
        m0 = mn0; m1 = mn1;
        float rs0 = 0.f, rs1 = 0.f;
        int tpA = (2 * t) & 3, tpB = (2 * t + 1) & 3;
        int slot = (t >= 2);
#pragma unroll
        for (int nt = 0; nt < 4; nt++) {
            float p0 = __expf(sv[nt][0] - mn0);
            float p1 = __expf(sv[nt][1] - mn0);
            float p2 = __expf(sv[nt][2] - mn1);
            float p3 = __expf(sv[nt][3] - mn1);
            rs0 += p0 + p1;
            rs1 += p2 + p3;
            ((float2*)&Ppk[nt][tpA][r0 + g])[slot]     = make_float2(tf32hi(p0), 0.f);
            ((float2*)&Ppk[nt][tpB][r0 + g])[slot]     = make_float2(tf32hi(p1), 0.f);
            ((float2*)&Ppk[nt][tpA][r0 + g + 8])[slot] = make_float2(tf32hi(p2), 0.f);
            ((float2*)&Ppk[nt][tpB][r0 + g + 8])[slot] = make_float2(tf32hi(p3), 0.f);
        }
        rs0 += __shfl_xor_sync(0xffffffffu, rs0, 1);
        rs0 += __shfl_xor_sync(0xffffffffu, rs0, 2);
        rs1 += __shfl_xor_sync(0xffffffffu, rs1, 1);
        rs1 += __shfl_xor_sync(0xffffffffu, rs1, 2);
        l0 = l0 * sc0 + rs0;
        l1 = l1 * sc1 + rs1;
#pragma unroll
        for (int nt = 0; nt < 8; nt++) {
            oacc[nt][0] *= sc0; oacc[nt][1] *= sc0;
            oacc[nt][2] *= sc1; oacc[nt][3] *= sc1;
        }
        __syncwarp();

        // ---- O += P @ V (1xTF32) ----
#pragma unroll
        for (int s = 0; s < 4; s++) {
            float4 f0 = Ppk[s][t][r0 + g];
            float4 f1 = Ppk[s][t][r0 + g + 8];
#pragma unroll
            for (int nt = 0; nt < 8; nt++) {
                float4 bf = Vpk[s][t][nt * 8 + g];
                mma1x4(oacc[nt], f0, f1, bf);
            }
        }
    }

    // ---- epilogue ----
    float inv0 = 1.f / l0, inv1 = 1.f / l1;
    int rg = b2 * SS + q0 + r0 + g;
#pragma unroll
    for (int nt = 0; nt < 8; nt++) {
        int col = h * HD + nt * 8 + 2 * t;
        *(float2*)&zc[(size_t)rg * EE + col] =
            make_float2(oacc[nt][0] * inv0, oacc[nt][1] * inv0);
        *(float2*)&zc[(size_t)(rg + 8) * EE + col] =
            make_float2(oacc[nt][2] * inv1, oacc[nt][3] * inv1);
    }
    if (t == 0) {
        gm[base + q0 + r0 + g] = m0;
        gl[base + q0 + r0 + g] = l0;
        gm[base + q0 + r0 + g + 8] = m1;
        gl[base + q0 + r0 + g + 8] = l1;
    }
}

// =============================================================================
// attn materialization: zero upper tiles, tf32x3 mma recompute lower tiles.
// =============================================================================
__global__ __launch_bounds__(128) void attn_out_full(const float* __restrict__ qn,
                                                     const float* __restrict__ kn,
                                                     const float* __restrict__ gm,
                                                     const float* __restrict__ gl,
                                                     float* __restrict__ out)
{
    extern __shared__ float4 sm4[];
    float4 (*Qpk)[4][66] = (float4(*)[4][66])sm4;
    float4 (*Kpk)[4][66] = (float4(*)[4][66])(sm4 + 8 * 4 * 66);

    int qb = blockIdx.x >> 5, kb = blockIdx.x & 31;
    int h = blockIdx.y, b2 = blockIdx.z;
    size_t obase = (size_t)(b2 * HH + h) * SS * SS;
    int q0 = qb * 64, k0 = kb * 64;
    int tid = threadIdx.x;

    if (kb > qb) {
        float4 z = make_float4(0.f, 0.f, 0.f, 0.f);
#pragma unroll
        for (int l = 0; l < 8; l++) {
            int idx = l * 128 + tid;
            int row = idx >> 4, c4 = idx & 15;
            *(float4*)&out[obase + (size_t)(q0 + row) * SS + k0 + c4 * 4] = z;
        }
        return;
    }

    int base = (b2 * HH + h) * SS;
    int w = tid >> 5, lane = tid & 31;
    int g = lane >> 2, t = lane & 3;
    int r0 = w * 16;

    {
        int m = tid >> 1, hs = tid & 1;
        const float4* qs = (const float4*)(qn + (size_t)(base + q0 + m) * HD + hs * 32);
        const float4* ks = (const float4*)(kn + (size_t)(base + k0 + m) * HD + hs * 32);
        float4 vq[8], vk[8];
#pragma unroll
        for (int j = 0; j < 8; j++) { vq[j] = qs[j]; vk[j] = ks[j]; }
        const float* qf = (const float*)vq;
        const float* kf = (const float*)vk;
#pragma unroll
        for (int sp = 0; sp < 4; sp++)
#pragma unroll
            for (int tt = 0; tt < 4; tt++) {
                Qpk[hs * 4 + sp][tt][m] = packsplit(qf[8 * sp + tt], qf[8 * sp + tt + 4]);
                Kpk[hs * 4 + sp][tt][m] = packsplit(kf[8 * sp + tt], kf[8 * sp + tt + 4]);
            }
    }
    __syncthreads();

    float sacc[8][4];
#pragma unroll
    for (int nt = 0; nt < 8; nt++)
#pragma unroll
        for (int c = 0; c < 4; c++) sacc[nt][c] = 0.f;

#pragma unroll
    for (int ks = 0; ks < 8; ks++) {
        float4 f0 = Qpk[ks][t][r0 + g];
        float4 f1 = Qpk[ks][t][r0 + g + 8];
#pragma unroll
        for (int nt = 0; nt < 8; nt++) {
            float4 bf = Kpk[ks][t][nt * 8 + g];
            mma3x4(sacc[nt], f0, f1, bf);
        }
    }

    int row0 = q0 + r0 + g, row1 = row0 + 8;
    float mm0 = gm[base + row0], il0 = 1.f / gl[base + row0];
    float mm1 = gm[base + row1], il1 = 1.f / gl[base + row1];

#pragma unroll
    for (int nt = 0; nt < 8; nt++) {
        int jg = k0 + nt * 8 + 2 * t;
        float p0 = (jg     > row0) ? 0.f : __expf(sacc[nt][0] * 1000.f - mm0) * il0;
        float p1 = (jg + 1 > row0) ? 0.f : __expf(sacc[nt][1] * 1000.f - mm0) * il0;
        float p2 = (jg     > row1) ? 0.f : __expf(sacc[nt][2] * 1000.f - mm1) * il1;
        float p3 = (jg + 1 > row1) ? 0.f : __expf(sacc[nt][3] * 1000.f - mm1) * il1;
        *(float2*)&out[obase + (size_t)row0 * SS + jg] = make_float2(p0, p1);
        *(float2*)&out[obase + (size_t)row1 * SS + jg] = make_float2(p2, p3);
    }
}

// =============================================================================
// Host launcher
// =============================================================================
extern "C" void kernel_launch(void* const* d_in, const int* in_sizes, int n_in,
                              void* d_out, int out_size)
{
    const float* q  = (const float*)d_in[0];
    const float* k  = (const float*)d_in[1];
    const float* v  = (const float*)d_in[2];
    const float* Wq = (const float*)d_in[4];
    const float* bq = (const float*)d_in[5];
    const float* Wk = (const float*)d_in[6];
    const float* bk = (const float*)d_in[7];
    const float* Wv = (const float*)d_in[8];
    const float* bv = (const float*)d_in[9];
    const float* Wz = (const float*)d_in[10];
    const float* bz = (const float*)d_in[11];
    float* out = (float*)d_out;

    float *proj, *heads, *zc, *gm, *gl;
    cudaGetSymbolAddress((void**)&proj,  g_proj);
    cudaGetSymbolAddress((void**)&heads, g_heads);
    cudaGetSymbolAddress((void**)&zc,    g_zc);
    cudaGetSymbolAddress((void**)&gm,    g_m);
    cudaGetSymbolAddress((void**)&gl,    g_l);

    size_t smG = (size_t)(4 * BUFSZ) * sizeof(float4);   // 66,560 B
    cudaFuncSetAttribute(gemm_tf32_pk, cudaFuncAttributeMaxDynamicSharedMemorySize, (int)smG);

    // 1) three projection GEMMs (q,k precise; v fast)
    GemmBatch pb;
    pb.A[0] = q;  pb.A[1] = k;  pb.A[2] = v;
    pb.B[0] = Wq; pb.B[1] = Wk; pb.B[2] = Wv;
    pb.bias[0] = bq; pb.bias[1] = bk; pb.bias[2] = bv;
    pb.C[0] = proj;
    pb.C[1] = proj + (size_t)PROJ_ELEMS;
    pb.C[2] = proj + 2 * (size_t)PROJ_ELEMS;
    pb.prec[0] = 1; pb.prec[1] = 1; pb.prec[2] = 0;
    gemm_tf32_pk<<<dim3(EE / 128, ROWS / 128, 3), 256, smG>>>(pb, ROWS, EE, EE);

    // 2) fused gather + normalize
    gather_norm3<<<dim3(NHROWS / 8, 3), 256>>>(proj, heads);

    // 3) mma flash attention
    size_t smA = (size_t)(8 * 4 * 66 + 8 * 4 * 34 + 4 * 4 * 66 + 4 * 4 * 66) * sizeof(float4);
    cudaFuncSetAttribute(attn_mma, cudaFuncAttributeMaxDynamicSharedMemorySize, (int)smA);
    attn_mma<<<dim3(SS / 64, HH, BB), 128, smA>>>(
        heads, heads + (size_t)PROJ_ELEMS, heads + 2 * (size_t)PROJ_ELEMS, zc, gm, gl);

    // 4) final output projection (fast path) — profiled slot
    GemmBatch fb;
    fb.A[0] = zc; fb.B[0] = Wz; fb.bias[0] = bz; fb.C[0] = out; fb.prec[0] = 0;
    fb.A[1] = fb.A[2] = zc; fb.B[1] = fb.B[2] = Wz;
    fb.bias[1] = fb.bias[2] = bz; fb.C[1] = fb.C[2] = out;
    fb.prec[1] = fb.prec[2] = 0;
    gemm_tf32_pk<<<dim3(EE / 128, ROWS / 128, 1), 256, smG>>>(fb, ROWS, EE, EE);

    // 5) attn materialization
    if ((long long)out_size >= (long long)PROJ_ELEMS + (long long)ATTN_ELEMS) {
        size_t smO = (size_t)(2 * 8 * 4 * 66) * sizeof(float4);
        cudaFuncSetAttribute(attn_out_full, cudaFuncAttributeMaxDynamicSharedMemorySize, (int)smO);
        attn_out_full<<<dim3(32 * 32, HH, BB), 128, smO>>>(
            heads, heads + (size_t)PROJ_ELEMS, gm, gl, out + PROJ_ELEMS);
    }
}

// round 6
// speedup vs baseline: 1.7994x; 1.2191x over previous
#include <cuda_runtime.h>
#include <math.h>
#include <stdint.h>

// ---------------- problem constants ----------------
#define BB 2
#define SS 2048
#define EE 1024
#define HH 16
#define HD 64
#define ROWS (BB*SS)           // 4096
#define NHROWS (BB*HH*SS)      // 65536
#define PROJ_ELEMS (ROWS*EE)   // 4194304
#define ATTN_ELEMS (BB*HH*SS*SS) // 134217728

// ---------------- scratch ----------------
__device__ float g_proj[3][PROJ_ELEMS];
__device__ float g_heads[3][PROJ_ELEMS];
__device__ float g_zc[PROJ_ELEMS];
__device__ float g_m[NHROWS];
__device__ float g_l[NHROWS];

// ---------------- tf32 helpers ----------------
__device__ __forceinline__ float2 tf32split(float x) {
    uint32_t hi;
    asm("cvt.rna.tf32.f32 %0, %1;" : "=r"(hi) : "f"(x));
    float h = __uint_as_float(hi);
    uint32_t lo;
    asm("cvt.rna.tf32.f32 %0, %1;" : "=r"(lo) : "f"(x - h));
    return make_float2(h, __uint_as_float(lo));
}

__device__ __forceinline__ float tf32hi(float x) {
    uint32_t hi;
    asm("cvt.rna.tf32.f32 %0, %1;" : "=r"(hi) : "f"(x));
    return __uint_as_float(hi);
}

__device__ __forceinline__ void mma8(float c[4],
                                     uint32_t a0, uint32_t a1, uint32_t a2, uint32_t a3,
                                     uint32_t b0, uint32_t b1) {
    asm volatile(
        "mma.sync.aligned.m16n8k8.row.col.f32.tf32.tf32.f32 "
        "{%0,%1,%2,%3}, {%4,%5,%6,%7}, {%8,%9}, {%0,%1,%2,%3};\n"
        : "+f"(c[0]), "+f"(c[1]), "+f"(c[2]), "+f"(c[3])
        : "r"(a0), "r"(a1), "r"(a2), "r"(a3), "r"(b0), "r"(b1));
}

#define F2U(x) __float_as_uint(x)

// 3xTF32 (hi*hi + hi*lo + lo*hi), fp32 accumulate. f = {hi_a, lo_a, hi_b, lo_b}
__device__ __forceinline__ void mma3x4(float c[4],
                                       const float4 f0, const float4 f1,
                                       const float4 bf) {
    mma8(c, F2U(f0.x), F2U(f1.x), F2U(f0.z), F2U(f1.z), F2U(bf.x), F2U(bf.z));
    mma8(c, F2U(f0.x), F2U(f1.x), F2U(f0.z), F2U(f1.z), F2U(bf.y), F2U(bf.w));
    mma8(c, F2U(f0.y), F2U(f1.y), F2U(f0.w), F2U(f1.w), F2U(bf.x), F2U(bf.z));
}

// 1xTF32 on float2 hi-only fragments: f = {hi(k=t), hi(k=t+4)}
__device__ __forceinline__ void mma1x2(float c[4],
                                       const float2 f0, const float2 f1,
                                       const float2 bf) {
    mma8(c, F2U(f0.x), F2U(f1.x), F2U(f0.y), F2U(f1.y), F2U(bf.x), F2U(bf.y));
}

// 1xTF32 on float4 fragments (attention P@V path)
__device__ __forceinline__ void mma1x4(float c[4],
                                       const float4 f0, const float4 f1,
                                       const float4 bf) {
    mma8(c, F2U(f0.x), F2U(f1.x), F2U(f0.z), F2U(f1.z), F2U(bf.x), F2U(bf.z));
}

__device__ __forceinline__ float4 packsplit(float v0, float v1) {
    float2 h0 = tf32split(v0);
    float2 h1 = tf32split(v1);
    return make_float4(h0.x, h0.y, h1.x, h1.y);
}

__device__ __forceinline__ float4 packhi(float v0, float v1) {
    return make_float4(tf32hi(v0), 0.f, tf32hi(v1), 0.f);
}

// =============================================================================
// Batched 128x128x16 3xTF32 GEMM (q,k projections), double-buffered.
// =============================================================================
struct GemmBatch {
    const float* A[2];
    const float* B[2];
    const float* bias[2];
    float* C[2];
};

#define BUFSZ  (2*4*130)   // one float4 buffer: [2 khalf][4 t][130]

__global__ __launch_bounds__(256) void gemm_3x(GemmBatch args, int M, int N, int K)
{
    extern __shared__ float4 smemg[];
    float4 (*Apk)[2][4][130] = (float4(*)[2][4][130])smemg;
    float4 (*Bpk)[2][4][130] = (float4(*)[2][4][130])(smemg + 2 * BUFSZ);

    const float* A    = args.A[blockIdx.z];
    const float* B    = args.B[blockIdx.z];
    const float* bias = args.bias[blockIdx.z];
    float*       C    = args.C[blockIdx.z];

    int tid = threadIdx.x;
    int wid = tid >> 5, lane = tid & 31;
    int g = lane >> 2, t = lane & 3;
    int wm = wid >> 2, wn = wid & 3;
    int m0 = blockIdx.y * 128, n0 = blockIdx.x * 128;

    int ma = tid & 127, ha = tid >> 7;
    int nq = tid & 31,  kr = tid >> 5;
    int bs = kr >> 2,   bt = kr & 3;

    float acc[4][4][4];
#pragma unroll
    for (int mt = 0; mt < 4; mt++)
#pragma unroll
        for (int nt = 0; nt < 4; nt++)
#pragma unroll
            for (int c = 0; c < 4; c++) acc[mt][nt][c] = 0.f;

    const int NC = K / 16;
    float4 pa0, pa1, pb0, pb1;
    {
        const float* pA = A + (size_t)(m0 + ma) * K + ha * 8;
        pa0 = *(const float4*)pA;
        pa1 = *(const float4*)(pA + 4);
        const float* pB = B + (size_t)(bs * 8 + bt) * N + n0 + nq * 4;
        pb0 = *(const float4*)pB;
        pb1 = *(const float4*)(pB + 4 * (size_t)N);
    }

    for (int c = 0; c < NC; c++) {
        int buf = c & 1;
        {
            float va[8] = {pa0.x, pa0.y, pa0.z, pa0.w, pa1.x, pa1.y, pa1.z, pa1.w};
            float vb0[4] = {pb0.x, pb0.y, pb0.z, pb0.w};
            float vb1[4] = {pb1.x, pb1.y, pb1.z, pb1.w};
#pragma unroll
            for (int tt = 0; tt < 4; tt++)
                Apk[buf][ha][tt][ma] = packsplit(va[tt], va[tt + 4]);
#pragma unroll
            for (int j = 0; j < 4; j++)
                Bpk[buf][bs][bt][nq * 4 + j] = packsplit(vb0[j], vb1[j]);
        }
        if (c + 1 < NC) {
            int k0 = (c + 1) * 16;
            const float* pA = A + (size_t)(m0 + ma) * K + k0 + ha * 8;
            pa0 = *(const float4*)pA;
            pa1 = *(const float4*)(pA + 4);
            const float* pB = B + (size_t)(k0 + bs * 8 + bt) * N + n0 + nq * 4;
            pb0 = *(const float4*)pB;
            pb1 = *(const float4*)(pB + 4 * (size_t)N);
        }
        __syncthreads();
#pragma unroll
        for (int s = 0; s < 2; s++) {
            float4 af0[4], af1[4];
#pragma unroll
            for (int mt = 0; mt < 4; mt++) {
                int rb = wm * 64 + mt * 16;
                af0[mt] = Apk[buf][s][t][rb + g];
                af1[mt] = Apk[buf][s][t][rb + g + 8];
            }
#pragma unroll
            for (int nt = 0; nt < 4; nt++) {
                float4 bf = Bpk[buf][s][t][wn * 32 + nt * 8 + g];
#pragma unroll
                for (int mt = 0; mt < 4; mt++)
                    mma3x4(acc[mt][nt], af0[mt], af1[mt], bf);
            }
        }
    }

#pragma unroll
    for (int mt = 0; mt < 4; mt++) {
        int r = m0 + wm * 64 + mt * 16 + g;
#pragma unroll
        for (int nt = 0; nt < 4; nt++) {
            int cc = n0 + wn * 32 + nt * 8 + 2 * t;
            float bb0 = bias[cc], bb1 = bias[cc + 1];
            *(float2*)&C[(size_t)r * N + cc] =
                make_float2(acc[mt][nt][0] + bb0, acc[mt][nt][1] + bb1);
            *(float2*)&C[(size_t)(r + 8) * N + cc] =
                make_float2(acc[mt][nt][2] + bb0, acc[mt][nt][3] + bb1);
        }
    }
}

// =============================================================================
// 128x128x16 1xTF32 GEMM, float2 hi-only smem (half the LDS/STS bytes),
// pitch 132 (conflict-free LDS.64), 2 CTAs/SM target.
// =============================================================================
__global__ __launch_bounds__(256, 2) void gemm_1x(const float* __restrict__ A,
                                                  const float* __restrict__ B,
                                                  const float* __restrict__ bias,
                                                  float* __restrict__ C,
                                                  int M, int N, int K)
{
    __shared__ float2 A2[2][2][4][132];
    __shared__ float2 B2[2][2][4][132];

    int tid = threadIdx.x;
    int wid = tid >> 5, lane = tid & 31;
    int g = lane >> 2, t = lane & 3;
    int wm = wid >> 2, wn = wid & 3;
    int m0 = blockIdx.y * 128, n0 = blockIdx.x * 128;

    int ma = tid & 127, ha = tid >> 7;
    int nq = tid & 31,  kr = tid >> 5;
    int bs = kr >> 2,   bt = kr & 3;

    float acc[4][4][4];
#pragma unroll
    for (int mt = 0; mt < 4; mt++)
#pragma unroll
        for (int nt = 0; nt < 4; nt++)
#pragma unroll
            for (int c = 0; c < 4; c++) acc[mt][nt][c] = 0.f;

    const int NC = K / 16;
    float4 pa0, pa1;
    float vb0[4], vb1[4];
    {
        const float* pA = A + (size_t)(m0 + ma) * K + ha * 8;
        pa0 = *(const float4*)pA;
        pa1 = *(const float4*)(pA + 4);
        const float* pB0 = B + (size_t)(bs * 8 + bt) * N + n0 + nq;
        const float* pB1 = pB0 + 4 * (size_t)N;
#pragma unroll
        for (int j = 0; j < 4; j++) { vb0[j] = pB0[j * 32]; vb1[j] = pB1[j * 32]; }
    }

    for (int c = 0; c < NC; c++) {
        int buf = c & 1;
        {
            float va[8] = {pa0.x, pa0.y, pa0.z, pa0.w, pa1.x, pa1.y, pa1.z, pa1.w};
#pragma unroll
            for (int tt = 0; tt < 4; tt++)
                A2[buf][ha][tt][ma] = make_float2(tf32hi(va[tt]), tf32hi(va[tt + 4]));
#pragma unroll
            for (int j = 0; j < 4; j++)
                B2[buf][bs][bt][j * 32 + nq] = make_float2(tf32hi(vb0[j]), tf32hi(vb1[j]));
        }
        if (c + 1 < NC) {
            int k0 = (c + 1) * 16;
            const float* pA = A + (size_t)(m0 + ma) * K + k0 + ha * 8;
            pa0 = *(const float4*)pA;
            pa1 = *(const float4*)(pA + 4);
            const float* pB0 = B + (size_t)(k0 + bs * 8 + bt) * N + n0 + nq;
            const float* pB1 = pB0 + 4 * (size_t)N;
#pragma unroll
            for (int j = 0; j < 4; j++) { vb0[j] = pB0[j * 32]; vb1[j] = pB1[j * 32]; }
        }
        __syncthreads();
#pragma unroll
        for (int s = 0; s < 2; s++) {
            float2 af0[4], af1[4];
#pragma unroll
            for (int mt = 0; mt < 4; mt++) {
                int rb = wm * 64 + mt * 16;
                af0[mt] = A2[buf][s][t][rb + g];
                af1[mt] = A2[buf][s][t][rb + g + 8];
            }
#pragma unroll
            for (int nt = 0; nt < 4; nt++) {
                float2 bf = B2[buf][s][t][wn * 32 + nt * 8 + g];
#pragma unroll
                for (int mt = 0; mt < 4; mt++)
                    mma1x2(acc[mt][nt], af0[mt], af1[mt], bf);
            }
        }
    }

#pragma unroll
    for (int mt = 0; mt < 4; mt++) {
        int r = m0 + wm * 64 + mt * 16 + g;
#pragma unroll
        for (int nt = 0; nt < 4; nt++) {
            int cc = n0 + wn * 32 + nt * 8 + 2 * t;
            float bb0 = bias[cc], bb1 = bias[cc + 1];
            *(float2*)&C[(size_t)r * N + cc] =
                make_float2(acc[mt][nt][0] + bb0, acc[mt][nt][1] + bb1);
            *(float2*)&C[(size_t)(r + 8) * N + cc] =
                make_float2(acc[mt][nt][2] + bb0, acc[mt][nt][3] + bb1);
        }
    }
}

// =============================================================================
// Fused gather (q,k,v) + optional L2-normalize.
// =============================================================================
__global__ __launch_bounds__(256) void gather_norm3(const float* __restrict__ proj_base,
                                                    float* __restrict__ heads_base)
{
    int which = blockIdx.y;
    const float* proj = proj_base + (size_t)which * PROJ_ELEMS;
    float* outp = heads_base + (size_t)which * PROJ_ELEMS;
    int do_norm = (which < 2);

    int w = blockIdx.x * 8 + (threadIdx.x >> 5);
    int lane = threadIdx.x & 31;
    int b2 = w >> 15;
    int h  = (w >> 11) & 15;
    int s2 = w & 2047;
    int e = b2 * 512 + h * 32 + (s2 >> 6);
    int s = ((s2 & 63) << 5) + lane;
    float v0 = proj[(size_t)s * EE + e];
    float v1 = proj[(size_t)(SS + s) * EE + e];
    float rn = 1.0f;
    if (do_norm) {
        float ssq = v0 * v0 + v1 * v1;
#pragma unroll
        for (int o = 16; o; o >>= 1) ssq += __shfl_xor_sync(0xffffffffu, ssq, o);
        rn = rsqrtf(ssq);
    }
    ((float2*)outp)[(size_t)w * 32 + lane] = make_float2(v0 * rn, v1 * rn);
}

// =============================================================================
// mma flash attention: QK^T at 3xTF32, P@V at 1xTF32.
// Streams raw logit tiles into pattn (lower triangle) for the normalize pass.
// =============================================================================
__global__ __launch_bounds__(128) void attn_mma(const float* __restrict__ qn,
                                                const float* __restrict__ kn,
                                                const float* __restrict__ vh,
                                                float* __restrict__ zc,
                                                float* __restrict__ gm,
                                                float* __restrict__ gl,
                                                float* __restrict__ pattn)
{
    extern __shared__ float4 sm4[];
    float4 (*Qpk)[4][66] = (float4(*)[4][66])sm4;                          // [8][4][66]
    float4 (*Kpk)[4][34] = (float4(*)[4][34])(sm4 + 8 * 4 * 66);           // [8][4][34]
    float4 (*Vpk)[4][66] = (float4(*)[4][66])(sm4 + 8 * 4 * 66 + 8 * 4 * 34); // [4][4][66]
    float4 (*Ppk)[4][66] = (float4(*)[4][66])(sm4 + 8 * 4 * 66 + 8 * 4 * 34 + 4 * 4 * 66);

    int tid = threadIdx.x;
    int w = tid >> 5, lane = tid & 31;
    int g = lane >> 2, t = lane & 3;
    int qb = blockIdx.x, h = blockIdx.y, b2 = blockIdx.z;
    int base = (b2 * HH + h) * SS;
    size_t obase = (size_t)(b2 * HH + h) * SS * SS;
    int q0 = qb * 64;
    int r0 = w * 16;

    // ---- stage Q ----
    {
        int m = tid >> 1, hs = tid & 1;
        const float4* src = (const float4*)(qn + (size_t)(base + q0 + m) * HD + hs * 32);
        float4 v[8];
#pragma unroll
        for (int j = 0; j < 8; j++) v[j] = src[j];
        const float* vf = (const float*)v;
#pragma unroll
        for (int sp = 0; sp < 4; sp++)
#pragma unroll
            for (int tt = 0; tt < 4; tt++)
                Qpk[hs * 4 + sp][tt][m] = packsplit(vf[8 * sp + tt], vf[8 * sp + tt + 4]);
    }

    float oacc[8][4];
#pragma unroll
    for (int nt = 0; nt < 8; nt++)
#pragma unroll
        for (int c = 0; c < 4; c++) oacc[nt][c] = 0.f;
    float m0 = -1e30f, m1 = -1e30f, l0 = 0.f, l1 = 0.f;

    int row0 = q0 + r0 + g, row1 = row0 + 8;
    int nkb = 2 * (qb + 1);

    for (int kb = 0; kb < nkb; kb++) {
        int k0 = kb * 32;
        __syncthreads();
        // ---- stage K tile (hi+lo) ----
        {
            int n = tid >> 2, qk = tid & 3;
            const float4* src = (const float4*)(kn + (size_t)(base + k0 + n) * HD + qk * 16);
            float4 v[4];
#pragma unroll
            for (int j = 0; j < 4; j++) v[j] = src[j];
            const float* vf = (const float*)v;
#pragma unroll
            for (int sp = 0; sp < 2; sp++)
#pragma unroll
                for (int tt = 0; tt < 4; tt++)
                    Kpk[qk * 2 + sp][tt][n] = packsplit(vf[8 * sp + tt], vf[8 * sp + tt + 4]);
        }
        // ---- stage V tile (hi only) ----
        {
            int n4 = tid & 15;
            int comb = tid >> 4;
            int s = comb >> 1, tb = (comb & 1) * 2;
#pragma unroll
            for (int dt = 0; dt < 2; dt++) {
                int tt = tb + dt;
                const float* p = vh + (size_t)(base + k0 + 8 * s + tt) * HD + n4 * 4;
                float4 x0 = *(const float4*)p;
                float4 x1 = *(const float4*)(p + 4 * HD);
                const float* f0 = (const float*)&x0;
                const float* f1 = (const float*)&x1;
#pragma unroll
                for (int j = 0; j < 4; j++)
                    Vpk[s][tt][n4 * 4 + j] = packhi(f0[j], f1[j]);
            }
        }
        __syncthreads();

        if (k0 > q0 + r0 + 15) continue;

        // ---- S = Q @ K^T (3xTF32) ----
        float sacc[4][4];
#pragma unroll
        for (int nt = 0; nt < 4; nt++)
#pragma unroll
            for (int c = 0; c < 4; c++) sacc[nt][c] = 0.f;
#pragma unroll
        for (int ks = 0; ks < 8; ks++) {
            float4 f0 = Qpk[ks][t][r0 + g];
            float4 f1 = Qpk[ks][t][r0 + g + 8];
#pragma unroll
            for (int nt = 0; nt < 4; nt++) {
                float4 bf = Kpk[ks][t][nt * 8 + g];
                mma3x4(sacc[nt], f0, f1, bf);
            }
        }

        // ---- scale + mask ----
        bool nm = (k0 + 31 > q0 + r0);
        float sv[4][4];
        float mx0 = -1e30f, mx1 = -1e30f;
#pragma unroll
        for (int nt = 0; nt < 4; nt++) {
            int cb = k0 + nt * 8 + 2 * t;
            float s0 = sacc[nt][0] * 1000.f;
            float s1 = sacc[nt][1] * 1000.f;
            float s2 = sacc[nt][2] * 1000.f;
            float s3 = sacc[nt][3] * 1000.f;
            if (nm) {
                if (cb > row0) s0 = -1e30f;
                if (cb + 1 > row0) s1 = -1e30f;
                if (cb > row1) s2 = -1e30f;
                if (cb + 1 > row1) s3 = -1e30f;
            }
            sv[nt][0] = s0; sv[nt][1] = s1; sv[nt][2] = s2; sv[nt][3] = s3;
            mx0 = fmaxf(mx0, fmaxf(s0, s1));
            mx1 = fmaxf(mx1, fmaxf(s2, s3));
        }

        // ---- stream logits to attn buffer (normalized later) ----
        if (pattn) {
#pragma unroll
            for (int nt = 0; nt < 4; nt++) {
                int jg = k0 + nt * 8 + 2 * t;
                *(float2*)&pattn[obase + (size_t)row0 * SS + jg] = make_float2(sv[nt][0], sv[nt][1]);
                *(float2*)&pattn[obase + (size_t)row1 * SS + jg] = make_float2(sv[nt][2], sv[nt][3]);
            }
        }

        // ---- online softmax ----
        mx0 = fmaxf(mx0, __shfl_xor_sync(0xffffffffu, mx0, 1));
        mx0 = fmaxf(mx0, __shfl_xor_sync(0xffffffffu, mx0, 2));
        mx1 = fmaxf(mx1, __shfl_xor_sync(0xffffffffu, mx1, 1));
        mx1 = fmaxf(mx1, __shfl_xor_sync(0xffffffffu, mx1, 2));
        float mn0 = fmaxf(m0, mx0), mn1 = fmaxf(m1, mx1);
        float sc0 = __expf(m0 - mn0), sc1 = __expf(m1 - mn1);
        m0 = mn0; m1 = mn1;
        float rs0 = 0.f, rs1 = 0.f;
        int tpA = (2 * t) & 3, tpB = (2 * t + 1) & 3;
        int slot = (t >= 2);
#pragma unroll
        for (int nt = 0; nt < 4; nt++) {
            float p0 = __expf(sv[nt][0] - mn0);
            float p1 = __expf(sv[nt][1] - mn0);
            float p2 = __expf(sv[nt][2] - mn1);
            float p3 = __expf(sv[nt][3] - mn1);
            rs0 += p0 + p1;
            rs1 += p2 + p3;
            ((float2*)&Ppk[nt][tpA][r0 + g])[slot]     = make_float2(tf32hi(p0), 0.f);
            ((float2*)&Ppk[nt][tpB][r0 + g])[slot]     = make_float2(tf32hi(p1), 0.f);
            ((float2*)&Ppk[nt][tpA][r0 + g + 8])[slot] = make_float2(tf32hi(p2), 0.f);
            ((float2*)&Ppk[nt][tpB][r0 + g + 8])[slot] = make_float2(tf32hi(p3), 0.f);
        }
        rs0 += __shfl_xor_sync(0xffffffffu, rs0, 1);
        rs0 += __shfl_xor_sync(0xffffffffu, rs0, 2);
        rs1 += __shfl_xor_sync(0xffffffffu, rs1, 1);
        rs1 += __shfl_xor_sync(0xffffffffu, rs1, 2);
        l0 = l0 * sc0 + rs0;
        l1 = l1 * sc1 + rs1;
#pragma unroll
        for (int nt = 0; nt < 8; nt++) {
            oacc[nt][0] *= sc0; oacc[nt][1] *= sc0;
            oacc[nt][2] *= sc1; oacc[nt][3] *= sc1;
        }
        __syncwarp();

        // ---- O += P @ V (1xTF32) ----
#pragma unroll
        for (int s = 0; s < 4; s++) {
            float4 f0 = Ppk[s][t][r0 + g];
            float4 f1 = Ppk[s][t][r0 + g + 8];
#pragma unroll
            for (int nt = 0; nt < 8; nt++) {
                float4 bf = Vpk[s][t][nt * 8 + g];
                mma1x4(oacc[nt], f0, f1, bf);
            }
        }
    }

    // ---- epilogue ----
    float inv0 = 1.f / l0, inv1 = 1.f / l1;
    int rg = b2 * SS + q0 + r0 + g;
#pragma unroll
    for (int nt = 0; nt < 8; nt++) {
        int col = h * HD + nt * 8 + 2 * t;
        *(float2*)&zc[(size_t)rg * EE + col] =
            make_float2(oacc[nt][0] * inv0, oacc[nt][1] * inv0);
        *(float2*)&zc[(size_t)(rg + 8) * EE + col] =
            make_float2(oacc[nt][2] * inv1, oacc[nt][3] * inv1);
    }
    if (t == 0) {
        gm[base + q0 + r0 + g] = m0;
        gl[base + q0 + r0 + g] = l0;
        gm[base + q0 + r0 + g + 8] = m1;
        gl[base + q0 + r0 + g + 8] = l1;
    }
}

// =============================================================================
// attn normalize: in-place exp(logit - m)/l on lower tiles; zero upper tiles.
// =============================================================================
__global__ __launch_bounds__(256) void attn_norm(const float* __restrict__ gm,
                                                 const float* __restrict__ gl,
                                                 float* __restrict__ attn)
{
    int qb = blockIdx.x >> 5, kb = blockIdx.x & 31;
    int h = blockIdx.y, b2 = blockIdx.z;
    size_t obase = (size_t)(b2 * HH + h) * SS * SS;
    int q0 = qb * 64, k0 = kb * 64;
    int tid = threadIdx.x;

    if (kb > qb) {
        float4 z = make_float4(0.f, 0.f, 0.f, 0.f);
#pragma unroll
        for (int l = 0; l < 4; l++) {
            int idx = l * 256 + tid;
            int row = idx >> 4, c4 = idx & 15;
            *(float4*)&attn[obase + (size_t)(q0 + row) * SS + k0 + c4 * 4] = z;
        }
        return;
    }

    __shared__ float ms[64], il[64];
    int base = (b2 * HH + h) * SS;
    if (tid < 64) {
        ms[tid] = gm[base + q0 + tid];
        il[tid] = 1.f / gl[base + q0 + tid];
    }
    __syncthreads();

#pragma unroll
    for (int l = 0; l < 4; l++) {
        int idx = l * 256 + tid;
        int row = idx >> 4, c4 = idx & 15;
        int grow = q0 + row;
        int gcol = k0 + c4 * 4;
        size_t off = obase + (size_t)grow * SS + gcol;
        float4 lg = *(const float4*)&attn[off];
        float mm = ms[row], ss = il[row];
        float4 p;
        p.x = (gcol     > grow) ? 0.f : __expf(lg.x - mm) * ss;
        p.y = (gcol + 1 > grow) ? 0.f : __expf(lg.y - mm) * ss;
        p.z = (gcol + 2 > grow) ? 0.f : __expf(lg.z - mm) * ss;
        p.w = (gcol + 3 > grow) ? 0.f : __expf(lg.w - mm) * ss;
        *(float4*)&attn[off] = p;
    }
}

// =============================================================================
// Host launcher
// =============================================================================
extern "C" void kernel_launch(void* const* d_in, const int* in_sizes, int n_in,
                              void* d_out, int out_size)
{
    const float* q  = (const float*)d_in[0];
    const float* k  = (const float*)d_in[1];
    const float* v  = (const float*)d_in[2];
    const float* Wq = (const float*)d_in[4];
    const float* bq = (const float*)d_in[5];
    const float* Wk = (const float*)d_in[6];
    const float* bk = (const float*)d_in[7];
    const float* Wv = (const float*)d_in[8];
    const float* bv = (const float*)d_in[9];
    const float* Wz = (const float*)d_in[10];
    const float* bz = (const float*)d_in[11];
    float* out = (float*)d_out;

    float *proj, *heads, *zc, *gm, *gl;
    cudaGetSymbolAddress((void**)&proj,  g_proj);
    cudaGetSymbolAddress((void**)&heads, g_heads);
    cudaGetSymbolAddress((void**)&zc,    g_zc);
    cudaGetSymbolAddress((void**)&gm,    g_m);
    cudaGetSymbolAddress((void**)&gl,    g_l);

    int need_attn = ((long long)out_size >= (long long)PROJ_ELEMS + (long long)ATTN_ELEMS);
    float* pattn = need_attn ? (out + PROJ_ELEMS) : (float*)0;

    size_t smG = (size_t)(4 * BUFSZ) * sizeof(float4);
    cudaFuncSetAttribute(gemm_3x, cudaFuncAttributeMaxDynamicSharedMemorySize, (int)smG);

    // 1) q,k projections at 3xTF32 (batched)
    GemmBatch pb;
    pb.A[0] = q;  pb.A[1] = k;
    pb.B[0] = Wq; pb.B[1] = Wk;
    pb.bias[0] = bq; pb.bias[1] = bk;
    pb.C[0] = proj;
    pb.C[1] = proj + (size_t)PROJ_ELEMS;
    gemm_3x<<<dim3(EE / 128, ROWS / 128, 2), 256, smG>>>(pb, ROWS, EE, EE);

    // 2) v projection at 1xTF32
    gemm_1x<<<dim3(EE / 128, ROWS / 128), 256>>>(v, Wv, bv,
        proj + 2 * (size_t)PROJ_ELEMS, ROWS, EE, EE);

    // 3) fused gather + normalize
    gather_norm3<<<dim3(NHROWS / 8, 3), 256>>>(proj, heads);

    // 4) mma flash attention (streams logits to pattn)
    size_t smA = (size_t)(8 * 4 * 66 + 8 * 4 * 34 + 4 * 4 * 66 + 4 * 4 * 66) * sizeof(float4);
    cudaFuncSetAttribute(attn_mma, cudaFuncAttributeMaxDynamicSharedMemorySize, (int)smA);
    attn_mma<<<dim3(SS / 64, HH, BB), 128, smA>>>(
        heads, heads + (size_t)PROJ_ELEMS, heads + 2 * (size_t)PROJ_ELEMS,
        zc, gm, gl, pattn);

    // 5) attn normalize (in place) + upper zero
    if (need_attn)
        attn_norm<<<dim3(32 * 32, HH, BB), 256>>>(gm, gl, pattn);

    // 6) final output projection at 1xTF32 — profiled slot
    gemm_1x<<<dim3(EE / 128, ROWS / 128), 256>>>(zc, Wz, bz, out, ROWS, EE, EE);
}

// round 7
// speedup vs baseline: 2.0278x; 1.1270x over previous
#include <cuda_runtime.h>
#include <math.h>
#include <stdint.h>

// ---------------- problem constants ----------------
#define BB 2
#define SS 2048
#define EE 1024
#define HH 16
#define HD 64
#define ROWS (BB*SS)           // 4096
#define NHROWS (BB*HH*SS)      // 65536
#define PROJ_ELEMS (ROWS*EE)   // 4194304
#define ATTN_ELEMS (BB*HH*SS*SS) // 134217728

// ---------------- scratch ----------------
__device__ float g_proj[3][PROJ_ELEMS];
__device__ float g_heads[3][PROJ_ELEMS];
__device__ float g_zc[PROJ_ELEMS];
__device__ float g_m[NHROWS];
__device__ float g_l[NHROWS];

// ---------------- tf32 helpers ----------------
__device__ __forceinline__ float2 tf32split(float x) {
    uint32_t hi;
    asm("cvt.rna.tf32.f32 %0, %1;" : "=r"(hi) : "f"(x));
    float h = __uint_as_float(hi);
    uint32_t lo;
    asm("cvt.rna.tf32.f32 %0, %1;" : "=r"(lo) : "f"(x - h));
    return make_float2(h, __uint_as_float(lo));
}

__device__ __forceinline__ float tf32hi(float x) {
    uint32_t hi;
    asm("cvt.rna.tf32.f32 %0, %1;" : "=r"(hi) : "f"(x));
    return __uint_as_float(hi);
}

__device__ __forceinline__ void mma8(float c[4],
                                     uint32_t a0, uint32_t a1, uint32_t a2, uint32_t a3,
                                     uint32_t b0, uint32_t b1) {
    asm volatile(
        "mma.sync.aligned.m16n8k8.row.col.f32.tf32.tf32.f32 "
        "{%0,%1,%2,%3}, {%4,%5,%6,%7}, {%8,%9}, {%0,%1,%2,%3};\n"
        : "+f"(c[0]), "+f"(c[1]), "+f"(c[2]), "+f"(c[3])
        : "r"(a0), "r"(a1), "r"(a2), "r"(a3), "r"(b0), "r"(b1));
}

#define F2U(x) __float_as_uint(x)

// 3xTF32 (hi*hi + hi*lo + lo*hi), fp32 accumulate. f = {hi_a, lo_a, hi_b, lo_b}
__device__ __forceinline__ void mma3x4(float c[4],
                                       const float4 f0, const float4 f1,
                                       const float4 bf) {
    mma8(c, F2U(f0.x), F2U(f1.x), F2U(f0.z), F2U(f1.z), F2U(bf.x), F2U(bf.z));
    mma8(c, F2U(f0.x), F2U(f1.x), F2U(f0.z), F2U(f1.z), F2U(bf.y), F2U(bf.w));
    mma8(c, F2U(f0.y), F2U(f1.y), F2U(f0.w), F2U(f1.w), F2U(bf.x), F2U(bf.z));
}

// 1xTF32 on float2 hi-only fragments: f = {hi(k=t), hi(k=t+4)}
__device__ __forceinline__ void mma1x2(float c[4],
                                       const float2 f0, const float2 f1,
                                       const float2 bf) {
    mma8(c, F2U(f0.x), F2U(f1.x), F2U(f0.y), F2U(f1.y), F2U(bf.x), F2U(bf.y));
}

__device__ __forceinline__ float4 packsplit(float v0, float v1) {
    float2 h0 = tf32split(v0);
    float2 h1 = tf32split(v1);
    return make_float4(h0.x, h0.y, h1.x, h1.y);
}

// =============================================================================
// Batched 128x128x16 3xTF32 GEMM (q,k projections), double-buffered.
// =============================================================================
struct GemmBatch {
    const float* A[2];
    const float* B[2];
    const float* bias[2];
    float* C[2];
};

#define BUFSZ  (2*4*130)   // one float4 buffer: [2 khalf][4 t][130]

__global__ __launch_bounds__(256) void gemm_3x(GemmBatch args, int M, int N, int K)
{
    extern __shared__ float4 smemg[];
    float4 (*Apk)[2][4][130] = (float4(*)[2][4][130])smemg;
    float4 (*Bpk)[2][4][130] = (float4(*)[2][4][130])(smemg + 2 * BUFSZ);

    const float* A    = args.A[blockIdx.z];
    const float* B    = args.B[blockIdx.z];
    const float* bias = args.bias[blockIdx.z];
    float*       C    = args.C[blockIdx.z];

    int tid = threadIdx.x;
    int wid = tid >> 5, lane = tid & 31;
    int g = lane >> 2, t = lane & 3;
    int wm = wid >> 2, wn = wid & 3;
    int m0 = blockIdx.y * 128, n0 = blockIdx.x * 128;

    int ma = tid & 127, ha = tid >> 7;
    int nq = tid & 31,  kr = tid >> 5;
    int bs = kr >> 2,   bt = kr & 3;

    float acc[4][4][4];
#pragma unroll
    for (int mt = 0; mt < 4; mt++)
#pragma unroll
        for (int nt = 0; nt < 4; nt++)
#pragma unroll
            for (int c = 0; c < 4; c++) acc[mt][nt][c] = 0.f;

    const int NC = K / 16;
    float4 pa0, pa1, pb0, pb1;
    {
        const float* pA = A + (size_t)(m0 + ma) * K + ha * 8;
        pa0 = *(const float4*)pA;
        pa1 = *(const float4*)(pA + 4);
        const float* pB = B + (size_t)(bs * 8 + bt) * N + n0 + nq * 4;
        pb0 = *(const float4*)pB;
        pb1 = *(const float4*)(pB + 4 * (size_t)N);
    }

    for (int c = 0; c < NC; c++) {
        int buf = c & 1;
        {
            float va[8] = {pa0.x, pa0.y, pa0.z, pa0.w, pa1.x, pa1.y, pa1.z, pa1.w};
            float vb0[4] = {pb0.x, pb0.y, pb0.z, pb0.w};
            float vb1[4] = {pb1.x, pb1.y, pb1.z, pb1.w};
#pragma unroll
            for (int tt = 0; tt < 4; tt++)
                Apk[buf][ha][tt][ma] = packsplit(va[tt], va[tt + 4]);
#pragma unroll
            for (int j = 0; j < 4; j++)
                Bpk[buf][bs][bt][nq * 4 + j] = packsplit(vb0[j], vb1[j]);
        }
        if (c + 1 < NC) {
            int k0 = (c + 1) * 16;
            const float* pA = A + (size_t)(m0 + ma) * K + k0 + ha * 8;
            pa0 = *(const float4*)pA;
            pa1 = *(const float4*)(pA + 4);
            const float* pB = B + (size_t)(k0 + bs * 8 + bt) * N + n0 + nq * 4;
            pb0 = *(const float4*)pB;
            pb1 = *(const float4*)(pB + 4 * (size_t)N);
        }
        __syncthreads();
#pragma unroll
        for (int s = 0; s < 2; s++) {
            float4 af0[4], af1[4];
#pragma unroll
            for (int mt = 0; mt < 4; mt++) {
                int rb = wm * 64 + mt * 16;
                af0[mt] = Apk[buf][s][t][rb + g];
                af1[mt] = Apk[buf][s][t][rb + g + 8];
            }
#pragma unroll
            for (int nt = 0; nt < 4; nt++) {
                float4 bf = Bpk[buf][s][t][wn * 32 + nt * 8 + g];
#pragma unroll
                for (int mt = 0; mt < 4; mt++)
                    mma3x4(acc[mt][nt], af0[mt], af1[mt], bf);
            }
        }
    }

#pragma unroll
    for (int mt = 0; mt < 4; mt++) {
        int r = m0 + wm * 64 + mt * 16 + g;
#pragma unroll
        for (int nt = 0; nt < 4; nt++) {
            int cc = n0 + wn * 32 + nt * 8 + 2 * t;
            float bb0 = bias[cc], bb1 = bias[cc + 1];
            *(float2*)&C[(size_t)r * N + cc] =
                make_float2(acc[mt][nt][0] + bb0, acc[mt][nt][1] + bb1);
            *(float2*)&C[(size_t)(r + 8) * N + cc] =
                make_float2(acc[mt][nt][2] + bb0, acc[mt][nt][3] + bb1);
        }
    }
}

// =============================================================================
// 128x128x16 1xTF32 GEMM, float2 hi-only smem, 2 CTAs/SM.
// =============================================================================
__global__ __launch_bounds__(256, 2) void gemm_1x(const float* __restrict__ A,
                                                  const float* __restrict__ B,
                                                  const float* __restrict__ bias,
                                                  float* __restrict__ C,
                                                  int M, int N, int K)
{
    __shared__ float2 A2[2][2][4][132];
    __shared__ float2 B2[2][2][4][132];

    int tid = threadIdx.x;
    int wid = tid >> 5, lane = tid & 31;
    int g = lane >> 2, t = lane & 3;
    int wm = wid >> 2, wn = wid & 3;
    int m0 = blockIdx.y * 128, n0 = blockIdx.x * 128;

    int ma = tid & 127, ha = tid >> 7;
    int nq = tid & 31,  kr = tid >> 5;
    int bs = kr >> 2,   bt = kr & 3;

    float acc[4][4][4];
#pragma unroll
    for (int mt = 0; mt < 4; mt++)
#pragma unroll
        for (int nt = 0; nt < 4; nt++)
#pragma unroll
            for (int c = 0; c < 4; c++) acc[mt][nt][c] = 0.f;

    const int NC = K / 16;
    float4 pa0, pa1;
    float vb0[4], vb1[4];
    {
        const float* pA = A + (size_t)(m0 + ma) * K + ha * 8;
        pa0 = *(const float4*)pA;
        pa1 = *(const float4*)(pA + 4);
        const float* pB0 = B + (size_t)(bs * 8 + bt) * N + n0 + nq;
        const float* pB1 = pB0 + 4 * (size_t)N;
#pragma unroll
        for (int j = 0; j < 4; j++) { vb0[j] = pB0[j * 32]; vb1[j] = pB1[j * 32]; }
    }

    for (int c = 0; c < NC; c++) {
        int buf = c & 1;
        {
            float va[8] = {pa0.x, pa0.y, pa0.z, pa0.w, pa1.x, pa1.y, pa1.z, pa1.w};
#pragma unroll
            for (int tt = 0; tt < 4; tt++)
                A2[buf][ha][tt][ma] = make_float2(tf32hi(va[tt]), tf32hi(va[tt + 4]));
#pragma unroll
            for (int j = 0; j < 4; j++)
                B2[buf][bs][bt][j * 32 + nq] = make_float2(tf32hi(vb0[j]), tf32hi(vb1[j]));
        }
        if (c + 1 < NC) {
            int k0 = (c + 1) * 16;
            const float* pA = A + (size_t)(m0 + ma) * K + k0 + ha * 8;
            pa0 = *(const float4*)pA;
            pa1 = *(const float4*)(pA + 4);
            const float* pB0 = B + (size_t)(k0 + bs * 8 + bt) * N + n0 + nq;
            const float* pB1 = pB0 + 4 * (size_t)N;
#pragma unroll
            for (int j = 0; j < 4; j++) { vb0[j] = pB0[j * 32]; vb1[j] = pB1[j * 32]; }
        }
        __syncthreads();
#pragma unroll
        for (int s = 0; s < 2; s++) {
            float2 af0[4], af1[4];
#pragma unroll
            for (int mt = 0; mt < 4; mt++) {
                int rb = wm * 64 + mt * 16;
                af0[mt] = A2[buf][s][t][rb + g];
                af1[mt] = A2[buf][s][t][rb + g + 8];
            }
#pragma unroll
            for (int nt = 0; nt < 4; nt++) {
                float2 bf = B2[buf][s][t][wn * 32 + nt * 8 + g];
#pragma unroll
                for (int mt = 0; mt < 4; mt++)
                    mma1x2(acc[mt][nt], af0[mt], af1[mt], bf);
            }
        }
    }

#pragma unroll
    for (int mt = 0; mt < 4; mt++) {
        int r = m0 + wm * 64 + mt * 16 + g;
#pragma unroll
        for (int nt = 0; nt < 4; nt++) {
            int cc = n0 + wn * 32 + nt * 8 + 2 * t;
            float bb0 = bias[cc], bb1 = bias[cc + 1];
            *(float2*)&C[(size_t)r * N + cc] =
                make_float2(acc[mt][nt][0] + bb0, acc[mt][nt][1] + bb1);
            *(float2*)&C[(size_t)(r + 8) * N + cc] =
                make_float2(acc[mt][nt][2] + bb0, acc[mt][nt][3] + bb1);
        }
    }
}

// =============================================================================
// Fused gather (q,k,v) + optional L2-normalize.
// =============================================================================
__global__ __launch_bounds__(256) void gather_norm3(const float* __restrict__ proj_base,
                                                    float* __restrict__ heads_base)
{
    int which = blockIdx.y;
    const float* proj = proj_base + (size_t)which * PROJ_ELEMS;
    float* outp = heads_base + (size_t)which * PROJ_ELEMS;
    int do_norm = (which < 2);

    int w = blockIdx.x * 8 + (threadIdx.x >> 5);
    int lane = threadIdx.x & 31;
    int b2 = w >> 15;
    int h  = (w >> 11) & 15;
    int s2 = w & 2047;
    int e = b2 * 512 + h * 32 + (s2 >> 6);
    int s = ((s2 & 63) << 5) + lane;
    float v0 = proj[(size_t)s * EE + e];
    float v1 = proj[(size_t)(SS + s) * EE + e];
    float rn = 1.0f;
    if (do_norm) {
        float ssq = v0 * v0 + v1 * v1;
#pragma unroll
        for (int o = 16; o; o >>= 1) ssq += __shfl_xor_sync(0xffffffffu, ssq, o);
        rn = rsqrtf(ssq);
    }
    ((float2*)outp)[(size_t)w * 32 + lane] = make_float2(v0 * rn, v1 * rn);
}

// =============================================================================
// mma flash attention: QK^T at 3xTF32 (float4 smem), P@V at 1xTF32 with
// float2 hi-only V/P smem. 68.6KB smem -> 3 CTAs/SM.
// =============================================================================
#define Q_SZ4 (8*4*66)   // float4s
#define K_SZ4 (8*4*34)   // float4s
#define V_SZ2 (4*4*68)   // float2s
#define P_SZ2 (4*4*68)   // float2s

__global__ __launch_bounds__(128, 3) void attn_mma(const float* __restrict__ qn,
                                                   const float* __restrict__ kn,
                                                   const float* __restrict__ vh,
                                                   float* __restrict__ zc,
                                                   float* __restrict__ gm,
                                                   float* __restrict__ gl,
                                                   float* __restrict__ pattn)
{
    extern __shared__ float4 sm4[];
    float4 (*Qpk)[4][66] = (float4(*)[4][66])sm4;                      // [8][4][66] f4
    float4 (*Kpk)[4][34] = (float4(*)[4][34])(sm4 + Q_SZ4);            // [8][4][34] f4
    float2 (*V2)[4][68]  = (float2(*)[4][68])(sm4 + Q_SZ4 + K_SZ4);    // [4][4][68] f2
    float2 (*P2)[4][68]  = (float2(*)[4][68])((float2*)(sm4 + Q_SZ4 + K_SZ4) + V_SZ2);

    int tid = threadIdx.x;
    int w = tid >> 5, lane = tid & 31;
    int g = lane >> 2, t = lane & 3;
    int qb = blockIdx.x, h = blockIdx.y, b2 = blockIdx.z;
    int base = (b2 * HH + h) * SS;
    size_t obase = (size_t)(b2 * HH + h) * SS * SS;
    int q0 = qb * 64;
    int r0 = w * 16;

    // ---- stage Q (hi+lo float4) ----
    {
        int m = tid >> 1, hs = tid & 1;
        const float4* src = (const float4*)(qn + (size_t)(base + q0 + m) * HD + hs * 32);
        float4 v[8];
#pragma unroll
        for (int j = 0; j < 8; j++) v[j] = src[j];
        const float* vf = (const float*)v;
#pragma unroll
        for (int sp = 0; sp < 4; sp++)
#pragma unroll
            for (int tt = 0; tt < 4; tt++)
                Qpk[hs * 4 + sp][tt][m] = packsplit(vf[8 * sp + tt], vf[8 * sp + tt + 4]);
    }

    float oacc[8][4];
#pragma unroll
    for (int nt = 0; nt < 8; nt++)
#pragma unroll
        for (int c = 0; c < 4; c++) oacc[nt][c] = 0.f;
    float m0 = -1e30f, m1 = -1e30f, l0 = 0.f, l1 = 0.f;

    int row0 = q0 + r0 + g, row1 = row0 + 8;
    int nkb = 2 * (qb + 1);

    for (int kb = 0; kb < nkb; kb++) {
        int k0 = kb * 32;
        __syncthreads();
        // ---- stage K tile (hi+lo) ----
        {
            int n = tid >> 2, qk = tid & 3;
            const float4* src = (const float4*)(kn + (size_t)(base + k0 + n) * HD + qk * 16);
            float4 v[4];
#pragma unroll
            for (int j = 0; j < 4; j++) v[j] = src[j];
            const float* vf = (const float*)v;
#pragma unroll
            for (int sp = 0; sp < 2; sp++)
#pragma unroll
                for (int tt = 0; tt < 4; tt++)
                    Kpk[qk * 2 + sp][tt][n] = packsplit(vf[8 * sp + tt], vf[8 * sp + tt + 4]);
        }
        // ---- stage V tile (hi-only float2) ----
        {
            int n4 = tid & 15;
            int comb = tid >> 4;
            int s = comb >> 1, tb = (comb & 1) * 2;
#pragma unroll
            for (int dt = 0; dt < 2; dt++) {
                int tt = tb + dt;
                const float* p = vh + (size_t)(base + k0 + 8 * s + tt) * HD + n4 * 4;
                float4 x0 = *(const float4*)p;
                float4 x1 = *(const float4*)(p + 4 * HD);
                const float* f0 = (const float*)&x0;
                const float* f1 = (const float*)&x1;
#pragma unroll
                for (int j = 0; j < 4; j++)
                    V2[s][tt][n4 * 4 + j] = make_float2(tf32hi(f0[j]), tf32hi(f1[j]));
            }
        }
        __syncthreads();

        if (k0 > q0 + r0 + 15) continue;

        // ---- S = Q @ K^T (3xTF32) ----
        float sacc[4][4];
#pragma unroll
        for (int nt = 0; nt < 4; nt++)
#pragma unroll
            for (int c = 0; c < 4; c++) sacc[nt][c] = 0.f;
#pragma unroll
        for (int ks = 0; ks < 8; ks++) {
            float4 f0 = Qpk[ks][t][r0 + g];
            float4 f1 = Qpk[ks][t][r0 + g + 8];
#pragma unroll
            for (int nt = 0; nt < 4; nt++) {
                float4 bf = Kpk[ks][t][nt * 8 + g];
                mma3x4(sacc[nt], f0, f1, bf);
            }
        }

        // ---- scale + mask ----
        bool nm = (k0 + 31 > q0 + r0);
        float sv[4][4];
        float mx0 = -1e30f, mx1 = -1e30f;
#pragma unroll
        for (int nt = 0; nt < 4; nt++) {
            int cb = k0 + nt * 8 + 2 * t;
            float s0 = sacc[nt][0] * 1000.f;
            float s1 = sacc[nt][1] * 1000.f;
            float s2 = sacc[nt][2] * 1000.f;
            float s3 = sacc[nt][3] * 1000.f;
            if (nm) {
                if (cb > row0) s0 = -1e30f;
                if (cb + 1 > row0) s1 = -1e30f;
                if (cb > row1) s2 = -1e30f;
                if (cb + 1 > row1) s3 = -1e30f;
            }
            sv[nt][0] = s0; sv[nt][1] = s1; sv[nt][2] = s2; sv[nt][3] = s3;
            mx0 = fmaxf(mx0, fmaxf(s0, s1));
            mx1 = fmaxf(mx1, fmaxf(s2, s3));
        }

        // ---- stream logits to attn buffer ----
        if (pattn) {
#pragma unroll
            for (int nt = 0; nt < 4; nt++) {
                int jg = k0 + nt * 8 + 2 * t;
                *(float2*)&pattn[obase + (size_t)row0 * SS + jg] = make_float2(sv[nt][0], sv[nt][1]);
                *(float2*)&pattn[obase + (size_t)row1 * SS + jg] = make_float2(sv[nt][2], sv[nt][3]);
            }
        }

        // ---- online softmax ----
        mx0 = fmaxf(mx0, __shfl_xor_sync(0xffffffffu, mx0, 1));
        mx0 = fmaxf(mx0, __shfl_xor_sync(0xffffffffu, mx0, 2));
        mx1 = fmaxf(mx1, __shfl_xor_sync(0xffffffffu, mx1, 1));
        mx1 = fmaxf(mx1, __shfl_xor_sync(0xffffffffu, mx1, 2));
        float mn0 = fmaxf(m0, mx0), mn1 = fmaxf(m1, mx1);
        float sc0 = __expf(m0 - mn0), sc1 = __expf(m1 - mn1);
        m0 = mn0; m1 = mn1;
        float rs0 = 0.f, rs1 = 0.f;
        int tpA = (2 * t) & 3, tpB = (2 * t + 1) & 3;
        int slot = (t >= 2);
#pragma unroll
        for (int nt = 0; nt < 4; nt++) {
            float p0 = __expf(sv[nt][0] - mn0);
            float p1 = __expf(sv[nt][1] - mn0);
            float p2 = __expf(sv[nt][2] - mn1);
            float p3 = __expf(sv[nt][3] - mn1);
            rs0 += p0 + p1;
            rs1 += p2 + p3;
            ((float*)&P2[nt][tpA][r0 + g])[slot]     = tf32hi(p0);
            ((float*)&P2[nt][tpB][r0 + g])[slot]     = tf32hi(p1);
            ((float*)&P2[nt][tpA][r0 + g + 8])[slot] = tf32hi(p2);
            ((float*)&P2[nt][tpB][r0 + g + 8])[slot] = tf32hi(p3);
        }
        rs0 += __shfl_xor_sync(0xffffffffu, rs0, 1);
        rs0 += __shfl_xor_sync(0xffffffffu, rs0, 2);
        rs1 += __shfl_xor_sync(0xffffffffu, rs1, 1);
        rs1 += __shfl_xor_sync(0xffffffffu, rs1, 2);
        l0 = l0 * sc0 + rs0;
        l1 = l1 * sc1 + rs1;
#pragma unroll
        for (int nt = 0; nt < 8; nt++) {
            oacc[nt][0] *= sc0; oacc[nt][1] *= sc0;
            oacc[nt][2] *= sc1; oacc[nt][3] *= sc1;
        }
        __syncwarp();

        // ---- O += P @ V (1xTF32, float2 fragments) ----
#pragma unroll
        for (int s = 0; s < 4; s++) {
            float2 f0 = P2[s][t][r0 + g];
            float2 f1 = P2[s][t][r0 + g + 8];
#pragma unroll
            for (int nt = 0; nt < 8; nt++) {
                float2 bf = V2[s][t][nt * 8 + g];
                mma1x2(oacc[nt], f0, f1, bf);
            }
        }
    }

    // ---- epilogue ----
    float inv0 = 1.f / l0, inv1 = 1.f / l1;
    int rg = b2 * SS + q0 + r0 + g;
#pragma unroll
    for (int nt = 0; nt < 8; nt++) {
        int col = h * HD + nt * 8 + 2 * t;
        *(float2*)&zc[(size_t)rg * EE + col] =
            make_float2(oacc[nt][0] * inv0, oacc[nt][1] * inv0);
        *(float2*)&zc[(size_t)(rg + 8) * EE + col] =
            make_float2(oacc[nt][2] * inv1, oacc[nt][3] * inv1);
    }
    if (t == 0) {
        gm[base + q0 + r0 + g] = m0;
        gl[base + q0 + r0 + g] = l0;
        gm[base + q0 + r0 + g + 8] = m1;
        gl[base + q0 + r0 + g + 8] = l1;
    }
}

// =============================================================================
// attn normalize: in-place exp(logit - m)/l on lower tiles; zero upper tiles.
// =============================================================================
__global__ __launch_bounds__(256) void attn_norm(const float* __restrict__ gm,
                                                 const float* __restrict__ gl,
                                                 float* __restrict__ attn)
{
    int qb = blockIdx.x >> 5, kb = blockIdx.x & 31;
    int h = blockIdx.y, b2 = blockIdx.z;
    size_t obase = (size_t)(b2 * HH + h) * SS * SS;
    int q0 = qb * 64, k0 = kb * 64;
    int tid = threadIdx.x;

    if (kb > qb) {
        float4 z = make_float4(0.f, 0.f, 0.f, 0.f);
#pragma unroll
        for (int l = 0; l < 4; l++) {
            int idx = l * 256 + tid;
            int row = idx >> 4, c4 = idx & 15;
            *(float4*)&attn[obase + (size_t)(q0 + row) * SS + k0 + c4 * 4] = z;
        }
        return;
    }

    __shared__ float ms[64], il[64];
    int base = (b2 * HH + h) * SS;
    if (tid < 64) {
        ms[tid] = gm[base + q0 + tid];
        il[tid] = 1.f / gl[base + q0 + tid];
    }
    __syncthreads();

#pragma unroll
    for (int l = 0; l < 4; l++) {
        int idx = l * 256 + tid;
        int row = idx >> 4, c4 = idx & 15;
        int grow = q0 + row;
        int gcol = k0 + c4 * 4;
        size_t off = obase + (size_t)grow * SS + gcol;
        float4 lg = *(const float4*)&attn[off];
        float mm = ms[row], ss = il[row];
        float4 p;
        p.x = (gcol     > grow) ? 0.f : __expf(lg.x - mm) * ss;
        p.y = (gcol + 1 > grow) ? 0.f : __expf(lg.y - mm) * ss;
        p.z = (gcol + 2 > grow) ? 0.f : __expf(lg.z - mm) * ss;
        p.w = (gcol + 3 > grow) ? 0.f : __expf(lg.w - mm) * ss;
        *(float4*)&attn[off] = p;
    }
}

// =============================================================================
// Host launcher
// =============================================================================
extern "C" void kernel_launch(void* const* d_in, const int* in_sizes, int n_in,
                              void* d_out, int out_size)
{
    const float* q  = (const float*)d_in[0];
    const float* k  = (const float*)d_in[1];
    const float* v  = (const float*)d_in[2];
    const float* Wq = (const float*)d_in[4];
    const float* bq = (const float*)d_in[5];
    const float* Wk = (const float*)d_in[6];
    const float* bk = (const float*)d_in[7];
    const float* Wv = (const float*)d_in[8];
    const float* bv = (const float*)d_in[9];
    const float* Wz = (const float*)d_in[10];
    const float* bz = (const float*)d_in[11];
    float* out = (float*)d_out;

    float *proj, *heads, *zc, *gm, *gl;
    cudaGetSymbolAddress((void**)&proj,  g_proj);
    cudaGetSymbolAddress((void**)&heads, g_heads);
    cudaGetSymbolAddress((void**)&zc,    g_zc);
    cudaGetSymbolAddress((void**)&gm,    g_m);
    cudaGetSymbolAddress((void**)&gl,    g_l);

    int need_attn = ((long long)out_size >= (long long)PROJ_ELEMS + (long long)ATTN_ELEMS);
    float* pattn = need_attn ? (out + PROJ_ELEMS) : (float*)0;

    size_t smG = (size_t)(4 * BUFSZ) * sizeof(float4);
    cudaFuncSetAttribute(gemm_3x, cudaFuncAttributeMaxDynamicSharedMemorySize, (int)smG);

    // 1) q,k projections at 3xTF32 (batched)
    GemmBatch pb;
    pb.A[0] = q;  pb.A[1] = k;
    pb.B[0] = Wq; pb.B[1] = Wk;
    pb.bias[0] = bq; pb.bias[1] = bk;
    pb.C[0] = proj;
    pb.C[1] = proj + (size_t)PROJ_ELEMS;
    gemm_3x<<<dim3(EE / 128, ROWS / 128, 2), 256, smG>>>(pb, ROWS, EE, EE);

    // 2) v projection at 1xTF32
    gemm_1x<<<dim3(EE / 128, ROWS / 128), 256>>>(v, Wv, bv,
        proj + 2 * (size_t)PROJ_ELEMS, ROWS, EE, EE);

    // 3) fused gather + normalize
    gather_norm3<<<dim3(NHROWS / 8, 3), 256>>>(proj, heads);

    // 4) mma flash attention (streams logits to pattn)
    size_t smA = (size_t)(Q_SZ4 + K_SZ4) * sizeof(float4)
               + (size_t)(V_SZ2 + P_SZ2) * sizeof(float2);   // 68,608 B
    cudaFuncSetAttribute(attn_mma, cudaFuncAttributeMaxDynamicSharedMemorySize, (int)smA);
    attn_mma<<<dim3(SS / 64, HH, BB), 128, smA>>>(
        heads, heads + (size_t)PROJ_ELEMS, heads + 2 * (size_t)PROJ_ELEMS,
        zc, gm, gl, pattn);

    // 5) attn normalize (in place) + upper zero
    if (need_attn)
        attn_norm<<<dim3(32 * 32, HH, BB), 256>>>(gm, gl, pattn);

    // 6) final output projection at 1xTF32 — profiled slot
    gemm_1x<<<dim3(EE / 128, ROWS / 128), 256>>>(zc, Wz, bz, out, ROWS, EE, EE);
}

// round 8
// speedup vs baseline: 2.0752x; 1.0234x over previous
#include <cuda_runtime.h>
#include <math.h>
#include <stdint.h>

// ---------------- problem constants ----------------
#define BB 2
#define SS 2048
#define EE 1024
#define HH 16
#define HD 64
#define ROWS (BB*SS)           // 4096
#define NHROWS (BB*HH*SS)      // 65536
#define PROJ_ELEMS (ROWS*EE)   // 4194304
#define ATTN_ELEMS (BB*HH*SS*SS) // 134217728

// ---------------- scratch ----------------
__device__ float g_proj[3][PROJ_ELEMS];
__device__ float g_heads[3][PROJ_ELEMS];
__device__ float g_zc[PROJ_ELEMS];
__device__ float g_m[NHROWS];
__device__ float g_l[NHROWS];

// ---------------- tf32 helpers ----------------
__device__ __forceinline__ float2 tf32split(float x) {
    uint32_t hi;
    asm("cvt.rna.tf32.f32 %0, %1;" : "=r"(hi) : "f"(x));
    float h = __uint_as_float(hi);
    uint32_t lo;
    asm("cvt.rna.tf32.f32 %0, %1;" : "=r"(lo) : "f"(x - h));
    return make_float2(h, __uint_as_float(lo));
}

__device__ __forceinline__ float tf32hi(float x) {
    uint32_t hi;
    asm("cvt.rna.tf32.f32 %0, %1;" : "=r"(hi) : "f"(x));
    return __uint_as_float(hi);
}

__device__ __forceinline__ void mma8(float c[4],
                                     uint32_t a0, uint32_t a1, uint32_t a2, uint32_t a3,
                                     uint32_t b0, uint32_t b1) {
    asm volatile(
        "mma.sync.aligned.m16n8k8.row.col.f32.tf32.tf32.f32 "
        "{%0,%1,%2,%3}, {%4,%5,%6,%7}, {%8,%9}, {%0,%1,%2,%3};\n"
        : "+f"(c[0]), "+f"(c[1]), "+f"(c[2]), "+f"(c[3])
        : "r"(a0), "r"(a1), "r"(a2), "r"(a3), "r"(b0), "r"(b1));
}

#define F2U(x) __float_as_uint(x)

// 3xTF32 (hi*hi + hi*lo + lo*hi), fp32 accumulate. f = {hi_a, lo_a, hi_b, lo_b}
__device__ __forceinline__ void mma3x4(float c[4],
                                       const float4 f0, const float4 f1,
                                       const float4 bf) {
    mma8(c, F2U(f0.x), F2U(f1.x), F2U(f0.z), F2U(f1.z), F2U(bf.x), F2U(bf.z));
    mma8(c, F2U(f0.x), F2U(f1.x), F2U(f0.z), F2U(f1.z), F2U(bf.y), F2U(bf.w));
    mma8(c, F2U(f0.y), F2U(f1.y), F2U(f0.w), F2U(f1.w), F2U(bf.x), F2U(bf.z));
}

// 1xTF32 on float2 hi-only fragments: f = {hi(k=t), hi(k=t+4)}
__device__ __forceinline__ void mma1x2(float c[4],
                                       const float2 f0, const float2 f1,
                                       const float2 bf) {
    mma8(c, F2U(f0.x), F2U(f1.x), F2U(f0.y), F2U(f1.y), F2U(bf.x), F2U(bf.y));
}

__device__ __forceinline__ float4 packsplit(float v0, float v1) {
    float2 h0 = tf32split(v0);
    float2 h1 = tf32split(v1);
    return make_float4(h0.x, h0.y, h1.x, h1.y);
}

// =============================================================================
// Batched 128x128x16 3xTF32 GEMM (q,k projections), double-buffered.
// =============================================================================
struct GemmBatch {
    const float* A[2];
    const float* B[2];
    const float* bias[2];
    float* C[2];
};

#define BUFSZ  (2*4*130)   // one float4 buffer: [2 khalf][4 t][130]

__global__ __launch_bounds__(256) void gemm_3x(GemmBatch args, int M, int N, int K)
{
    extern __shared__ float4 smemg[];
    float4 (*Apk)[2][4][130] = (float4(*)[2][4][130])smemg;
    float4 (*Bpk)[2][4][130] = (float4(*)[2][4][130])(smemg + 2 * BUFSZ);

    const float* A    = args.A[blockIdx.z];
    const float* B    = args.B[blockIdx.z];
    const float* bias = args.bias[blockIdx.z];
    float*       C    = args.C[blockIdx.z];

    int tid = threadIdx.x;
    int wid = tid >> 5, lane = tid & 31;
    int g = lane >> 2, t = lane & 3;
    int wm = wid >> 2, wn = wid & 3;
    int m0 = blockIdx.y * 128, n0 = blockIdx.x * 128;

    int ma = tid & 127, ha = tid >> 7;
    int nq = tid & 31,  kr = tid >> 5;
    int bs = kr >> 2,   bt = kr & 3;

    float acc[4][4][4];
#pragma unroll
    for (int mt = 0; mt < 4; mt++)
#pragma unroll
        for (int nt = 0; nt < 4; nt++)
#pragma unroll
            for (int c = 0; c < 4; c++) acc[mt][nt][c] = 0.f;

    const int NC = K / 16;
    float4 pa0, pa1, pb0, pb1;
    {
        const float* pA = A + (size_t)(m0 + ma) * K + ha * 8;
        pa0 = *(const float4*)pA;
        pa1 = *(const float4*)(pA + 4);
        const float* pB = B + (size_t)(bs * 8 + bt) * N + n0 + nq * 4;
        pb0 = *(const float4*)pB;
        pb1 = *(const float4*)(pB + 4 * (size_t)N);
    }

    for (int c = 0; c < NC; c++) {
        int buf = c & 1;
        {
            float va[8] = {pa0.x, pa0.y, pa0.z, pa0.w, pa1.x, pa1.y, pa1.z, pa1.w};
            float vb0[4] = {pb0.x, pb0.y, pb0.z, pb0.w};
            float vb1[4] = {pb1.x, pb1.y, pb1.z, pb1.w};
#pragma unroll
            for (int tt = 0; tt < 4; tt++)
                Apk[buf][ha][tt][ma] = packsplit(va[tt], va[tt + 4]);
#pragma unroll
            for (int j = 0; j < 4; j++)
                Bpk[buf][bs][bt][nq * 4 + j] = packsplit(vb0[j], vb1[j]);
        }
        if (c + 1 < NC) {
            int k0 = (c + 1) * 16;
            const float* pA = A + (size_t)(m0 + ma) * K + k0 + ha * 8;
            pa0 = *(const float4*)pA;
            pa1 = *(const float4*)(pA + 4);
            const float* pB = B + (size_t)(k0 + bs * 8 + bt) * N + n0 + nq * 4;
            pb0 = *(const float4*)pB;
            pb1 = *(const float4*)(pB + 4 * (size_t)N);
        }
        __syncthreads();
#pragma unroll
        for (int s = 0; s < 2; s++) {
            float4 af0[4], af1[4];
#pragma unroll
            for (int mt = 0; mt < 4; mt++) {
                int rb = wm * 64 + mt * 16;
                af0[mt] = Apk[buf][s][t][rb + g];
                af1[mt] = Apk[buf][s][t][rb + g + 8];
            }
#pragma unroll
            for (int nt = 0; nt < 4; nt++) {
                float4 bf = Bpk[buf][s][t][wn * 32 + nt * 8 + g];
#pragma unroll
                for (int mt = 0; mt < 4; mt++)
                    mma3x4(acc[mt][nt], af0[mt], af1[mt], bf);
            }
        }
    }

#pragma unroll
    for (int mt = 0; mt < 4; mt++) {
        int r = m0 + wm * 64 + mt * 16 + g;
#pragma unroll
        for (int nt = 0; nt < 4; nt++) {
            int cc = n0 + wn * 32 + nt * 8 + 2 * t;
            float bb0 = bias[cc], bb1 = bias[cc + 1];
            *(float2*)&C[(size_t)r * N + cc] =
                make_float2(acc[mt][nt][0] + bb0, acc[mt][nt][1] + bb1);
            *(float2*)&C[(size_t)(r + 8) * N + cc] =
                make_float2(acc[mt][nt][2] + bb0, acc[mt][nt][3] + bb1);
        }
    }
}

// =============================================================================
// 128x128x16 1xTF32 GEMM, float2 hi-only smem, 2 CTAs/SM.
// =============================================================================
__global__ __launch_bounds__(256, 2) void gemm_1x(const float* __restrict__ A,
                                                  const float* __restrict__ B,
                                                  const float* __restrict__ bias,
                                                  float* __restrict__ C,
                                                  int M, int N, int K)
{
    __shared__ float2 A2[2][2][4][132];
    __shared__ float2 B2[2][2][4][132];

    int tid = threadIdx.x;
    int wid = tid >> 5, lane = tid & 31;
    int g = lane >> 2, t = lane & 3;
    int wm = wid >> 2, wn = wid & 3;
    int m0 = blockIdx.y * 128, n0 = blockIdx.x * 128;

    int ma = tid & 127, ha = tid >> 7;
    int nq = tid & 31,  kr = tid >> 5;
    int bs = kr >> 2,   bt = kr & 3;

    float acc[4][4][4];
#pragma unroll
    for (int mt = 0; mt < 4; mt++)
#pragma unroll
        for (int nt = 0; nt < 4; nt++)
#pragma unroll
            for (int c = 0; c < 4; c++) acc[mt][nt][c] = 0.f;

    const int NC = K / 16;
    float4 pa0, pa1;
    float vb0[4], vb1[4];
    {
        const float* pA = A + (size_t)(m0 + ma) * K + ha * 8;
        pa0 = *(const float4*)pA;
        pa1 = *(const float4*)(pA + 4);
        const float* pB0 = B + (size_t)(bs * 8 + bt) * N + n0 + nq;
        const float* pB1 = pB0 + 4 * (size_t)N;
#pragma unroll
        for (int j = 0; j < 4; j++) { vb0[j] = pB0[j * 32]; vb1[j] = pB1[j * 32]; }
    }

    for (int c = 0; c < NC; c++) {
        int buf = c & 1;
        {
            float va[8] = {pa0.x, pa0.y, pa0.z, pa0.w, pa1.x, pa1.y, pa1.z, pa1.w};
#pragma unroll
            for (int tt = 0; tt < 4; tt++)
                A2[buf][ha][tt][ma] = make_float2(tf32hi(va[tt]), tf32hi(va[tt + 4]));
#pragma unroll
            for (int j = 0; j < 4; j++)
                B2[buf][bs][bt][j * 32 + nq] = make_float2(tf32hi(vb0[j]), tf32hi(vb1[j]));
        }
        if (c + 1 < NC) {
            int k0 = (c + 1) * 16;
            const float* pA = A + (size_t)(m0 + ma) * K + k0 + ha * 8;
            pa0 = *(const float4*)pA;
            pa1 = *(const float4*)(pA + 4);
            const float* pB0 = B + (size_t)(k0 + bs * 8 + bt) * N + n0 + nq;
            const float* pB1 = pB0 + 4 * (size_t)N;
#pragma unroll
            for (int j = 0; j < 4; j++) { vb0[j] = pB0[j * 32]; vb1[j] = pB1[j * 32]; }
        }
        __syncthreads();
#pragma unroll
        for (int s = 0; s < 2; s++) {
            float2 af0[4], af1[4];
#pragma unroll
            for (int mt = 0; mt < 4; mt++) {
                int rb = wm * 64 + mt * 16;
                af0[mt] = A2[buf][s][t][rb + g];
                af1[mt] = A2[buf][s][t][rb + g + 8];
            }
#pragma unroll
            for (int nt = 0; nt < 4; nt++) {
                float2 bf = B2[buf][s][t][wn * 32 + nt * 8 + g];
#pragma unroll
                for (int mt = 0; mt < 4; mt++)
                    mma1x2(acc[mt][nt], af0[mt], af1[mt], bf);
            }
        }
    }

#pragma unroll
    for (int mt = 0; mt < 4; mt++) {
        int r = m0 + wm * 64 + mt * 16 + g;
#pragma unroll
        for (int nt = 0; nt < 4; nt++) {
            int cc = n0 + wn * 32 + nt * 8 + 2 * t;
            float bb0 = bias[cc], bb1 = bias[cc + 1];
            *(float2*)&C[(size_t)r * N + cc] =
                make_float2(acc[mt][nt][0] + bb0, acc[mt][nt][1] + bb1);
            *(float2*)&C[(size_t)(r + 8) * N + cc] =
                make_float2(acc[mt][nt][2] + bb0, acc[mt][nt][3] + bb1);
        }
    }
}

// =============================================================================
// Fused gather (q,k,v) + optional L2-normalize.
// =============================================================================
__global__ __launch_bounds__(256) void gather_norm3(const float* __restrict__ proj_base,
                                                    float* __restrict__ heads_base)
{
    int which = blockIdx.y;
    const float* proj = proj_base + (size_t)which * PROJ_ELEMS;
    float* outp = heads_base + (size_t)which * PROJ_ELEMS;
    int do_norm = (which < 2);

    int w = blockIdx.x * 8 + (threadIdx.x >> 5);
    int lane = threadIdx.x & 31;
    int b2 = w >> 15;
    int h  = (w >> 11) & 15;
    int s2 = w & 2047;
    int e = b2 * 512 + h * 32 + (s2 >> 6);
    int s = ((s2 & 63) << 5) + lane;
    float v0 = proj[(size_t)s * EE + e];
    float v1 = proj[(size_t)(SS + s) * EE + e];
    float rn = 1.0f;
    if (do_norm) {
        float ssq = v0 * v0 + v1 * v1;
#pragma unroll
        for (int o = 16; o; o >>= 1) ssq += __shfl_xor_sync(0xffffffffu, ssq, o);
        rn = rsqrtf(ssq);
    }
    ((float2*)outp)[(size_t)w * 32 + lane] = make_float2(v0 * rn, v1 * rn);
}

// =============================================================================
// mma flash attention, BQ=128 / BK=32, 256 threads (8 warps x 16 q-rows),
// 2 CTAs/SM. QK^T at 3xTF32; P@V at 1xTF32 float2 hi-only smem.
// =============================================================================
#define Q_SZ4 (8*4*130)   // float4s
#define K_SZ4 (8*4*34)    // float4s
#define V_SZ2 (4*4*68)    // float2s
#define P_SZ2 (4*4*132)   // float2s

__global__ __launch_bounds__(256, 2) void attn_mma(const float* __restrict__ qn,
                                                   const float* __restrict__ kn,
                                                   const float* __restrict__ vh,
                                                   float* __restrict__ zc,
                                                   float* __restrict__ gm,
                                                   float* __restrict__ gl,
                                                   float* __restrict__ pattn)
{
    extern __shared__ float4 sm4[];
    float4 (*Qpk)[4][130] = (float4(*)[4][130])sm4;                    // [8][4][130] f4
    float4 (*Kpk)[4][34]  = (float4(*)[4][34])(sm4 + Q_SZ4);           // [8][4][34] f4
    float2 (*V2)[4][68]   = (float2(*)[4][68])(sm4 + Q_SZ4 + K_SZ4);   // [4][4][68] f2
    float2 (*P2)[4][132]  = (float2(*)[4][132])((float2*)(sm4 + Q_SZ4 + K_SZ4) + V_SZ2);

    int tid = threadIdx.x;
    int w = tid >> 5, lane = tid & 31;
    int g = lane >> 2, t = lane & 3;
    int qb = blockIdx.x, h = blockIdx.y, b2 = blockIdx.z;
    int base = (b2 * HH + h) * SS;
    size_t obase = (size_t)(b2 * HH + h) * SS * SS;
    int q0 = qb * 128;
    int r0 = w * 16;

    // ---- stage Q: 128 rows (hi+lo float4) ----
    {
        int m = tid >> 1, hs = tid & 1;
        const float4* src = (const float4*)(qn + (size_t)(base + q0 + m) * HD + hs * 32);
        float4 v[8];
#pragma unroll
        for (int j = 0; j < 8; j++) v[j] = src[j];
        const float* vf = (const float*)v;
#pragma unroll
        for (int sp = 0; sp < 4; sp++)
#pragma unroll
            for (int tt = 0; tt < 4; tt++)
                Qpk[hs * 4 + sp][tt][m] = packsplit(vf[8 * sp + tt], vf[8 * sp + tt + 4]);
    }

    float oacc[8][4];
#pragma unroll
    for (int nt = 0; nt < 8; nt++)
#pragma unroll
        for (int c = 0; c < 4; c++) oacc[nt][c] = 0.f;
    float m0 = -1e30f, m1 = -1e30f, l0 = 0.f, l1 = 0.f;

    int row0 = q0 + r0 + g, row1 = row0 + 8;
    int nkb = 4 * (qb + 1);

    for (int kb = 0; kb < nkb; kb++) {
        int k0 = kb * 32;
        __syncthreads();
        // ---- stage K tile (hi+lo): 32 rows x 64 cols, 256 threads ----
        {
            int n = tid >> 3, oct = tid & 7;
            const float4* src = (const float4*)(kn + (size_t)(base + k0 + n) * HD + oct * 8);
            float4 v0 = src[0], v1 = src[1];
            float vf[8] = {v0.x, v0.y, v0.z, v0.w, v1.x, v1.y, v1.z, v1.w};
#pragma unroll
            for (int tt = 0; tt < 4; tt++)
                Kpk[oct][tt][n] = packsplit(vf[tt], vf[tt + 4]);
        }
        // ---- stage V tile (hi-only float2): 32 rows x 64 cols ----
        {
            int n4 = tid & 15;
            int comb = tid >> 4;           // 0..15
            int s = comb >> 2, tt = comb & 3;
            const float* p = vh + (size_t)(base + k0 + 8 * s + tt) * HD + n4 * 4;
            float4 x0 = *(const float4*)p;
            float4 x1 = *(const float4*)(p + 4 * HD);
            const float* f0 = (const float*)&x0;
            const float* f1 = (const float*)&x1;
#pragma unroll
            for (int j = 0; j < 4; j++)
                V2[s][tt][n4 * 4 + j] = make_float2(tf32hi(f0[j]), tf32hi(f1[j]));
        }
        __syncthreads();

        if (k0 > q0 + r0 + 15) continue;

        // ---- S = Q @ K^T (3xTF32) ----
        float sacc[4][4];
#pragma unroll
        for (int nt = 0; nt < 4; nt++)
#pragma unroll
            for (int c = 0; c < 4; c++) sacc[nt][c] = 0.f;
#pragma unroll
        for (int ks = 0; ks < 8; ks++) {
            float4 f0 = Qpk[ks][t][r0 + g];
            float4 f1 = Qpk[ks][t][r0 + g + 8];
#pragma unroll
            for (int nt = 0; nt < 4; nt++) {
                float4 bf = Kpk[ks][t][nt * 8 + g];
                mma3x4(sacc[nt], f0, f1, bf);
            }
        }

        // ---- scale + mask ----
        bool nm = (k0 + 31 > q0 + r0);
        float sv[4][4];
        float mx0 = -1e30f, mx1 = -1e30f;
#pragma unroll
        for (int nt = 0; nt < 4; nt++) {
            int cb = k0 + nt * 8 + 2 * t;
            float s0 = sacc[nt][0] * 1000.f;
            float s1 = sacc[nt][1] * 1000.f;
            float s2 = sacc[nt][2] * 1000.f;
            float s3 = sacc[nt][3] * 1000.f;
            if (nm) {
                if (cb > row0) s0 = -1e30f;
                if (cb + 1 > row0) s1 = -1e30f;
                if (cb > row1) s2 = -1e30f;
                if (cb + 1 > row1) s3 = -1e30f;
            }
            sv[nt][0] = s0; sv[nt][1] = s1; sv[nt][2] = s2; sv[nt][3] = s3;
            mx0 = fmaxf(mx0, fmaxf(s0, s1));
            mx1 = fmaxf(mx1, fmaxf(s2, s3));
        }

        // ---- stream logits to attn buffer ----
        if (pattn) {
#pragma unroll
            for (int nt = 0; nt < 4; nt++) {
                int jg = k0 + nt * 8 + 2 * t;
                *(float2*)&pattn[obase + (size_t)row0 * SS + jg] = make_float2(sv[nt][0], sv[nt][1]);
                *(float2*)&pattn[obase + (size_t)row1 * SS + jg] = make_float2(sv[nt][2], sv[nt][3]);
            }
        }

        // ---- online softmax ----
        mx0 = fmaxf(mx0, __shfl_xor_sync(0xffffffffu, mx0, 1));
        mx0 = fmaxf(mx0, __shfl_xor_sync(0xffffffffu, mx0, 2));
        mx1 = fmaxf(mx1, __shfl_xor_sync(0xffffffffu, mx1, 1));
        mx1 = fmaxf(mx1, __shfl_xor_sync(0xffffffffu, mx1, 2));
        float mn0 = fmaxf(m0, mx0), mn1 = fmaxf(m1, mx1);
        float sc0 = __expf(m0 - mn0), sc1 = __expf(m1 - mn1);
        m0 = mn0; m1 = mn1;
        float rs0 = 0.f, rs1 = 0.f;
        int tpA = (2 * t) & 3, tpB = (2 * t + 1) & 3;
        int slot = (t >= 2);
#pragma unroll
        for (int nt = 0; nt < 4; nt++) {
            float p0 = __expf(sv[nt][0] - mn0);
            float p1 = __expf(sv[nt][1] - mn0);
            float p2 = __expf(sv[nt][2] - mn1);
            float p3 = __expf(sv[nt][3] - mn1);
            rs0 += p0 + p1;
            rs1 += p2 + p3;
            ((float*)&P2[nt][tpA][r0 + g])[slot]     = tf32hi(p0);
            ((float*)&P2[nt][tpB][r0 + g])[slot]     = tf32hi(p1);
            ((float*)&P2[nt][tpA][r0 + g + 8])[slot] = tf32hi(p2);
            ((float*)&P2[nt][tpB][r0 + g + 8])[slot] = tf32hi(p3);
        }
        rs0 += __shfl_xor_sync(0xffffffffu, rs0, 1);
        rs0 += __shfl_xor_sync(0xffffffffu, rs0, 2);
        rs1 += __shfl_xor_sync(0xffffffffu, rs1, 1);
        rs1 += __shfl_xor_sync(0xffffffffu, rs1, 2);
        l0 = l0 * sc0 + rs0;
        l1 = l1 * sc1 + rs1;
#pragma unroll
        for (int nt = 0; nt < 8; nt++) {
            oacc[nt][0] *= sc0; oacc[nt][1] *= sc0;
            oacc[nt][2] *= sc1; oacc[nt][3] *= sc1;
        }
        __syncwarp();

        // ---- O += P @ V (1xTF32, float2 fragments) ----
#pragma unroll
        for (int s = 0; s < 4; s++) {
            float2 f0 = P2[s][t][r0 + g];
            float2 f1 = P2[s][t][r0 + g + 8];
#pragma unroll
            for (int nt = 0; nt < 8; nt++) {
                float2 bf = V2[s][t][nt * 8 + g];
                mma1x2(oacc[nt], f0, f1, bf);
            }
        }
    }

    // ---- epilogue ----
    float inv0 = 1.f / l0, inv1 = 1.f / l1;
    int rg = b2 * SS + q0 + r0 + g;
#pragma unroll
    for (int nt = 0; nt < 8; nt++) {
        int col = h * HD + nt * 8 + 2 * t;
        *(float2*)&zc[(size_t)rg * EE + col] =
            make_float2(oacc[nt][0] * inv0, oacc[nt][1] * inv0);
        *(float2*)&zc[(size_t)(rg + 8) * EE + col] =
            make_float2(oacc[nt][2] * inv1, oacc[nt][3] * inv1);
    }
    if (t == 0) {
        gm[base + q0 + r0 + g] = m0;
        gl[base + q0 + r0 + g] = l0;
        gm[base + q0 + r0 + g + 8] = m1;
        gl[base + q0 + r0 + g + 8] = l1;
    }
}

// =============================================================================
// attn normalize: in-place exp(logit - m)/l on lower tiles; zero upper tiles.
// =============================================================================
__global__ __launch_bounds__(256) void attn_norm(const float* __restrict__ gm,
                                                 const float* __restrict__ gl,
                                                 float* __restrict__ attn)
{
    int qb = blockIdx.x >> 5, kb = blockIdx.x & 31;
    int h = blockIdx.y, b2 = blockIdx.z;
    size_t obase = (size_t)(b2 * HH + h) * SS * SS;
    int q0 = qb * 64, k0 = kb * 64;
    int tid = threadIdx.x;

    if (kb > qb) {
        float4 z = make_float4(0.f, 0.f, 0.f, 0.f);
#pragma unroll
        for (int l = 0; l < 4; l++) {
            int idx = l * 256 + tid;
            int row = idx >> 4, c4 = idx & 15;
            *(float4*)&attn[obase + (size_t)(q0 + row) * SS + k0 + c4 * 4] = z;
        }
        return;
    }

    __shared__ float ms[64], il[64];
    int base = (b2 * HH + h) * SS;
    if (tid < 64) {
        ms[tid] = gm[base + q0 + tid];
        il[tid] = 1.f / gl[base + q0 + tid];
    }
    __syncthreads();

#pragma unroll
    for (int l = 0; l < 4; l++) {
        int idx = l * 256 + tid;
        int row = idx >> 4, c4 = idx & 15;
        int grow = q0 + row;
        int gcol = k0 + c4 * 4;
        size_t off = obase + (size_t)grow * SS + gcol;
        float4 lg = *(const float4*)&attn[off];
        float mm = ms[row], ss = il[row];
        float4 p;
        p.x = (gcol     > grow) ? 0.f : __expf(lg.x - mm) * ss;
        p.y = (gcol + 1 > grow) ? 0.f : __expf(lg.y - mm) * ss;
        p.z = (gcol + 2 > grow) ? 0.f : __expf(lg.z - mm) * ss;
        p.w = (gcol + 3 > grow) ? 0.f : __expf(lg.w - mm) * ss;
        *(float4*)&attn[off] = p;
    }
}

// =============================================================================
// Host launcher — fork/join streams for independent branches.
// =============================================================================
static cudaStream_t s_v = 0, s_n = 0;
static cudaEvent_t  e_root = 0, e_v = 0, e_attn = 0, e_n = 0;

extern "C" void kernel_launch(void* const* d_in, const int* in_sizes, int n_in,
                              void* d_out, int out_size)
{
    const float* q  = (const float*)d_in[0];
    const float* k  = (const float*)d_in[1];
    const float* v  = (const float*)d_in[2];
    const float* Wq = (const float*)d_in[4];
    const float* bq = (const float*)d_in[5];
    const float* Wk = (const float*)d_in[6];
    const float* bk = (const float*)d_in[7];
    const float* Wv = (const float*)d_in[8];
    const float* bv = (const float*)d_in[9];
    const float* Wz = (const float*)d_in[10];
    const float* bz = (const float*)d_in[11];
    float* out = (float*)d_out;

    if (!s_v) {
        cudaStreamCreateWithFlags(&s_v, cudaStreamNonBlocking);
        cudaStreamCreateWithFlags(&s_n, cudaStreamNonBlocking);
        cudaEventCreateWithFlags(&e_root, cudaEventDisableTiming);
        cudaEventCreateWithFlags(&e_v,    cudaEventDisableTiming);
        cudaEventCreateWithFlags(&e_attn, cudaEventDisableTiming);
        cudaEventCreateWithFlags(&e_n,    cudaEventDisableTiming);
    }

    float *proj, *heads, *zc, *gm, *gl;
    cudaGetSymbolAddress((void**)&proj,  g_proj);
    cudaGetSymbolAddress((void**)&heads, g_heads);
    cudaGetSymbolAddress((void**)&zc,    g_zc);
    cudaGetSymbolAddress((void**)&gm,    g_m);
    cudaGetSymbolAddress((void**)&gl,    g_l);

    int need_attn = ((long long)out_size >= (long long)PROJ_ELEMS + (long long)ATTN_ELEMS);
    float* pattn = need_attn ? (out + PROJ_ELEMS) : (float*)0;

    size_t smG = (size_t)(4 * BUFSZ) * sizeof(float4);
    cudaFuncSetAttribute(gemm_3x, cudaFuncAttributeMaxDynamicSharedMemorySize, (int)smG);
    size_t smA = (size_t)(Q_SZ4 + K_SZ4) * sizeof(float4)
               + (size_t)(V_SZ2 + P_SZ2) * sizeof(float2);   // 112,256 B... (Q 66.6K + K 17.4K + V 8.7K + P 16.9K)
    cudaFuncSetAttribute(attn_mma, cudaFuncAttributeMaxDynamicSharedMemorySize, (int)smA);

    // ---- fork: v projection runs concurrently with q,k projections ----
    cudaEventRecord(e_root, 0);
    cudaStreamWaitEvent(s_v, e_root, 0);

    GemmBatch pb;
    pb.A[0] = q;  pb.A[1] = k;
    pb.B[0] = Wq; pb.B[1] = Wk;
    pb.bias[0] = bq; pb.bias[1] = bk;
    pb.C[0] = proj;
    pb.C[1] = proj + (size_t)PROJ_ELEMS;
    gemm_3x<<<dim3(EE / 128, ROWS / 128, 2), 256, smG>>>(pb, ROWS, EE, EE);

    gemm_1x<<<dim3(EE / 128, ROWS / 128), 256, 0, s_v>>>(v, Wv, bv,
        proj + 2 * (size_t)PROJ_ELEMS, ROWS, EE, EE);
    cudaEventRecord(e_v, s_v);
    cudaStreamWaitEvent(0, e_v, 0);

    // ---- gather + attention (main stream) ----
    gather_norm3<<<dim3(NHROWS / 8, 3), 256>>>(proj, heads);

    attn_mma<<<dim3(SS / 128, HH, BB), 256, smA>>>(
        heads, heads + (size_t)PROJ_ELEMS, heads + 2 * (size_t)PROJ_ELEMS,
        zc, gm, gl, pattn);

    // ---- fork: attn normalize runs concurrently with final GEMM ----
    cudaEventRecord(e_attn, 0);
    cudaStreamWaitEvent(s_n, e_attn, 0);

    if (need_attn)
        attn_norm<<<dim3(32 * 32, HH, BB), 256, 0, s_n>>>(gm, gl, pattn);

    gemm_1x<<<dim3(EE / 128, ROWS / 128), 256>>>(zc, Wz, bz, out, ROWS, EE, EE);

    cudaEventRecord(e_n, s_n);
    cudaStreamWaitEvent(0, e_n, 0);
}

// round 9
// speedup vs baseline: 2.1666x; 1.0441x over previous
#include <cuda_runtime.h>
#include <math.h>
#include <stdint.h>

// ---------------- problem constants ----------------
#define BB 2
#define SS 2048
#define EE 1024
#define HH 16
#define HD 64
#define ROWS (BB*SS)           // 4096
#define NHROWS (BB*HH*SS)      // 65536
#define PROJ_ELEMS (ROWS*EE)   // 4194304
#define ATTN_ELEMS (BB*HH*SS*SS) // 134217728

// ---------------- scratch ----------------
__device__ float g_proj[3][PROJ_ELEMS];
__device__ float g_heads[3][PROJ_ELEMS];
__device__ float g_zc[PROJ_ELEMS];
__device__ float g_m[NHROWS];
__device__ float g_l[NHROWS];

// ---------------- tf32 helpers ----------------
__device__ __forceinline__ float2 tf32split(float x) {
    uint32_t hi;
    asm("cvt.rna.tf32.f32 %0, %1;" : "=r"(hi) : "f"(x));
    float h = __uint_as_float(hi);
    uint32_t lo;
    asm("cvt.rna.tf32.f32 %0, %1;" : "=r"(lo) : "f"(x - h));
    return make_float2(h, __uint_as_float(lo));
}

__device__ __forceinline__ float tf32hi(float x) {
    uint32_t hi;
    asm("cvt.rna.tf32.f32 %0, %1;" : "=r"(hi) : "f"(x));
    return __uint_as_float(hi);
}

__device__ __forceinline__ void mma8(float c[4],
                                     uint32_t a0, uint32_t a1, uint32_t a2, uint32_t a3,
                                     uint32_t b0, uint32_t b1) {
    asm volatile(
        "mma.sync.aligned.m16n8k8.row.col.f32.tf32.tf32.f32 "
        "{%0,%1,%2,%3}, {%4,%5,%6,%7}, {%8,%9}, {%0,%1,%2,%3};\n"
        : "+f"(c[0]), "+f"(c[1]), "+f"(c[2]), "+f"(c[3])
        : "r"(a0), "r"(a1), "r"(a2), "r"(a3), "r"(b0), "r"(b1));
}

#define F2U(x) __float_as_uint(x)

// 3xTF32 (hi*hi + hi*lo + lo*hi), fp32 accumulate. f = {hi_a, lo_a, hi_b, lo_b}
__device__ __forceinline__ void mma3x4(float c[4],
                                       const float4 f0, const float4 f1,
                                       const float4 bf) {
    mma8(c, F2U(f0.x), F2U(f1.x), F2U(f0.z), F2U(f1.z), F2U(bf.x), F2U(bf.z));
    mma8(c, F2U(f0.x), F2U(f1.x), F2U(f0.z), F2U(f1.z), F2U(bf.y), F2U(bf.w));
    mma8(c, F2U(f0.y), F2U(f1.y), F2U(f0.w), F2U(f1.w), F2U(bf.x), F2U(bf.z));
}

// 1xTF32 on float2 hi-only fragments: f = {hi(k=t), hi(k=t+4)}
__device__ __forceinline__ void mma1x2(float c[4],
                                       const float2 f0, const float2 f1,
                                       const float2 bf) {
    mma8(c, F2U(f0.x), F2U(f1.x), F2U(f0.y), F2U(f1.y), F2U(bf.x), F2U(bf.y));
}

__device__ __forceinline__ float4 packsplit(float v0, float v1) {
    float2 h0 = tf32split(v0);
    float2 h1 = tf32split(v1);
    return make_float4(h0.x, h0.y, h1.x, h1.y);
}

// =============================================================================
// Batched 128x128x16 3xTF32 GEMM (q,k projections), double-buffered.
// =============================================================================
struct GemmBatch {
    const float* A[2];
    const float* B[2];
    const float* bias[2];
    float* C[2];
};

#define BUFSZ  (2*4*130)   // one float4 buffer: [2 khalf][4 t][130]

__global__ __launch_bounds__(256) void gemm_3x(GemmBatch args, int M, int N, int K)
{
    extern __shared__ float4 smemg[];
    float4 (*Apk)[2][4][130] = (float4(*)[2][4][130])smemg;
    float4 (*Bpk)[2][4][130] = (float4(*)[2][4][130])(smemg + 2 * BUFSZ);

    const float* A    = args.A[blockIdx.z];
    const float* B    = args.B[blockIdx.z];
    const float* bias = args.bias[blockIdx.z];
    float*       C    = args.C[blockIdx.z];

    int tid = threadIdx.x;
    int wid = tid >> 5, lane = tid & 31;
    int g = lane >> 2, t = lane & 3;
    int wm = wid >> 2, wn = wid & 3;
    int m0 = blockIdx.y * 128, n0 = blockIdx.x * 128;

    int ma = tid & 127, ha = tid >> 7;
    int nq = tid & 31,  kr = tid >> 5;
    int bs = kr >> 2,   bt = kr & 3;

    float acc[4][4][4];
#pragma unroll
    for (int mt = 0; mt < 4; mt++)
#pragma unroll
        for (int nt = 0; nt < 4; nt++)
#pragma unroll
            for (int c = 0; c < 4; c++) acc[mt][nt][c] = 0.f;

    const int NC = K / 16;
    float4 pa0, pa1, pb0, pb1;
    {
        const float* pA = A + (size_t)(m0 + ma) * K + ha * 8;
        pa0 = *(const float4*)pA;
        pa1 = *(const float4*)(pA + 4);
        const float* pB = B + (size_t)(bs * 8 + bt) * N + n0 + nq * 4;
        pb0 = *(const float4*)pB;
        pb1 = *(const float4*)(pB + 4 * (size_t)N);
    }

    for (int c = 0; c < NC; c++) {
        int buf = c & 1;
        {
            float va[8] = {pa0.x, pa0.y, pa0.z, pa0.w, pa1.x, pa1.y, pa1.z, pa1.w};
            float vb0[4] = {pb0.x, pb0.y, pb0.z, pb0.w};
            float vb1[4] = {pb1.x, pb1.y, pb1.z, pb1.w};
#pragma unroll
            for (int tt = 0; tt < 4; tt++)
                Apk[buf][ha][tt][ma] = packsplit(va[tt], va[tt + 4]);
#pragma unroll
            for (int j = 0; j < 4; j++)
                Bpk[buf][bs][bt][nq * 4 + j] = packsplit(vb0[j], vb1[j]);
        }
        if (c + 1 < NC) {
            int k0 = (c + 1) * 16;
            const float* pA = A + (size_t)(m0 + ma) * K + k0 + ha * 8;
            pa0 = *(const float4*)pA;
            pa1 = *(const float4*)(pA + 4);
            const float* pB = B + (size_t)(k0 + bs * 8 + bt) * N + n0 + nq * 4;
            pb0 = *(const float4*)pB;
            pb1 = *(const float4*)(pB + 4 * (size_t)N);
        }
        __syncthreads();
#pragma unroll
        for (int s = 0; s < 2; s++) {
            float4 af0[4], af1[4];
#pragma unroll
            for (int mt = 0; mt < 4; mt++) {
                int rb = wm * 64 + mt * 16;
                af0[mt] = Apk[buf][s][t][rb + g];
                af1[mt] = Apk[buf][s][t][rb + g + 8];
            }
#pragma unroll
            for (int nt = 0; nt < 4; nt++) {
                float4 bf = Bpk[buf][s][t][wn * 32 + nt * 8 + g];
#pragma unroll
                for (int mt = 0; mt < 4; mt++)
                    mma3x4(acc[mt][nt], af0[mt], af1[mt], bf);
            }
        }
    }

#pragma unroll
    for (int mt = 0; mt < 4; mt++) {
        int r = m0 + wm * 64 + mt * 16 + g;
#pragma unroll
        for (int nt = 0; nt < 4; nt++) {
            int cc = n0 + wn * 32 + nt * 8 + 2 * t;
            float bb0 = bias[cc], bb1 = bias[cc + 1];
            *(float2*)&C[(size_t)r * N + cc] =
                make_float2(acc[mt][nt][0] + bb0, acc[mt][nt][1] + bb1);
            *(float2*)&C[(size_t)(r + 8) * N + cc] =
                make_float2(acc[mt][nt][2] + bb0, acc[mt][nt][3] + bb1);
        }
    }
}

// =============================================================================
// 128x128x16 1xTF32 GEMM, float2 hi-only smem, 2 CTAs/SM.
// =============================================================================
__global__ __launch_bounds__(256, 2) void gemm_1x(const float* __restrict__ A,
                                                  const float* __restrict__ B,
                                                  const float* __restrict__ bias,
                                                  float* __restrict__ C,
                                                  int M, int N, int K)
{
    __shared__ float2 A2[2][2][4][132];
    __shared__ float2 B2[2][2][4][132];

    int tid = threadIdx.x;
    int wid = tid >> 5, lane = tid & 31;
    int g = lane >> 2, t = lane & 3;
    int wm = wid >> 2, wn = wid & 3;
    int m0 = blockIdx.y * 128, n0 = blockIdx.x * 128;

    int ma = tid & 127, ha = tid >> 7;
    int nq = tid & 31,  kr = tid >> 5;
    int bs = kr >> 2,   bt = kr & 3;

    float acc[4][4][4];
#pragma unroll
    for (int mt = 0; mt < 4; mt++)
#pragma unroll
        for (int nt = 0; nt < 4; nt++)
#pragma unroll
            for (int c = 0; c < 4; c++) acc[mt][nt][c] = 0.f;

    const int NC = K / 16;
    float4 pa0, pa1;
    float vb0[4], vb1[4];
    {
        const float* pA = A + (size_t)(m0 + ma) * K + ha * 8;
        pa0 = *(const float4*)pA;
        pa1 = *(const float4*)(pA + 4);
        const float* pB0 = B + (size_t)(bs * 8 + bt) * N + n0 + nq;
        const float* pB1 = pB0 + 4 * (size_t)N;
#pragma unroll
        for (int j = 0; j < 4; j++) { vb0[j] = pB0[j * 32]; vb1[j] = pB1[j * 32]; }
    }

    for (int c = 0; c < NC; c++) {
        int buf = c & 1;
        {
            float va[8] = {pa0.x, pa0.y, pa0.z, pa0.w, pa1.x, pa1.y, pa1.z, pa1.w};
#pragma unroll
            for (int tt = 0; tt < 4; tt++)
                A2[buf][ha][tt][ma] = make_float2(tf32hi(va[tt]), tf32hi(va[tt + 4]));
#pragma unroll
            for (int j = 0; j < 4; j++)
                B2[buf][bs][bt][j * 32 + nq] = make_float2(tf32hi(vb0[j]), tf32hi(vb1[j]));
        }
        if (c + 1 < NC) {
            int k0 = (c + 1) * 16;
            const float* pA = A + (size_t)(m0 + ma) * K + k0 + ha * 8;
            pa0 = *(const float4*)pA;
            pa1 = *(const float4*)(pA + 4);
            const float* pB0 = B + (size_t)(k0 + bs * 8 + bt) * N + n0 + nq;
            const float* pB1 = pB0 + 4 * (size_t)N;
#pragma unroll
            for (int j = 0; j < 4; j++) { vb0[j] = pB0[j * 32]; vb1[j] = pB1[j * 32]; }
        }
        __syncthreads();
#pragma unroll
        for (int s = 0; s < 2; s++) {
            float2 af0[4], af1[4];
#pragma unroll
            for (int mt = 0; mt < 4; mt++) {
                int rb = wm * 64 + mt * 16;
                af0[mt] = A2[buf][s][t][rb + g];
                af1[mt] = A2[buf][s][t][rb + g + 8];
            }
#pragma unroll
            for (int nt = 0; nt < 4; nt++) {
                float2 bf = B2[buf][s][t][wn * 32 + nt * 8 + g];
#pragma unroll
                for (int mt = 0; mt < 4; mt++)
                    mma1x2(acc[mt][nt], af0[mt], af1[mt], bf);
            }
        }
    }

#pragma unroll
    for (int mt = 0; mt < 4; mt++) {
        int r = m0 + wm * 64 + mt * 16 + g;
#pragma unroll
        for (int nt = 0; nt < 4; nt++) {
            int cc = n0 + wn * 32 + nt * 8 + 2 * t;
            float bb0 = bias[cc], bb1 = bias[cc + 1];
            *(float2*)&C[(size_t)r * N + cc] =
                make_float2(acc[mt][nt][0] + bb0, acc[mt][nt][1] + bb1);
            *(float2*)&C[(size_t)(r + 8) * N + cc] =
                make_float2(acc[mt][nt][2] + bb0, acc[mt][nt][3] + bb1);
        }
    }
}

// =============================================================================
// Fused gather (q,k,v) + optional L2-normalize.
// =============================================================================
__global__ __launch_bounds__(256) void gather_norm3(const float* __restrict__ proj_base,
                                                    float* __restrict__ heads_base)
{
    int which = blockIdx.y;
    const float* proj = proj_base + (size_t)which * PROJ_ELEMS;
    float* outp = heads_base + (size_t)which * PROJ_ELEMS;
    int do_norm = (which < 2);

    int w = blockIdx.x * 8 + (threadIdx.x >> 5);
    int lane = threadIdx.x & 31;
    int b2 = w >> 15;
    int h  = (w >> 11) & 15;
    int s2 = w & 2047;
    int e = b2 * 512 + h * 32 + (s2 >> 6);
    int s = ((s2 & 63) << 5) + lane;
    float v0 = proj[(size_t)s * EE + e];
    float v1 = proj[(size_t)(SS + s) * EE + e];
    float rn = 1.0f;
    if (do_norm) {
        float ssq = v0 * v0 + v1 * v1;
#pragma unroll
        for (int o = 16; o; o >>= 1) ssq += __shfl_xor_sync(0xffffffffu, ssq, o);
        rn = rsqrtf(ssq);
    }
    ((float2*)outp)[(size_t)w * 32 + lane] = make_float2(v0 * rn, v1 * rn);
}

// =============================================================================
// mma flash attention, BQ=64 / BK=32, 128 threads (4 warps x 16 q-rows),
// 3 CTAs/SM. QK^T at 3xTF32; P@V at 1xTF32 float2 hi-only smem.
// LPT block ordering: heaviest q-blocks first (qb = 31 - blockIdx.x).
// =============================================================================
#define Q_SZ4 (8*4*66)   // float4s
#define K_SZ4 (8*4*34)   // float4s
#define V_SZ2 (4*4*68)   // float2s
#define P_SZ2 (4*4*68)   // float2s

__global__ __launch_bounds__(128, 3) void attn_mma(const float* __restrict__ qn,
                                                   const float* __restrict__ kn,
                                                   const float* __restrict__ vh,
                                                   float* __restrict__ zc,
                                                   float* __restrict__ gm,
                                                   float* __restrict__ gl,
                                                   float* __restrict__ pattn)
{
    extern __shared__ float4 sm4[];
    float4 (*Qpk)[4][66] = (float4(*)[4][66])sm4;                      // [8][4][66] f4
    float4 (*Kpk)[4][34] = (float4(*)[4][34])(sm4 + Q_SZ4);            // [8][4][34] f4
    float2 (*V2)[4][68]  = (float2(*)[4][68])(sm4 + Q_SZ4 + K_SZ4);    // [4][4][68] f2
    float2 (*P2)[4][68]  = (float2(*)[4][68])((float2*)(sm4 + Q_SZ4 + K_SZ4) + V_SZ2);

    int tid = threadIdx.x;
    int w = tid >> 5, lane = tid & 31;
    int g = lane >> 2, t = lane & 3;
    int qb = (gridDim.x - 1) - blockIdx.x;   // LPT: heavy blocks first
    int h = blockIdx.y, b2 = blockIdx.z;
    int base = (b2 * HH + h) * SS;
    size_t obase = (size_t)(b2 * HH + h) * SS * SS;
    int q0 = qb * 64;
    int r0 = w * 16;

    // ---- stage Q (hi+lo float4) ----
    {
        int m = tid >> 1, hs = tid & 1;
        const float4* src = (const float4*)(qn + (size_t)(base + q0 + m) * HD + hs * 32);
        float4 v[8];
#pragma unroll
        for (int j = 0; j < 8; j++) v[j] = src[j];
        const float* vf = (const float*)v;
#pragma unroll
        for (int sp = 0; sp < 4; sp++)
#pragma unroll
            for (int tt = 0; tt < 4; tt++)
                Qpk[hs * 4 + sp][tt][m] = packsplit(vf[8 * sp + tt], vf[8 * sp + tt + 4]);
    }

    float oacc[8][4];
#pragma unroll
    for (int nt = 0; nt < 8; nt++)
#pragma unroll
        for (int c = 0; c < 4; c++) oacc[nt][c] = 0.f;
    float m0 = -1e30f, m1 = -1e30f, l0 = 0.f, l1 = 0.f;

    int row0 = q0 + r0 + g, row1 = row0 + 8;
    int nkb = 2 * (qb + 1);

    for (int kb = 0; kb < nkb; kb++) {
        int k0 = kb * 32;
        __syncthreads();
        // ---- stage K tile (hi+lo) ----
        {
            int n = tid >> 2, qk = tid & 3;
            const float4* src = (const float4*)(kn + (size_t)(base + k0 + n) * HD + qk * 16);
            float4 v[4];
#pragma unroll
            for (int j = 0; j < 4; j++) v[j] = src[j];
            const float* vf = (const float*)v;
#pragma unroll
            for (int sp = 0; sp < 2; sp++)
#pragma unroll
                for (int tt = 0; tt < 4; tt++)
                    Kpk[qk * 2 + sp][tt][n] = packsplit(vf[8 * sp + tt], vf[8 * sp + tt + 4]);
        }
        // ---- stage V tile (hi-only float2) ----
        {
            int n4 = tid & 15;
            int comb = tid >> 4;
            int s = comb >> 1, tb = (comb & 1) * 2;
#pragma unroll
            for (int dt = 0; dt < 2; dt++) {
                int tt = tb + dt;
                const float* p = vh + (size_t)(base + k0 + 8 * s + tt) * HD + n4 * 4;
                float4 x0 = *(const float4*)p;
                float4 x1 = *(const float4*)(p + 4 * HD);
                const float* f0 = (const float*)&x0;
                const float* f1 = (const float*)&x1;
#pragma unroll
                for (int j = 0; j < 4; j++)
                    V2[s][tt][n4 * 4 + j] = make_float2(tf32hi(f0[j]), tf32hi(f1[j]));
            }
        }
        __syncthreads();

        if (k0 > q0 + r0 + 15) continue;

        // ---- S = Q @ K^T (3xTF32) ----
        float sacc[4][4];
#pragma unroll
        for (int nt = 0; nt < 4; nt++)
#pragma unroll
            for (int c = 0; c < 4; c++) sacc[nt][c] = 0.f;
#pragma unroll
        for (int ks = 0; ks < 8; ks++) {
            float4 f0 = Qpk[ks][t][r0 + g];
            float4 f1 = Qpk[ks][t][r0 + g + 8];
#pragma unroll
            for (int nt = 0; nt < 4; nt++) {
                float4 bf = Kpk[ks][t][nt * 8 + g];
                mma3x4(sacc[nt], f0, f1, bf);
            }
        }

        // ---- scale + mask ----
        bool nm = (k0 + 31 > q0 + r0);
        float sv[4][4];
        float mx0 = -1e30f, mx1 = -1e30f;
#pragma unroll
        for (int nt = 0; nt < 4; nt++) {
            int cb = k0 + nt * 8 + 2 * t;
            float s0 = sacc[nt][0] * 1000.f;
            float s1 = sacc[nt][1] * 1000.f;
            float s2 = sacc[nt][2] * 1000.f;
            float s3 = sacc[nt][3] * 1000.f;
            if (nm) {
                if (cb > row0) s0 = -1e30f;
                if (cb + 1 > row0) s1 = -1e30f;
                if (cb > row1) s2 = -1e30f;
                if (cb + 1 > row1) s3 = -1e30f;
            }
            sv[nt][0] = s0; sv[nt][1] = s1; sv[nt][2] = s2; sv[nt][3] = s3;
            mx0 = fmaxf(mx0, fmaxf(s0, s1));
            mx1 = fmaxf(mx1, fmaxf(s2, s3));
        }

        // ---- stream logits to attn buffer ----
        if (pattn) {
#pragma unroll
            for (int nt = 0; nt < 4; nt++) {
                int jg = k0 + nt * 8 + 2 * t;
                *(float2*)&pattn[obase + (size_t)row0 * SS + jg] = make_float2(sv[nt][0], sv[nt][1]);
                *(float2*)&pattn[obase + (size_t)row1 * SS + jg] = make_float2(sv[nt][2], sv[nt][3]);
            }
        }

        // ---- online softmax ----
        mx0 = fmaxf(mx0, __shfl_xor_sync(0xffffffffu, mx0, 1));
        mx0 = fmaxf(mx0, __shfl_xor_sync(0xffffffffu, mx0, 2));
        mx1 = fmaxf(mx1, __shfl_xor_sync(0xffffffffu, mx1, 1));
        mx1 = fmaxf(mx1, __shfl_xor_sync(0xffffffffu, mx1, 2));
        float mn0 = fmaxf(m0, mx0), mn1 = fmaxf(m1, mx1);
        float sc0 = __expf(m0 - mn0), sc1 = __expf(m1 - mn1);
        m0 = mn0; m1 = mn1;
        float rs0 = 0.f, rs1 = 0.f;
        int tpA = (2 * t) & 3, tpB = (2 * t + 1) & 3;
        int slot = (t >= 2);
#pragma unroll
        for (int nt = 0; nt < 4; nt++) {
            float p0 = __expf(sv[nt][0] - mn0);
            float p1 = __expf(sv[nt][1] - mn0);
            float p2 = __expf(sv[nt][2] - mn1);
            float p3 = __expf(sv[nt][3] - mn1);
            rs0 += p0 + p1;
            rs1 += p2 + p3;
            ((float*)&P2[nt][tpA][r0 + g])[slot]     = tf32hi(p0);
            ((float*)&P2[nt][tpB][r0 + g])[slot]     = tf32hi(p1);
            ((float*)&P2[nt][tpA][r0 + g + 8])[slot] = tf32hi(p2);
            ((float*)&P2[nt][tpB][r0 + g + 8])[slot] = tf32hi(p3);
        }
        rs0 += __shfl_xor_sync(0xffffffffu, rs0, 1);
        rs0 += __shfl_xor_sync(0xffffffffu, rs0, 2);
        rs1 += __shfl_xor_sync(0xffffffffu, rs1, 1);
        rs1 += __shfl_xor_sync(0xffffffffu, rs1, 2);
        l0 = l0 * sc0 + rs0;
        l1 = l1 * sc1 + rs1;
#pragma unroll
        for (int nt = 0; nt < 8; nt++) {
            oacc[nt][0] *= sc0; oacc[nt][1] *= sc0;
            oacc[nt][2] *= sc1; oacc[nt][3] *= sc1;
        }
        __syncwarp();

        // ---- O += P @ V (1xTF32, float2 fragments) ----
#pragma unroll
        for (int s = 0; s < 4; s++) {
            float2 f0 = P2[s][t][r0 + g];
            float2 f1 = P2[s][t][r0 + g + 8];
#pragma unroll
            for (int nt = 0; nt < 8; nt++) {
                float2 bf = V2[s][t][nt * 8 + g];
                mma1x2(oacc[nt], f0, f1, bf);
            }
        }
    }

    // ---- epilogue ----
    float inv0 = 1.f / l0, inv1 = 1.f / l1;
    int rg = b2 * SS + q0 + r0 + g;
#pragma unroll
    for (int nt = 0; nt < 8; nt++) {
        int col = h * HD + nt * 8 + 2 * t;
        *(float2*)&zc[(size_t)rg * EE + col] =
            make_float2(oacc[nt][0] * inv0, oacc[nt][1] * inv0);
        *(float2*)&zc[(size_t)(rg + 8) * EE + col] =
            make_float2(oacc[nt][2] * inv1, oacc[nt][3] * inv1);
    }
    if (t == 0) {
        gm[base + q0 + r0 + g] = m0;
        gl[base + q0 + r0 + g] = l0;
        gm[base + q0 + r0 + g + 8] = m1;
        gl[base + q0 + r0 + g + 8] = l1;
    }
}

// =============================================================================
// attn normalize: in-place exp(logit - m)/l on lower tiles; zero upper tiles.
// =============================================================================
__global__ __launch_bounds__(256) void attn_norm(const float* __restrict__ gm,
                                                 const float* __restrict__ gl,
                                                 float* __restrict__ attn)
{
    int qb = blockIdx.x >> 5, kb = blockIdx.x & 31;
    int h = blockIdx.y, b2 = blockIdx.z;
    size_t obase = (size_t)(b2 * HH + h) * SS * SS;
    int q0 = qb * 64, k0 = kb * 64;
    int tid = threadIdx.x;

    if (kb > qb) {
        float4 z = make_float4(0.f, 0.f, 0.f, 0.f);
#pragma unroll
        for (int l = 0; l < 4; l++) {
            int idx = l * 256 + tid;
            int row = idx >> 4, c4 = idx & 15;
            *(float4*)&attn[obase + (size_t)(q0 + row) * SS + k0 + c4 * 4] = z;
        }
        return;
    }

    __shared__ float ms[64], il[64];
    int base = (b2 * HH + h) * SS;
    if (tid < 64) {
        ms[tid] = gm[base + q0 + tid];
        il[tid] = 1.f / gl[base + q0 + tid];
    }
    __syncthreads();

#pragma unroll
    for (int l = 0; l < 4; l++) {
        int idx = l * 256 + tid;
        int row = idx >> 4, c4 = idx & 15;
        int grow = q0 + row;
        int gcol = k0 + c4 * 4;
        size_t off = obase + (size_t)grow * SS + gcol;
        float4 lg = *(const float4*)&attn[off];
        float mm = ms[row], ss = il[row];
        float4 p;
        p.x = (gcol     > grow) ? 0.f : __expf(lg.x - mm) * ss;
        p.y = (gcol + 1 > grow) ? 0.f : __expf(lg.y - mm) * ss;
        p.z = (gcol + 2 > grow) ? 0.f : __expf(lg.z - mm) * ss;
        p.w = (gcol + 3 > grow) ? 0.f : __expf(lg.w - mm) * ss;
        *(float4*)&attn[off] = p;
    }
}

// =============================================================================
// Host launcher — fork/join streams for independent branches.
// =============================================================================
static cudaStream_t s_v = 0, s_n = 0;
static cudaEvent_t  e_root = 0, e_v = 0, e_attn = 0, e_n = 0;

extern "C" void kernel_launch(void* const* d_in, const int* in_sizes, int n_in,
                              void* d_out, int out_size)
{
    const float* q  = (const float*)d_in[0];
    const float* k  = (const float*)d_in[1];
    const float* v  = (const float*)d_in[2];
    const float* Wq = (const float*)d_in[4];
    const float* bq = (const float*)d_in[5];
    const float* Wk = (const float*)d_in[6];
    const float* bk = (const float*)d_in[7];
    const float* Wv = (const float*)d_in[8];
    const float* bv = (const float*)d_in[9];
    const float* Wz = (const float*)d_in[10];
    const float* bz = (const float*)d_in[11];
    float* out = (float*)d_out;

    if (!s_v) {
        cudaStreamCreateWithFlags(&s_v, cudaStreamNonBlocking);
        cudaStreamCreateWithFlags(&s_n, cudaStreamNonBlocking);
        cudaEventCreateWithFlags(&e_root, cudaEventDisableTiming);
        cudaEventCreateWithFlags(&e_v,    cudaEventDisableTiming);
        cudaEventCreateWithFlags(&e_attn, cudaEventDisableTiming);
        cudaEventCreateWithFlags(&e_n,    cudaEventDisableTiming);
    }

    float *proj, *heads, *zc, *gm, *gl;
    cudaGetSymbolAddress((void**)&proj,  g_proj);
    cudaGetSymbolAddress((void**)&heads, g_heads);
    cudaGetSymbolAddress((void**)&zc,    g_zc);
    cudaGetSymbolAddress((void**)&gm,    g_m);
    cudaGetSymbolAddress((void**)&gl,    g_l);

    int need_attn = ((long long)out_size >= (long long)PROJ_ELEMS + (long long)ATTN_ELEMS);
    float* pattn = need_attn ? (out + PROJ_ELEMS) : (float*)0;

    size_t smG = (size_t)(4 * BUFSZ) * sizeof(float4);
    cudaFuncSetAttribute(gemm_3x, cudaFuncAttributeMaxDynamicSharedMemorySize, (int)smG);
    size_t smA = (size_t)(Q_SZ4 + K_SZ4) * sizeof(float4)
               + (size_t)(V_SZ2 + P_SZ2) * sizeof(float2);   // 68,608 B -> 3 CTAs/SM
    cudaFuncSetAttribute(attn_mma, cudaFuncAttributeMaxDynamicSharedMemorySize, (int)smA);

    // ---- fork: v projection runs concurrently with q,k projections ----
    cudaEventRecord(e_root, 0);
    cudaStreamWaitEvent(s_v, e_root, 0);

    GemmBatch pb;
    pb.A[0] = q;  pb.A[1] = k;
    pb.B[0] = Wq; pb.B[1] = Wk;
    pb.bias[0] = bq; pb.bias[1] = bk;
    pb.C[0] = proj;
    pb.C[1] = proj + (size_t)PROJ_ELEMS;
    gemm_3x<<<dim3(EE / 128, ROWS / 128, 2), 256, smG>>>(pb, ROWS, EE, EE);

    gemm_1x<<<dim3(EE / 128, ROWS / 128), 256, 0, s_v>>>(v, Wv, bv,
        proj + 2 * (size_t)PROJ_ELEMS, ROWS, EE, EE);
    cudaEventRecord(e_v, s_v);
    cudaStreamWaitEvent(0, e_v, 0);

    // ---- gather + attention (main stream) ----
    gather_norm3<<<dim3(NHROWS / 8, 3), 256>>>(proj, heads);

    attn_mma<<<dim3(SS / 64, HH, BB), 128, smA>>>(
        heads, heads + (size_t)PROJ_ELEMS, heads + 2 * (size_t)PROJ_ELEMS,
        zc, gm, gl, pattn);

    // ---- fork: attn normalize runs concurrently with final GEMM ----
    cudaEventRecord(e_attn, 0);
    cudaStreamWaitEvent(s_n, e_attn, 0);

    if (need_attn)
        attn_norm<<<dim3(32 * 32, HH, BB), 256, 0, s_n>>>(gm, gl, pattn);

    gemm_1x<<<dim3(EE / 128, ROWS / 128), 256>>>(zc, Wz, bz, out, ROWS, EE, EE);

    cudaEventRecord(e_n, s_n);
    cudaStreamWaitEvent(0, e_n, 0);
}